// round 1
// baseline (speedup 1.0000x reference)
#include <cuda_runtime.h>
#include <cstdint>

// ---------------- problem constants ----------------
#define BB   2
#define SS   1024
#define DD   768
#define HH   12
#define HDIM 64
#define DFF  3072
#define NROW (BB*SS)        // 2048
#define D3   (3*DD)         // 2304

// ---------------- scratch (device globals, no allocs) ----------------
__device__ __align__(16) float g_xln [NROW*DD];
__device__ __align__(16) float g_qkv [NROW*D3];
__device__ __align__(16) float g_attn[NROW*DD];
__device__ __align__(16) float g_x1  [NROW*DD];
__device__ __align__(16) float g_h   [NROW*DD];
__device__ __align__(16) float g_ff  [NROW*DFF];

// ================= LayerNorm: one block per row =================
__global__ void __launch_bounds__(256) ln_kernel(
    const float* __restrict__ x, const float* __restrict__ g,
    const float* __restrict__ bt, float* __restrict__ y)
{
    __shared__ float red[8];
    __shared__ float red2[8];
    const int row = blockIdx.x;
    const int tid = threadIdx.x;
    const float* xr = x + (size_t)row * DD;

    float v0 = xr[tid], v1 = xr[tid + 256], v2 = xr[tid + 512];
    float s = v0 + v1 + v2;
    #pragma unroll
    for (int off = 16; off >= 1; off >>= 1)
        s += __shfl_xor_sync(0xffffffffu, s, off);
    if ((tid & 31) == 0) red[tid >> 5] = s;
    __syncthreads();
    float tot = 0.f;
    #pragma unroll
    for (int i = 0; i < 8; i++) tot += red[i];
    const float mean = tot * (1.0f / DD);

    float d0 = v0 - mean, d1 = v1 - mean, d2 = v2 - mean;
    float ss = d0*d0 + d1*d1 + d2*d2;
    #pragma unroll
    for (int off = 16; off >= 1; off >>= 1)
        ss += __shfl_xor_sync(0xffffffffu, ss, off);
    if ((tid & 31) == 0) red2[tid >> 5] = ss;
    __syncthreads();
    float vtot = 0.f;
    #pragma unroll
    for (int i = 0; i < 8; i++) vtot += red2[i];
    const float rstd = rsqrtf(vtot * (1.0f / DD) + 1e-5f);

    float* yr = y + (size_t)row * DD;
    yr[tid      ] = d0 * rstd * g[tid      ] + bt[tid      ];
    yr[tid + 256] = d1 * rstd * g[tid + 256] + bt[tid + 256];
    yr[tid + 512] = d2 * rstd * g[tid + 512] + bt[tid + 512];
}

// ================= SGEMM: C[M,N] = A[M,K] @ Bw[N,K]^T (+bias)(+relu)(+resid) ======
// BM=128, BN=64, BK=16, 256 threads, 8x4 register tile.
template<bool RELU, bool BIAS, bool RESID>
__global__ void __launch_bounds__(256) gemm_kernel(
    const float* __restrict__ A, const float* __restrict__ Bw,
    const float* __restrict__ bias, const float* __restrict__ resid,
    float* __restrict__ C, int M, int N, int K)
{
    constexpr int BM = 128, BN = 64, BK = 16;
    __shared__ float As[BK][BM + 4];
    __shared__ float Bs[BK][BN + 4];

    const int tid = threadIdx.x;
    const int tx = tid & 15;          // n dir (4 cols each)
    const int ty = tid >> 4;          // m dir (8 rows each)
    const int m0 = blockIdx.y * BM;
    const int n0 = blockIdx.x * BN;

    float acc[8][4] = {};

    for (int k0 = 0; k0 < K; k0 += BK) {
        // --- load A tile (2 float4 per thread) ---
        #pragma unroll
        for (int i = 0; i < 2; i++) {
            int l4 = tid + i * 256;
            int m  = l4 >> 2;
            int kq = (l4 & 3) << 2;
            float4 v = *(const float4*)(A + (size_t)(m0 + m) * K + k0 + kq);
            As[kq + 0][m] = v.x; As[kq + 1][m] = v.y;
            As[kq + 2][m] = v.z; As[kq + 3][m] = v.w;
        }
        // --- load B tile (1 float4 per thread) ---
        {
            int n  = tid >> 2;
            int kq = (tid & 3) << 2;
            float4 v = *(const float4*)(Bw + (size_t)(n0 + n) * K + k0 + kq);
            Bs[kq + 0][n] = v.x; Bs[kq + 1][n] = v.y;
            Bs[kq + 2][n] = v.z; Bs[kq + 3][n] = v.w;
        }
        __syncthreads();

        #pragma unroll
        for (int kk = 0; kk < BK; kk++) {
            float a[8], b[4];
            #pragma unroll
            for (int i = 0; i < 8; i++) a[i] = As[kk][ty * 8 + i];
            #pragma unroll
            for (int j = 0; j < 4; j++) b[j] = Bs[kk][tx * 4 + j];
            #pragma unroll
            for (int i = 0; i < 8; i++)
                #pragma unroll
                for (int j = 0; j < 4; j++)
                    acc[i][j] += a[i] * b[j];
        }
        __syncthreads();
    }

    // --- epilogue ---
    #pragma unroll
    for (int i = 0; i < 8; i++) {
        int m = m0 + ty * 8 + i;
        int n = n0 + tx * 4;
        float4 r;
        float vals[4];
        #pragma unroll
        for (int j = 0; j < 4; j++) {
            float c = acc[i][j];
            if (BIAS)  c += bias[n + j];
            if (RELU)  c = fmaxf(c, 0.f);
            vals[j] = c;
        }
        if (RESID) {
            float4 rv = *(const float4*)(resid + (size_t)m * N + n);
            vals[0] += rv.x; vals[1] += rv.y; vals[2] += rv.z; vals[3] += rv.w;
        }
        r.x = vals[0]; r.y = vals[1]; r.z = vals[2]; r.w = vals[3];
        *(float4*)(C + (size_t)m * N + n) = r;
    }
}

// ================= Flash attention with relative bias ==================
// Block: 64 q rows of one (b,h). Key tiles of 32. Online softmax.
// Q pre-scaled by 1/sqrt(64)=0.125 so both q.k and q@relA^T are pre-scaled.
__global__ void __launch_bounds__(256) attn_kernel(
    const float* __restrict__ qkv, const int* __restrict__ relm,
    const unsigned char* __restrict__ amask, const float* __restrict__ relA,
    float* __restrict__ attnout)
{
    constexpr int BQ = 64, BK = 32;
    __shared__ float Qt[64][68];     // [d][q], scaled
    __shared__ float KP[64][34];     // K as [d][k], reused as P [q][k]
    __shared__ float Vs[32][68];     // [k][d]
    __shared__ char  idxs[64][32];   // rel class index {0,1,2}
    __shared__ float rs[64][3];      // per-q relative logits (scaled)
    __shared__ float ms[64], ls[64], mbias[32];

    const int tid = threadIdx.x;
    const int qy = tid >> 4;          // 0..15  (4 q rows each)
    const int kx = tid & 15;          // 0..15  (2 k cols / 4 d cols each)
    const int b  = blockIdx.z, h = blockIdx.y;
    const int q0 = blockIdx.x * BQ;
    const int hq = h * HDIM, hk = DD + h * HDIM, hv = 2 * DD + h * HDIM;

    // ---- load Q tile (scaled) ----
    #pragma unroll
    for (int i = 0; i < 16; i++) {
        int l = tid + i * 256;
        int q = l >> 6, d = l & 63;
        Qt[d][q] = qkv[(size_t)(b * SS + q0 + q) * D3 + hq + d] * 0.125f;
    }
    if (tid < 64) { ms[tid] = -1e30f; ls[tid] = 0.f; }
    __syncthreads();

    // ---- per-q relative logits r[q][c] = qhat . relA[c] ----
    if (tid < 192) {
        int q = tid / 3, c = tid - q * 3;
        float acc = 0.f;
        #pragma unroll
        for (int d = 0; d < 64; d++) acc += Qt[d][q] * relA[c * 64 + d];
        rs[q][c] = acc;
    }

    float o[4][4] = {};

    for (int kt = 0; kt < SS / BK; kt++) {
        const int k0 = kt * BK;
        __syncthreads();   // previous P@V done before reloading K/V

        // ---- load K,V tiles ----
        #pragma unroll
        for (int i = 0; i < 8; i++) {
            int l = tid + i * 256;
            int k = l >> 6, d = l & 63;
            size_t gbase = (size_t)(b * SS + k0 + k) * D3;
            KP[d][k] = qkv[gbase + hk + d];
            Vs[k][d] = qkv[gbase + hv + d];
        }
        // ---- rel index tile ----
        #pragma unroll
        for (int i = 0; i < 8; i++) {
            int l = tid + i * 256;
            int q = l >> 5, k = l & 31;
            idxs[q][k] = (char)(relm[(size_t)(b * SS + q0 + q) * SS + k0 + k] + 1);
        }
        if (tid < 32) mbias[tid] = amask[b * SS + k0 + tid] ? -1e30f : 0.f;
        __syncthreads();

        // ---- S = Qhat K^T  (each thread: 4q x 2k) ----
        float sacc[4][2] = {};
        #pragma unroll 8
        for (int d = 0; d < 64; d++) {
            float a0 = Qt[d][qy*4+0], a1 = Qt[d][qy*4+1];
            float a2 = Qt[d][qy*4+2], a3 = Qt[d][qy*4+3];
            float b0 = KP[d][kx*2+0], b1 = KP[d][kx*2+1];
            sacc[0][0] += a0*b0; sacc[0][1] += a0*b1;
            sacc[1][0] += a1*b0; sacc[1][1] += a1*b1;
            sacc[2][0] += a2*b0; sacc[2][1] += a2*b1;
            sacc[3][0] += a3*b0; sacc[3][1] += a3*b1;
        }
        __syncthreads();   // all K reads done; KP may now become P

        // ---- bias + online softmax; write P into KP ----
        float fac[4];
        #pragma unroll
        for (int i = 0; i < 4; i++) {
            const int q = qy * 4 + i;
            float v0 = sacc[i][0] + rs[q][(int)idxs[q][kx*2+0]] + mbias[kx*2+0];
            float v1 = sacc[i][1] + rs[q][(int)idxs[q][kx*2+1]] + mbias[kx*2+1];
            float tmax = fmaxf(v0, v1);
            #pragma unroll
            for (int off = 8; off >= 1; off >>= 1)
                tmax = fmaxf(tmax, __shfl_xor_sync(0xffffffffu, tmax, off));
            const float mold = ms[q];
            const float mnew = fmaxf(mold, tmax);
            float p0 = __expf(v0 - mnew), p1 = __expf(v1 - mnew);
            float tsum = p0 + p1;
            #pragma unroll
            for (int off = 8; off >= 1; off >>= 1)
                tsum += __shfl_xor_sync(0xffffffffu, tsum, off);
            fac[i] = __expf(mold - mnew);
            if (kx == 0) { ms[q] = mnew; ls[q] = ls[q] * fac[i] + tsum; }
            KP[q][kx*2+0] = p0;
            KP[q][kx*2+1] = p1;
        }
        __syncthreads();   // full P visible, l/m updated

        // ---- rescale O; O += P @ V  (each thread: 4q x 4d) ----
        #pragma unroll
        for (int i = 0; i < 4; i++)
            #pragma unroll
            for (int j = 0; j < 4; j++)
                o[i][j] *= fac[i];

        #pragma unroll 8
        for (int kk = 0; kk < 32; kk++) {
            float p0 = KP[qy*4+0][kk], p1 = KP[qy*4+1][kk];
            float p2 = KP[qy*4+2][kk], p3 = KP[qy*4+3][kk];
            float w0 = Vs[kk][kx*4+0], w1 = Vs[kk][kx*4+1];
            float w2 = Vs[kk][kx*4+2], w3 = Vs[kk][kx*4+3];
            o[0][0] += p0*w0; o[0][1] += p0*w1; o[0][2] += p0*w2; o[0][3] += p0*w3;
            o[1][0] += p1*w0; o[1][1] += p1*w1; o[1][2] += p1*w2; o[1][3] += p1*w3;
            o[2][0] += p2*w0; o[2][1] += p2*w1; o[2][2] += p2*w2; o[2][3] += p2*w3;
            o[3][0] += p3*w0; o[3][1] += p3*w1; o[3][2] += p3*w2; o[3][3] += p3*w3;
        }
    }

    // ---- finalize: divide by l, write (B,S,H*HD) ----
    #pragma unroll
    for (int i = 0; i < 4; i++) {
        const int q = qy * 4 + i;
        const float inv = 1.0f / ls[q];
        float4 r;
        r.x = o[i][0] * inv; r.y = o[i][1] * inv;
        r.z = o[i][2] * inv; r.w = o[i][3] * inv;
        *(float4*)(attnout + (size_t)(b * SS + q0 + q) * DD + h * HDIM + kx * 4) = r;
    }
}

// ================= launch =================
extern "C" void kernel_launch(void* const* d_in, const int* in_sizes, int n_in,
                              void* d_out, int out_size)
{
    const float*         inp   = (const float*)d_in[0];
    const unsigned char* amask = (const unsigned char*)d_in[1];
    const int*           relm  = (const int*)d_in[2];
    const float*         qkv_w = (const float*)d_in[3];
    const float*         relA  = (const float*)d_in[4];
    const float*         o_w   = (const float*)d_in[5];
    const float*         w1    = (const float*)d_in[6];
    const float*         b1    = (const float*)d_in[7];
    const float*         w2    = (const float*)d_in[8];
    const float*         b2    = (const float*)d_in[9];
    const float*         ln1g  = (const float*)d_in[10];
    const float*         ln1b  = (const float*)d_in[11];
    const float*         ln2g  = (const float*)d_in[12];
    const float*         ln2b  = (const float*)d_in[13];
    float* out = (float*)d_out;

    float *xln, *qkv, *attn, *x1, *hbuf, *ff;
    cudaGetSymbolAddress((void**)&xln,  g_xln);
    cudaGetSymbolAddress((void**)&qkv,  g_qkv);
    cudaGetSymbolAddress((void**)&attn, g_attn);
    cudaGetSymbolAddress((void**)&x1,   g_x1);
    cudaGetSymbolAddress((void**)&hbuf, g_h);
    cudaGetSymbolAddress((void**)&ff,   g_ff);

    // 1) LN1
    ln_kernel<<<NROW, 256>>>(inp, ln1g, ln1b, xln);
    // 2) QKV = xln @ qkv_w^T      (2048 x 2304 x 768)
    gemm_kernel<false,false,false><<<dim3(D3/64, NROW/128), 256>>>(
        xln, qkv_w, nullptr, nullptr, qkv, NROW, D3, DD);
    // 3) attention
    attn_kernel<<<dim3(SS/64, HH, BB), 256>>>(qkv, relm, amask, relA, attn);
    // 4) x1 = inp + attn @ o_w^T  (2048 x 768 x 768)
    gemm_kernel<false,false,true><<<dim3(DD/64, NROW/128), 256>>>(
        attn, o_w, nullptr, inp, x1, NROW, DD, DD);
    // 5) LN2
    ln_kernel<<<NROW, 256>>>(x1, ln2g, ln2b, hbuf);
    // 6) ff = relu(h @ w1^T + b1) (2048 x 3072 x 768)
    gemm_kernel<true,true,false><<<dim3(DFF/64, NROW/128), 256>>>(
        hbuf, w1, b1, nullptr, ff, NROW, DFF, DD);
    // 7) out = x1 + ff @ w2^T + b2 (2048 x 768 x 3072)
    gemm_kernel<false,true,true><<<dim3(DD/64, NROW/128), 256>>>(
        ff, w2, b2, x1, out, NROW, DD, DFF);
}

// round 4
// speedup vs baseline: 3.0714x; 3.0714x over previous
#include <cuda_runtime.h>
#include <cuda_bf16.h>
#include <cstdint>

// ---------------- problem constants ----------------
#define BB   2
#define SS   1024
#define DD   768
#define HH   12
#define HDIM 64
#define DFF  3072
#define NROW (BB*SS)        // 2048
#define D3   (3*DD)         // 2304

// ---------------- scratch (device globals, no allocs) ----------------
__device__ __align__(16) float g_qkv [NROW*D3];
__device__ __align__(16) float g_x1  [NROW*DD];

__device__ __align__(16) __nv_bfloat16 g_xln_h [NROW*DD],  g_xln_l [NROW*DD];
__device__ __align__(16) __nv_bfloat16 g_h_h   [NROW*DD],  g_h_l   [NROW*DD];
__device__ __align__(16) __nv_bfloat16 g_attn_h[NROW*DD],  g_attn_l[NROW*DD];
__device__ __align__(16) __nv_bfloat16 g_ff_h  [NROW*DFF], g_ff_l  [NROW*DFF];
__device__ __align__(16) __nv_bfloat16 g_wqkv_h[D3*DD],    g_wqkv_l[D3*DD];
__device__ __align__(16) __nv_bfloat16 g_wo_h  [DD*DD],    g_wo_l  [DD*DD];
__device__ __align__(16) __nv_bfloat16 g_w1_h  [DFF*DD],   g_w1_l  [DFF*DD];
__device__ __align__(16) __nv_bfloat16 g_w2_h  [DD*DFF],   g_w2_l  [DD*DFF];

// ================= helpers =================
__device__ __forceinline__ uint32_t smem_u32(const void* p) {
    uint32_t a;
    asm("{ .reg .u64 t; cvta.to.shared.u64 t, %1; cvt.u32.u64 %0, t; }" : "=r"(a) : "l"(p));
    return a;
}
__device__ __forceinline__ void cp_async16(uint32_t dst, const void* src) {
    asm volatile("cp.async.cg.shared.global [%0], [%1], 16;\n" :: "r"(dst), "l"(src));
}
__device__ __forceinline__ void cp_commit() { asm volatile("cp.async.commit_group;\n" ::: "memory"); }

__device__ __forceinline__ void ldsm4(uint32_t addr, uint32_t& r0, uint32_t& r1, uint32_t& r2, uint32_t& r3) {
    asm volatile("ldmatrix.sync.aligned.m8n8.x4.shared.b16 {%0,%1,%2,%3}, [%4];"
                 : "=r"(r0), "=r"(r1), "=r"(r2), "=r"(r3) : "r"(addr));
}
__device__ __forceinline__ void mma_bf16(float* c, const uint32_t* a, const uint32_t* b) {
    asm volatile("mma.sync.aligned.m16n8k16.row.col.f32.bf16.bf16.f32 "
                 "{%0,%1,%2,%3}, {%4,%5,%6,%7}, {%8,%9}, {%0,%1,%2,%3};"
                 : "+f"(c[0]), "+f"(c[1]), "+f"(c[2]), "+f"(c[3])
                 : "r"(a[0]), "r"(a[1]), "r"(a[2]), "r"(a[3]), "r"(b[0]), "r"(b[1]));
}

// ================= fp32 -> bf16 hi/lo split (weights) =================
__global__ void __launch_bounds__(256) split_kernel(
    const float* __restrict__ x, __nv_bfloat16* __restrict__ hi,
    __nv_bfloat16* __restrict__ lo, int n)
{
    int i = (blockIdx.x * 256 + threadIdx.x) * 4;
    if (i >= n) return;
    float4 v = *(const float4*)(x + i);
    float vv[4] = {v.x, v.y, v.z, v.w};
    __nv_bfloat16 hb[4], lb[4];
    #pragma unroll
    for (int j = 0; j < 4; j++) {
        hb[j] = __float2bfloat16(vv[j]);
        lb[j] = __float2bfloat16(vv[j] - __bfloat162float(hb[j]));
    }
    __nv_bfloat162 h0; h0.x = hb[0]; h0.y = hb[1];
    __nv_bfloat162 h1; h1.x = hb[2]; h1.y = hb[3];
    __nv_bfloat162 l0; l0.x = lb[0]; l0.y = lb[1];
    __nv_bfloat162 l1; l1.x = lb[2]; l1.y = lb[3];
    *(__nv_bfloat162*)(hi + i)     = h0;
    *(__nv_bfloat162*)(hi + i + 2) = h1;
    *(__nv_bfloat162*)(lo + i)     = l0;
    *(__nv_bfloat162*)(lo + i + 2) = l1;
}

// ================= LayerNorm (fused bf16 hi/lo split output) =================
__global__ void __launch_bounds__(256) ln_kernel(
    const float* __restrict__ x, const float* __restrict__ g,
    const float* __restrict__ bt, __nv_bfloat16* __restrict__ yh,
    __nv_bfloat16* __restrict__ yl)
{
    __shared__ float red[8];
    __shared__ float red2[8];
    const int row = blockIdx.x;
    const int tid = threadIdx.x;
    const float* xr = x + (size_t)row * DD;

    float v0 = xr[tid], v1 = xr[tid + 256], v2 = xr[tid + 512];
    float s = v0 + v1 + v2;
    #pragma unroll
    for (int off = 16; off >= 1; off >>= 1)
        s += __shfl_xor_sync(0xffffffffu, s, off);
    if ((tid & 31) == 0) red[tid >> 5] = s;
    __syncthreads();
    float tot = 0.f;
    #pragma unroll
    for (int i = 0; i < 8; i++) tot += red[i];
    const float mean = tot * (1.0f / DD);

    float d0 = v0 - mean, d1 = v1 - mean, d2 = v2 - mean;
    float ss = d0*d0 + d1*d1 + d2*d2;
    #pragma unroll
    for (int off = 16; off >= 1; off >>= 1)
        ss += __shfl_xor_sync(0xffffffffu, ss, off);
    if ((tid & 31) == 0) red2[tid >> 5] = ss;
    __syncthreads();
    float vtot = 0.f;
    #pragma unroll
    for (int i = 0; i < 8; i++) vtot += red2[i];
    const float rstd = rsqrtf(vtot * (1.0f / DD) + 1e-5f);

    #pragma unroll
    for (int j = 0; j < 3; j++) {
        int c = tid + j * 256;
        float dv = (j == 0 ? d0 : (j == 1 ? d1 : d2));
        float val = dv * rstd * g[c] + bt[c];
        __nv_bfloat16 h = __float2bfloat16(val);
        yh[(size_t)row * DD + c] = h;
        yl[(size_t)row * DD + c] = __float2bfloat16(val - __bfloat162float(h));
    }
}

// ================= HMMA GEMM: C[M,N] = A[M,K] @ Bw[N,K]^T ==================
// bf16-split (hi+lo), 3 MMA terms, fp32 reg accum. CTA 128x128, BK=32.
// 8 warps: warp_m = wid&3 (32 rows), warp_n = wid>>2 (64 cols).
// Smem stage: Ah,Al,Bh,Bl tiles of [128][32] bf16 = 8KB each; 2 stages = 64KB.
#define SWZOFF(row, ch) ((uint32_t)((row) * 64 + (((ch) ^ (((row) >> 1) & 3)) * 16)))

template<bool RELU, bool BIAS, bool RESID, bool SPLIT>
__global__ void __launch_bounds__(256, 1) mma_gemm(
    const __nv_bfloat16* __restrict__ Ahi, const __nv_bfloat16* __restrict__ Alo,
    const __nv_bfloat16* __restrict__ Bhi, const __nv_bfloat16* __restrict__ Blo,
    const float* __restrict__ bias, const float* __restrict__ resid,
    float* __restrict__ C, __nv_bfloat16* __restrict__ Chi, __nv_bfloat16* __restrict__ Clo,
    int M, int N, int K)
{
    extern __shared__ __align__(128) char smem[];
    const uint32_t sb = smem_u32(smem);

    const int tid = threadIdx.x;
    const int wid = tid >> 5, lane = tid & 31;
    const int warp_m = wid & 3, warp_n = wid >> 2;
    const int m0 = blockIdx.y * 128, n0 = blockIdx.x * 128;

    float acc[2][8][4];
    #pragma unroll
    for (int mt = 0; mt < 2; mt++)
        #pragma unroll
        for (int nt = 0; nt < 8; nt++)
            #pragma unroll
            for (int j = 0; j < 4; j++) acc[mt][nt][j] = 0.f;

    const int niter = K >> 5;

    // ---- stage loader ----
    auto load_stage = [&](int buf, int k0) {
        uint32_t base = sb + buf * 32768;
        #pragma unroll
        for (int t = 0; t < 8; t++) {
            int lin  = tid + t * 256;          // 0..2047
            int tile = lin >> 9;               // 0..3
            int w    = lin & 511;
            int row  = w >> 2, ch = w & 3;
            uint32_t so = base + tile * 8192 + SWZOFF(row, ch);
            const __nv_bfloat16* src;
            if      (tile == 0) src = Ahi + (size_t)(m0 + row) * K + k0 + ch * 8;
            else if (tile == 1) src = Alo + (size_t)(m0 + row) * K + k0 + ch * 8;
            else if (tile == 2) src = Bhi + (size_t)(n0 + row) * K + k0 + ch * 8;
            else                src = Blo + (size_t)(n0 + row) * K + k0 + ch * 8;
            cp_async16(so, src);
        }
        cp_commit();
    };

    load_stage(0, 0);

    const int lr = lane & 15, lh = lane >> 4;

    for (int it = 0; it < niter; it++) {
        if (it + 1 < niter) {
            load_stage((it + 1) & 1, (it + 1) * 32);
            asm volatile("cp.async.wait_group 1;\n" ::: "memory");
        } else {
            asm volatile("cp.async.wait_group 0;\n" ::: "memory");
        }
        __syncthreads();

        const uint32_t base = sb + (it & 1) * 32768;
        #pragma unroll
        for (int ks = 0; ks < 2; ks++) {
            const int ch = ks * 2 + lh;
            // A hi/lo fragments (2 m-tiles)
            uint32_t ah[2][4], alo[2][4];
            #pragma unroll
            for (int mt = 0; mt < 2; mt++) {
                int row = warp_m * 32 + mt * 16 + lr;
                uint32_t off = SWZOFF(row, ch);
                ldsm4(base + off,        ah[mt][0],  ah[mt][1],  ah[mt][2],  ah[mt][3]);
                ldsm4(base + 8192 + off, alo[mt][0], alo[mt][1], alo[mt][2], alo[mt][3]);
            }
            // B hi fragments (8 n-tiles via 4 x4-ldmatrix)
            uint32_t bh[8][2];
            #pragma unroll
            for (int np = 0; np < 4; np++) {
                int row = warp_n * 64 + np * 16 + lr;
                uint32_t off = base + 16384 + SWZOFF(row, ch);
                ldsm4(off, bh[2*np][0], bh[2*np+1][0], bh[2*np][1], bh[2*np+1][1]);
            }
            #pragma unroll
            for (int mt = 0; mt < 2; mt++)
                #pragma unroll
                for (int nt = 0; nt < 8; nt++)
                    mma_bf16(acc[mt][nt], ah[mt], bh[nt]);
            #pragma unroll
            for (int mt = 0; mt < 2; mt++)
                #pragma unroll
                for (int nt = 0; nt < 8; nt++)
                    mma_bf16(acc[mt][nt], alo[mt], bh[nt]);
            // B lo fragments (reuse regs)
            uint32_t bl[8][2];
            #pragma unroll
            for (int np = 0; np < 4; np++) {
                int row = warp_n * 64 + np * 16 + lr;
                uint32_t off = base + 24576 + SWZOFF(row, ch);
                ldsm4(off, bl[2*np][0], bl[2*np+1][0], bl[2*np][1], bl[2*np+1][1]);
            }
            #pragma unroll
            for (int mt = 0; mt < 2; mt++)
                #pragma unroll
                for (int nt = 0; nt < 8; nt++)
                    mma_bf16(acc[mt][nt], ah[mt], bl[nt]);
        }
        __syncthreads();
    }

    // ---- epilogue ----
    #pragma unroll
    for (int mt = 0; mt < 2; mt++) {
        #pragma unroll
        for (int half = 0; half < 2; half++) {
            const int m = m0 + warp_m * 32 + mt * 16 + (lane >> 2) + half * 8;
            #pragma unroll
            for (int nt = 0; nt < 8; nt++) {
                const int n = n0 + warp_n * 64 + nt * 8 + (lane & 3) * 2;
                float v0 = acc[mt][nt][half * 2 + 0];
                float v1 = acc[mt][nt][half * 2 + 1];
                if (BIAS) { v0 += bias[n]; v1 += bias[n + 1]; }
                if (RELU) { v0 = fmaxf(v0, 0.f); v1 = fmaxf(v1, 0.f); }
                if (RESID) {
                    float2 rv = *(const float2*)(resid + (size_t)m * N + n);
                    v0 += rv.x; v1 += rv.y;
                }
                if (SPLIT) {
                    __nv_bfloat16 h0 = __float2bfloat16(v0);
                    __nv_bfloat16 h1 = __float2bfloat16(v1);
                    __nv_bfloat162 hh; hh.x = h0; hh.y = h1;
                    __nv_bfloat162 ll;
                    ll.x = __float2bfloat16(v0 - __bfloat162float(h0));
                    ll.y = __float2bfloat16(v1 - __bfloat162float(h1));
                    *(__nv_bfloat162*)(Chi + (size_t)m * N + n) = hh;
                    *(__nv_bfloat162*)(Clo + (size_t)m * N + n) = ll;
                } else {
                    float2 o2; o2.x = v0; o2.y = v1;
                    *(float2*)(C + (size_t)m * N + n) = o2;
                }
            }
        }
    }
}

// ================= Flash attention with relative bias (fp32 SIMT) ==========
__global__ void __launch_bounds__(256) attn_kernel(
    const float* __restrict__ qkv, const int* __restrict__ relm,
    const unsigned char* __restrict__ amask, const float* __restrict__ relA,
    __nv_bfloat16* __restrict__ outh, __nv_bfloat16* __restrict__ outl)
{
    constexpr int BK = 32;
    __shared__ float Qt[64][68];
    __shared__ float KP[64][34];
    __shared__ float Vs[32][68];
    __shared__ char  idxs[64][32];
    __shared__ float rs[64][3];
    __shared__ float ms[64], ls[64], mbias[32];

    const int tid = threadIdx.x;
    const int qy = tid >> 4;
    const int kx = tid & 15;
    const int b  = blockIdx.z, h = blockIdx.y;
    const int q0 = blockIdx.x * 64;
    const int hq = h * HDIM, hk = DD + h * HDIM, hv = 2 * DD + h * HDIM;

    #pragma unroll
    for (int i = 0; i < 16; i++) {
        int l = tid + i * 256;
        int q = l >> 6, d = l & 63;
        Qt[d][q] = qkv[(size_t)(b * SS + q0 + q) * D3 + hq + d] * 0.125f;
    }
    if (tid < 64) { ms[tid] = -1e30f; ls[tid] = 0.f; }
    __syncthreads();

    if (tid < 192) {
        int q = tid / 3, c = tid - q * 3;
        float acc = 0.f;
        #pragma unroll
        for (int d = 0; d < 64; d++) acc += Qt[d][q] * relA[c * 64 + d];
        rs[q][c] = acc;
    }

    float o[4][4] = {};

    for (int kt = 0; kt < SS / BK; kt++) {
        const int k0 = kt * BK;
        __syncthreads();

        #pragma unroll
        for (int i = 0; i < 8; i++) {
            int l = tid + i * 256;
            int k = l >> 6, d = l & 63;
            size_t gbase = (size_t)(b * SS + k0 + k) * D3;
            KP[d][k] = qkv[gbase + hk + d];
            Vs[k][d] = qkv[gbase + hv + d];
        }
        #pragma unroll
        for (int i = 0; i < 8; i++) {
            int l = tid + i * 256;
            int q = l >> 5, k = l & 31;
            idxs[q][k] = (char)(relm[(size_t)(b * SS + q0 + q) * SS + k0 + k] + 1);
        }
        if (tid < 32) mbias[tid] = amask[b * SS + k0 + tid] ? -1e30f : 0.f;
        __syncthreads();

        float sacc[4][2] = {};
        #pragma unroll 8
        for (int d = 0; d < 64; d++) {
            float a0 = Qt[d][qy*4+0], a1 = Qt[d][qy*4+1];
            float a2 = Qt[d][qy*4+2], a3 = Qt[d][qy*4+3];
            float b0 = KP[d][kx*2+0], b1 = KP[d][kx*2+1];
            sacc[0][0] += a0*b0; sacc[0][1] += a0*b1;
            sacc[1][0] += a1*b0; sacc[1][1] += a1*b1;
            sacc[2][0] += a2*b0; sacc[2][1] += a2*b1;
            sacc[3][0] += a3*b0; sacc[3][1] += a3*b1;
        }
        __syncthreads();

        float fac[4];
        #pragma unroll
        for (int i = 0; i < 4; i++) {
            const int q = qy * 4 + i;
            float v0 = sacc[i][0] + rs[q][(int)idxs[q][kx*2+0]] + mbias[kx*2+0];
            float v1 = sacc[i][1] + rs[q][(int)idxs[q][kx*2+1]] + mbias[kx*2+1];
            float tmax = fmaxf(v0, v1);
            #pragma unroll
            for (int off = 8; off >= 1; off >>= 1)
                tmax = fmaxf(tmax, __shfl_xor_sync(0xffffffffu, tmax, off));
            const float mold = ms[q];
            const float mnew = fmaxf(mold, tmax);
            float p0 = __expf(v0 - mnew), p1 = __expf(v1 - mnew);
            float tsum = p0 + p1;
            #pragma unroll
            for (int off = 8; off >= 1; off >>= 1)
                tsum += __shfl_xor_sync(0xffffffffu, tsum, off);
            fac[i] = __expf(mold - mnew);
            if (kx == 0) { ms[q] = mnew; ls[q] = ls[q] * fac[i] + tsum; }
            KP[q][kx*2+0] = p0;
            KP[q][kx*2+1] = p1;
        }
        __syncthreads();

        #pragma unroll
        for (int i = 0; i < 4; i++)
            #pragma unroll
            for (int j = 0; j < 4; j++)
                o[i][j] *= fac[i];

        #pragma unroll 8
        for (int kk = 0; kk < 32; kk++) {
            float p0 = KP[qy*4+0][kk], p1 = KP[qy*4+1][kk];
            float p2 = KP[qy*4+2][kk], p3 = KP[qy*4+3][kk];
            float w0 = Vs[kk][kx*4+0], w1 = Vs[kk][kx*4+1];
            float w2 = Vs[kk][kx*4+2], w3 = Vs[kk][kx*4+3];
            o[0][0] += p0*w0; o[0][1] += p0*w1; o[0][2] += p0*w2; o[0][3] += p0*w3;
            o[1][0] += p1*w0; o[1][1] += p1*w1; o[1][2] += p1*w2; o[1][3] += p1*w3;
            o[2][0] += p2*w0; o[2][1] += p2*w1; o[2][2] += p2*w2; o[2][3] += p2*w3;
            o[3][0] += p3*w0; o[3][1] += p3*w1; o[3][2] += p3*w2; o[3][3] += p3*w3;
        }
    }

    #pragma unroll
    for (int i = 0; i < 4; i++) {
        const int q = qy * 4 + i;
        const float inv = 1.0f / ls[q];
        size_t base = (size_t)(b * SS + q0 + q) * DD + h * HDIM + kx * 4;
        #pragma unroll
        for (int j = 0; j < 4; j++) {
            float val = o[i][j] * inv;
            __nv_bfloat16 hb = __float2bfloat16(val);
            outh[base + j] = hb;
            outl[base + j] = __float2bfloat16(val - __bfloat162float(hb));
        }
    }
}

// ================= launch =================
extern "C" void kernel_launch(void* const* d_in, const int* in_sizes, int n_in,
                              void* d_out, int out_size)
{
    const float*         inp   = (const float*)d_in[0];
    const unsigned char* amask = (const unsigned char*)d_in[1];
    const int*           relm  = (const int*)d_in[2];
    const float*         qkv_w = (const float*)d_in[3];
    const float*         relA  = (const float*)d_in[4];
    const float*         o_w   = (const float*)d_in[5];
    const float*         w1    = (const float*)d_in[6];
    const float*         b1    = (const float*)d_in[7];
    const float*         w2    = (const float*)d_in[8];
    const float*         b2    = (const float*)d_in[9];
    const float*         ln1g  = (const float*)d_in[10];
    const float*         ln1b  = (const float*)d_in[11];
    const float*         ln2g  = (const float*)d_in[12];
    const float*         ln2b  = (const float*)d_in[13];
    float* out = (float*)d_out;

    float *qkv, *x1;
    __nv_bfloat16 *xlnh, *xlnl, *hh, *hl, *ah, *al, *ffh, *ffl;
    __nv_bfloat16 *wqh, *wql, *woh, *wol, *w1h, *w1l, *w2h, *w2l;
    cudaGetSymbolAddress((void**)&qkv,  g_qkv);
    cudaGetSymbolAddress((void**)&x1,   g_x1);
    cudaGetSymbolAddress((void**)&xlnh, g_xln_h); cudaGetSymbolAddress((void**)&xlnl, g_xln_l);
    cudaGetSymbolAddress((void**)&hh,   g_h_h);   cudaGetSymbolAddress((void**)&hl,   g_h_l);
    cudaGetSymbolAddress((void**)&ah,   g_attn_h);cudaGetSymbolAddress((void**)&al,   g_attn_l);
    cudaGetSymbolAddress((void**)&ffh,  g_ff_h);  cudaGetSymbolAddress((void**)&ffl,  g_ff_l);
    cudaGetSymbolAddress((void**)&wqh,  g_wqkv_h);cudaGetSymbolAddress((void**)&wql,  g_wqkv_l);
    cudaGetSymbolAddress((void**)&woh,  g_wo_h);  cudaGetSymbolAddress((void**)&wol,  g_wo_l);
    cudaGetSymbolAddress((void**)&w1h,  g_w1_h);  cudaGetSymbolAddress((void**)&w1l,  g_w1_l);
    cudaGetSymbolAddress((void**)&w2h,  g_w2_h);  cudaGetSymbolAddress((void**)&w2l,  g_w2_l);

    const int SMEM = 65536;
    cudaFuncSetAttribute(mma_gemm<false,false,false,false>, cudaFuncAttributeMaxDynamicSharedMemorySize, SMEM);
    cudaFuncSetAttribute(mma_gemm<false,false,true ,false>, cudaFuncAttributeMaxDynamicSharedMemorySize, SMEM);
    cudaFuncSetAttribute(mma_gemm<true ,true ,false,true >, cudaFuncAttributeMaxDynamicSharedMemorySize, SMEM);
    cudaFuncSetAttribute(mma_gemm<false,true ,true ,false>, cudaFuncAttributeMaxDynamicSharedMemorySize, SMEM);

    // 0) split weights to bf16 hi/lo
    split_kernel<<<(D3*DD/4 + 255)/256, 256>>>(qkv_w, wqh, wql, D3*DD);
    split_kernel<<<(DD*DD/4 + 255)/256, 256>>>(o_w,   woh, wol, DD*DD);
    split_kernel<<<(DFF*DD/4 + 255)/256, 256>>>(w1,   w1h, w1l, DFF*DD);
    split_kernel<<<(DD*DFF/4 + 255)/256, 256>>>(w2,   w2h, w2l, DD*DFF);

    // 1) LN1 -> xln (bf16 split)
    ln_kernel<<<NROW, 256>>>(inp, ln1g, ln1b, xlnh, xlnl);

    // 2) QKV = xln @ qkv_w^T  (2048 x 2304 x 768), fp32 out
    mma_gemm<false,false,false,false><<<dim3(D3/128, NROW/128), 256, SMEM>>>(
        xlnh, xlnl, wqh, wql, nullptr, nullptr, qkv, nullptr, nullptr, NROW, D3, DD);

    // 3) attention -> attn (bf16 split)
    attn_kernel<<<dim3(SS/64, HH, BB), 256>>>(qkv, relm, amask, relA, ah, al);

    // 4) x1 = inp + attn @ o_w^T  (2048 x 768 x 768), fp32 out
    mma_gemm<false,false,true,false><<<dim3(DD/128, NROW/128), 256, SMEM>>>(
        ah, al, woh, wol, nullptr, inp, x1, nullptr, nullptr, NROW, DD, DD);

    // 5) LN2 -> h (bf16 split)
    ln_kernel<<<NROW, 256>>>(x1, ln2g, ln2b, hh, hl);

    // 6) ff = relu(h @ w1^T + b1) (2048 x 3072 x 768), bf16-split out
    mma_gemm<true,true,false,true><<<dim3(DFF/128, NROW/128), 256, SMEM>>>(
        hh, hl, w1h, w1l, b1, nullptr, nullptr, ffh, ffl, NROW, DFF, DD);

    // 7) out = x1 + ff @ w2^T + b2 (2048 x 768 x 3072), fp32 out
    mma_gemm<false,true,true,false><<<dim3(DD/128, NROW/128), 256, SMEM>>>(
        ffh, ffl, w2h, w2l, b2, x1, out, nullptr, nullptr, NROW, DD, DFF);
}

// round 5
// speedup vs baseline: 3.3960x; 1.1057x over previous
#include <cuda_runtime.h>
#include <cuda_bf16.h>
#include <cstdint>

// ---------------- problem constants ----------------
#define BB   2
#define SS   1024
#define DD   768
#define HH   12
#define HDIM 64
#define DFF  3072
#define NROW (BB*SS)        // 2048
#define D3   (3*DD)         // 2304

// ---------------- scratch (device globals, no allocs) ----------------
__device__ __align__(16) float g_x1  [NROW*DD];

__device__ __align__(16) __nv_bfloat16 g_qkvs_h[NROW*D3], g_qkvs_l[NROW*D3];
__device__ __align__(16) __nv_bfloat16 g_xln_h [NROW*DD],  g_xln_l [NROW*DD];
__device__ __align__(16) __nv_bfloat16 g_h_h   [NROW*DD],  g_h_l   [NROW*DD];
__device__ __align__(16) __nv_bfloat16 g_attn_h[NROW*DD],  g_attn_l[NROW*DD];
__device__ __align__(16) __nv_bfloat16 g_ff_h  [NROW*DFF], g_ff_l  [NROW*DFF];
__device__ __align__(16) __nv_bfloat16 g_wqkv_h[D3*DD],    g_wqkv_l[D3*DD];
__device__ __align__(16) __nv_bfloat16 g_wo_h  [DD*DD],    g_wo_l  [DD*DD];
__device__ __align__(16) __nv_bfloat16 g_w1_h  [DFF*DD],   g_w1_l  [DFF*DD];
__device__ __align__(16) __nv_bfloat16 g_w2_h  [DD*DFF],   g_w2_l  [DD*DFF];

// ================= helpers =================
__device__ __forceinline__ uint32_t smem_u32(const void* p) {
    uint32_t a;
    asm("{ .reg .u64 t; cvta.to.shared.u64 t, %1; cvt.u32.u64 %0, t; }" : "=r"(a) : "l"(p));
    return a;
}
__device__ __forceinline__ void cp_async16(uint32_t dst, const void* src) {
    asm volatile("cp.async.cg.shared.global [%0], [%1], 16;\n" :: "r"(dst), "l"(src));
}
__device__ __forceinline__ void cp_commit() { asm volatile("cp.async.commit_group;\n" ::: "memory"); }

__device__ __forceinline__ void ldsm4(uint32_t addr, uint32_t& r0, uint32_t& r1, uint32_t& r2, uint32_t& r3) {
    asm volatile("ldmatrix.sync.aligned.m8n8.x4.shared.b16 {%0,%1,%2,%3}, [%4];"
                 : "=r"(r0), "=r"(r1), "=r"(r2), "=r"(r3) : "r"(addr));
}
__device__ __forceinline__ void ldsm4t(uint32_t addr, uint32_t& r0, uint32_t& r1, uint32_t& r2, uint32_t& r3) {
    asm volatile("ldmatrix.sync.aligned.m8n8.x4.trans.shared.b16 {%0,%1,%2,%3}, [%4];"
                 : "=r"(r0), "=r"(r1), "=r"(r2), "=r"(r3) : "r"(addr));
}
__device__ __forceinline__ void mma_bf16(float* c, const uint32_t* a, const uint32_t* b) {
    asm volatile("mma.sync.aligned.m16n8k16.row.col.f32.bf16.bf16.f32 "
                 "{%0,%1,%2,%3}, {%4,%5,%6,%7}, {%8,%9}, {%0,%1,%2,%3};"
                 : "+f"(c[0]), "+f"(c[1]), "+f"(c[2]), "+f"(c[3])
                 : "r"(a[0]), "r"(a[1]), "r"(a[2]), "r"(a[3]), "r"(b[0]), "r"(b[1]));
}
__device__ __forceinline__ void split2(float a, float b, uint32_t& hi, uint32_t& lo) {
    __nv_bfloat16 ha = __float2bfloat16(a), hb = __float2bfloat16(b);
    __nv_bfloat162 hh; hh.x = ha; hh.y = hb;
    __nv_bfloat162 ll;
    ll.x = __float2bfloat16(a - __bfloat162float(ha));
    ll.y = __float2bfloat16(b - __bfloat162float(hb));
    hi = *(uint32_t*)&hh; lo = *(uint32_t*)&ll;
}
__device__ __forceinline__ float pick3(float a, float b, float c, int i) {
    return i == 0 ? a : (i == 1 ? b : c);
}

// ================= fp32 -> bf16 hi/lo split (weights) =================
__global__ void __launch_bounds__(256) split_kernel(
    const float* __restrict__ x, __nv_bfloat16* __restrict__ hi,
    __nv_bfloat16* __restrict__ lo, int n)
{
    int i = (blockIdx.x * 256 + threadIdx.x) * 4;
    if (i >= n) return;
    float4 v = *(const float4*)(x + i);
    float vv[4] = {v.x, v.y, v.z, v.w};
    uint32_t h0, l0, h1, l1;
    split2(vv[0], vv[1], h0, l0);
    split2(vv[2], vv[3], h1, l1);
    *(uint32_t*)(hi + i)     = h0;
    *(uint32_t*)(hi + i + 2) = h1;
    *(uint32_t*)(lo + i)     = l0;
    *(uint32_t*)(lo + i + 2) = l1;
}

// ================= LayerNorm (fused bf16 hi/lo split output) =================
__global__ void __launch_bounds__(256) ln_kernel(
    const float* __restrict__ x, const float* __restrict__ g,
    const float* __restrict__ bt, __nv_bfloat16* __restrict__ yh,
    __nv_bfloat16* __restrict__ yl)
{
    __shared__ float red[8];
    __shared__ float red2[8];
    const int row = blockIdx.x;
    const int tid = threadIdx.x;
    const float* xr = x + (size_t)row * DD;

    float v0 = xr[tid], v1 = xr[tid + 256], v2 = xr[tid + 512];
    float s = v0 + v1 + v2;
    #pragma unroll
    for (int off = 16; off >= 1; off >>= 1)
        s += __shfl_xor_sync(0xffffffffu, s, off);
    if ((tid & 31) == 0) red[tid >> 5] = s;
    __syncthreads();
    float tot = 0.f;
    #pragma unroll
    for (int i = 0; i < 8; i++) tot += red[i];
    const float mean = tot * (1.0f / DD);

    float d0 = v0 - mean, d1 = v1 - mean, d2 = v2 - mean;
    float ss = d0*d0 + d1*d1 + d2*d2;
    #pragma unroll
    for (int off = 16; off >= 1; off >>= 1)
        ss += __shfl_xor_sync(0xffffffffu, ss, off);
    if ((tid & 31) == 0) red2[tid >> 5] = ss;
    __syncthreads();
    float vtot = 0.f;
    #pragma unroll
    for (int i = 0; i < 8; i++) vtot += red2[i];
    const float rstd = rsqrtf(vtot * (1.0f / DD) + 1e-5f);

    #pragma unroll
    for (int j = 0; j < 3; j++) {
        int c = tid + j * 256;
        float dv = (j == 0 ? d0 : (j == 1 ? d1 : d2));
        float val = dv * rstd * g[c] + bt[c];
        __nv_bfloat16 h = __float2bfloat16(val);
        yh[(size_t)row * DD + c] = h;
        yl[(size_t)row * DD + c] = __float2bfloat16(val - __bfloat162float(h));
    }
}

// ================= HMMA GEMM (unchanged from round 4) ==================
#define SWZOFF(row, ch) ((uint32_t)((row) * 64 + (((ch) ^ (((row) >> 1) & 3)) * 16)))

template<bool RELU, bool BIAS, bool RESID, bool SPLIT>
__global__ void __launch_bounds__(256, 1) mma_gemm(
    const __nv_bfloat16* __restrict__ Ahi, const __nv_bfloat16* __restrict__ Alo,
    const __nv_bfloat16* __restrict__ Bhi, const __nv_bfloat16* __restrict__ Blo,
    const float* __restrict__ bias, const float* __restrict__ resid,
    float* __restrict__ C, __nv_bfloat16* __restrict__ Chi, __nv_bfloat16* __restrict__ Clo,
    int M, int N, int K)
{
    extern __shared__ __align__(128) char smem[];
    const uint32_t sb = smem_u32(smem);

    const int tid = threadIdx.x;
    const int wid = tid >> 5, lane = tid & 31;
    const int warp_m = wid & 3, warp_n = wid >> 2;
    const int m0 = blockIdx.y * 128, n0 = blockIdx.x * 128;

    float acc[2][8][4];
    #pragma unroll
    for (int mt = 0; mt < 2; mt++)
        #pragma unroll
        for (int nt = 0; nt < 8; nt++)
            #pragma unroll
            for (int j = 0; j < 4; j++) acc[mt][nt][j] = 0.f;

    const int niter = K >> 5;

    auto load_stage = [&](int buf, int k0) {
        uint32_t base = sb + buf * 32768;
        #pragma unroll
        for (int t = 0; t < 8; t++) {
            int lin  = tid + t * 256;
            int tile = lin >> 9;
            int w    = lin & 511;
            int row  = w >> 2, ch = w & 3;
            uint32_t so = base + tile * 8192 + SWZOFF(row, ch);
            const __nv_bfloat16* src;
            if      (tile == 0) src = Ahi + (size_t)(m0 + row) * K + k0 + ch * 8;
            else if (tile == 1) src = Alo + (size_t)(m0 + row) * K + k0 + ch * 8;
            else if (tile == 2) src = Bhi + (size_t)(n0 + row) * K + k0 + ch * 8;
            else                src = Blo + (size_t)(n0 + row) * K + k0 + ch * 8;
            cp_async16(so, src);
        }
        cp_commit();
    };

    load_stage(0, 0);

    const int lr = lane & 15, lh = lane >> 4;

    for (int it = 0; it < niter; it++) {
        if (it + 1 < niter) {
            load_stage((it + 1) & 1, (it + 1) * 32);
            asm volatile("cp.async.wait_group 1;\n" ::: "memory");
        } else {
            asm volatile("cp.async.wait_group 0;\n" ::: "memory");
        }
        __syncthreads();

        const uint32_t base = sb + (it & 1) * 32768;
        #pragma unroll
        for (int ks = 0; ks < 2; ks++) {
            const int ch = ks * 2 + lh;
            uint32_t ah[2][4], alo[2][4];
            #pragma unroll
            for (int mt = 0; mt < 2; mt++) {
                int row = warp_m * 32 + mt * 16 + lr;
                uint32_t off = SWZOFF(row, ch);
                ldsm4(base + off,        ah[mt][0],  ah[mt][1],  ah[mt][2],  ah[mt][3]);
                ldsm4(base + 8192 + off, alo[mt][0], alo[mt][1], alo[mt][2], alo[mt][3]);
            }
            uint32_t bh[8][2];
            #pragma unroll
            for (int np = 0; np < 4; np++) {
                int row = warp_n * 64 + np * 16 + lr;
                uint32_t off = base + 16384 + SWZOFF(row, ch);
                ldsm4(off, bh[2*np][0], bh[2*np+1][0], bh[2*np][1], bh[2*np+1][1]);
            }
            #pragma unroll
            for (int mt = 0; mt < 2; mt++)
                #pragma unroll
                for (int nt = 0; nt < 8; nt++)
                    mma_bf16(acc[mt][nt], ah[mt], bh[nt]);
            #pragma unroll
            for (int mt = 0; mt < 2; mt++)
                #pragma unroll
                for (int nt = 0; nt < 8; nt++)
                    mma_bf16(acc[mt][nt], alo[mt], bh[nt]);
            uint32_t bl[8][2];
            #pragma unroll
            for (int np = 0; np < 4; np++) {
                int row = warp_n * 64 + np * 16 + lr;
                uint32_t off = base + 24576 + SWZOFF(row, ch);
                ldsm4(off, bl[2*np][0], bl[2*np+1][0], bl[2*np][1], bl[2*np+1][1]);
            }
            #pragma unroll
            for (int mt = 0; mt < 2; mt++)
                #pragma unroll
                for (int nt = 0; nt < 8; nt++)
                    mma_bf16(acc[mt][nt], ah[mt], bl[nt]);
        }
        __syncthreads();
    }

    #pragma unroll
    for (int mt = 0; mt < 2; mt++) {
        #pragma unroll
        for (int half = 0; half < 2; half++) {
            const int m = m0 + warp_m * 32 + mt * 16 + (lane >> 2) + half * 8;
            #pragma unroll
            for (int nt = 0; nt < 8; nt++) {
                const int n = n0 + warp_n * 64 + nt * 8 + (lane & 3) * 2;
                float v0 = acc[mt][nt][half * 2 + 0];
                float v1 = acc[mt][nt][half * 2 + 1];
                if (BIAS) { v0 += bias[n]; v1 += bias[n + 1]; }
                if (RELU) { v0 = fmaxf(v0, 0.f); v1 = fmaxf(v1, 0.f); }
                if (RESID) {
                    float2 rv = *(const float2*)(resid + (size_t)m * N + n);
                    v0 += rv.x; v1 += rv.y;
                }
                if (SPLIT) {
                    uint32_t hi, lo;
                    split2(v0, v1, hi, lo);
                    *(uint32_t*)(Chi + (size_t)m * N + n) = hi;
                    *(uint32_t*)(Clo + (size_t)m * N + n) = lo;
                } else {
                    float2 o2; o2.x = v0; o2.y = v1;
                    *(float2*)(C + (size_t)m * N + n) = o2;
                }
            }
        }
    }
}

// ================= HMMA flash attention with relative bias ==================
// CTA: 128 q rows of one (b,h). 8 warps x 16 rows. Key tiles of 64.
// Smem: Qh/Ql [128][64] (32KB) + 2 stages of {Kh,Kl,Vh,Vl}[64][64] (32KB each)
// 128B rows, swizzle ch ^ (row&7).
#define SWZ128(row, ch) ((uint32_t)((row) * 128 + (((ch) ^ ((row) & 7)) * 16)))

__global__ void __launch_bounds__(256) attn_mma_kernel(
    const __nv_bfloat16* __restrict__ qkvh, const __nv_bfloat16* __restrict__ qkvl,
    const int* __restrict__ relm, const unsigned char* __restrict__ amask,
    const float* __restrict__ relA,
    __nv_bfloat16* __restrict__ outh, __nv_bfloat16* __restrict__ outl)
{
    extern __shared__ __align__(128) char smem[];
    const uint32_t sQh = smem_u32(smem);
    const uint32_t sQl = sQh + 16384;
    const uint32_t sStage = sQh + 32768;            // + stage*32768: Kh,Kl,Vh,Vl @ +0,8192,16384,24576
    float* mb = (float*)(smem + 98304);             // [2][64]

    const int tid = threadIdx.x, wid = tid >> 5, lane = tid & 31;
    const int lr = lane & 15, lh = lane >> 4;
    const int b = blockIdx.z, h = blockIdx.y;
    const int q0 = blockIdx.x * 128;

    // ---- Q tiles (hi/lo) via cp.async ----
    #pragma unroll
    for (int t = 0; t < 8; t++) {
        int lin = tid + t * 256;          // 0..2047
        int half = lin >> 10;
        int w = lin & 1023;
        int row = w >> 3, ch = w & 7;
        uint32_t off = (half ? sQl : sQh) + SWZ128(row, ch);
        const __nv_bfloat16* src = (half ? qkvl : qkvh)
            + (size_t)(b * SS + q0 + row) * D3 + h * HDIM + ch * 8;
        cp_async16(off, src);
    }
    cp_commit();

    auto load_kv = [&](int stage, int kt) {
        const int k0 = kt * 64;
        uint32_t base = sStage + stage * 32768;
        #pragma unroll
        for (int t = 0; t < 8; t++) {
            int lin = tid + t * 256;
            int tensor = lin >> 9;        // 0:Kh 1:Kl 2:Vh 3:Vl
            int w = lin & 511;
            int row = w >> 3, ch = w & 7;
            uint32_t off = base + tensor * 8192 + SWZ128(row, ch);
            size_t g = (size_t)(b * SS + k0 + row) * D3 + h * HDIM + ch * 8;
            const __nv_bfloat16* src;
            if      (tensor == 0) src = qkvh + g + DD;
            else if (tensor == 1) src = qkvl + g + DD;
            else if (tensor == 2) src = qkvh + g + 2 * DD;
            else                  src = qkvl + g + 2 * DD;
            cp_async16(off, src);
        }
        if (tid < 64) mb[stage * 64 + tid] = amask[b * SS + k0 + tid] ? -1e30f : 0.f;
    };

    load_kv(0, 0);
    cp_commit();

    asm volatile("cp.async.wait_group 1;\n" ::: "memory");  // Q ready
    __syncthreads();

    // ---- Q fragments (registers, persist) ----
    uint32_t qh[4][4], ql[4][4];
    #pragma unroll
    for (int ks = 0; ks < 4; ks++) {
        uint32_t off = SWZ128(wid * 16 + lr, ks * 2 + lh);
        ldsm4(sQh + off, qh[ks][0], qh[ks][1], qh[ks][2], qh[ks][3]);
        ldsm4(sQl + off, ql[ks][0], ql[ks][1], ql[ks][2], ql[ks][3]);
    }

    // ---- per-row relative logits rs[3] (quad-cooperative over d) ----
    const int r0 = wid * 16 + (lane >> 2);
    float rs00 = 0.f, rs01 = 0.f, rs02 = 0.f;
    float rs10 = 0.f, rs11 = 0.f, rs12 = 0.f;
    {
        const int dbase = (lane & 3) * 16;
        #pragma unroll
        for (int dd = 0; dd < 16; dd++) {
            int d = dbase + dd;
            uint32_t boff = SWZ128(r0, d >> 3) + (d & 7) * 2;
            uint32_t boff1 = SWZ128(r0 + 8, d >> 3) + (d & 7) * 2;
            float q0v = __bfloat162float(*(const __nv_bfloat16*)(smem + boff))
                      + __bfloat162float(*(const __nv_bfloat16*)(smem + 16384 + boff));
            float q1v = __bfloat162float(*(const __nv_bfloat16*)(smem + boff1))
                      + __bfloat162float(*(const __nv_bfloat16*)(smem + 16384 + boff1));
            float a0 = relA[d], a1 = relA[64 + d], a2 = relA[128 + d];
            rs00 += q0v * a0; rs01 += q0v * a1; rs02 += q0v * a2;
            rs10 += q1v * a0; rs11 += q1v * a1; rs12 += q1v * a2;
        }
        #pragma unroll
        for (int off = 1; off <= 2; off <<= 1) {
            rs00 += __shfl_xor_sync(0xffffffffu, rs00, off);
            rs01 += __shfl_xor_sync(0xffffffffu, rs01, off);
            rs02 += __shfl_xor_sync(0xffffffffu, rs02, off);
            rs10 += __shfl_xor_sync(0xffffffffu, rs10, off);
            rs11 += __shfl_xor_sync(0xffffffffu, rs11, off);
            rs12 += __shfl_xor_sync(0xffffffffu, rs12, off);
        }
    }

    float o[8][4];
    #pragma unroll
    for (int nt = 0; nt < 8; nt++)
        #pragma unroll
        for (int j = 0; j < 4; j++) o[nt][j] = 0.f;
    float m0 = -1e30f, m1 = -1e30f, l0 = 0.f, l1 = 0.f;

    for (int kt = 0; kt < SS / 64; kt++) {
        const int cur = kt & 1;
        if (kt + 1 < SS / 64) {
            load_kv((kt + 1) & 1, kt + 1);
            cp_commit();
            asm volatile("cp.async.wait_group 1;\n" ::: "memory");
        } else {
            asm volatile("cp.async.wait_group 0;\n" ::: "memory");
        }
        __syncthreads();

        const uint32_t stg = sStage + cur * 32768;
        const float* mbc = mb + cur * 64;
        const int k0 = kt * 64;

        // ---- S = Q K^T (3 split terms) ----
        float s[8][4];
        #pragma unroll
        for (int nt = 0; nt < 8; nt++)
            #pragma unroll
            for (int j = 0; j < 4; j++) s[nt][j] = 0.f;

        #pragma unroll
        for (int ks = 0; ks < 4; ks++) {
            uint32_t kf[8][2];
            #pragma unroll
            for (int np = 0; np < 4; np++) {
                uint32_t off = stg + SWZ128(np * 16 + lr, ks * 2 + lh);
                ldsm4(off, kf[2*np][0], kf[2*np+1][0], kf[2*np][1], kf[2*np+1][1]);
            }
            #pragma unroll
            for (int nt = 0; nt < 8; nt++) mma_bf16(s[nt], qh[ks], kf[nt]);
            #pragma unroll
            for (int nt = 0; nt < 8; nt++) mma_bf16(s[nt], ql[ks], kf[nt]);
            #pragma unroll
            for (int np = 0; np < 4; np++) {
                uint32_t off = stg + 8192 + SWZ128(np * 16 + lr, ks * 2 + lh);
                ldsm4(off, kf[2*np][0], kf[2*np+1][0], kf[2*np][1], kf[2*np+1][1]);
            }
            #pragma unroll
            for (int nt = 0; nt < 8; nt++) mma_bf16(s[nt], qh[ks], kf[nt]);
        }

        // ---- bias + online softmax (S overwritten by P in place) ----
        float mx0 = -1e30f, mx1 = -1e30f;
        #pragma unroll
        for (int nt = 0; nt < 8; nt++) {
            const int c0 = nt * 8 + (lane & 3) * 2;
            int2 i0 = *(const int2*)(relm + (size_t)(b * SS + q0 + r0) * SS + k0 + c0);
            int2 i1 = *(const int2*)(relm + (size_t)(b * SS + q0 + r0 + 8) * SS + k0 + c0);
            float mb0 = mbc[c0], mb1 = mbc[c0 + 1];
            s[nt][0] = (s[nt][0] + pick3(rs00, rs01, rs02, i0.x + 1)) * 0.125f + mb0;
            s[nt][1] = (s[nt][1] + pick3(rs00, rs01, rs02, i0.y + 1)) * 0.125f + mb1;
            s[nt][2] = (s[nt][2] + pick3(rs10, rs11, rs12, i1.x + 1)) * 0.125f + mb0;
            s[nt][3] = (s[nt][3] + pick3(rs10, rs11, rs12, i1.y + 1)) * 0.125f + mb1;
            mx0 = fmaxf(mx0, fmaxf(s[nt][0], s[nt][1]));
            mx1 = fmaxf(mx1, fmaxf(s[nt][2], s[nt][3]));
        }
        #pragma unroll
        for (int off = 1; off <= 2; off <<= 1) {
            mx0 = fmaxf(mx0, __shfl_xor_sync(0xffffffffu, mx0, off));
            mx1 = fmaxf(mx1, __shfl_xor_sync(0xffffffffu, mx1, off));
        }
        const float mn0 = fmaxf(m0, mx0), mn1 = fmaxf(m1, mx1);
        const float fac0 = __expf(m0 - mn0), fac1 = __expf(m1 - mn1);
        float sum0 = 0.f, sum1 = 0.f;
        #pragma unroll
        for (int nt = 0; nt < 8; nt++) {
            s[nt][0] = __expf(s[nt][0] - mn0);
            s[nt][1] = __expf(s[nt][1] - mn0);
            s[nt][2] = __expf(s[nt][2] - mn1);
            s[nt][3] = __expf(s[nt][3] - mn1);
            sum0 += s[nt][0] + s[nt][1];
            sum1 += s[nt][2] + s[nt][3];
        }
        #pragma unroll
        for (int off = 1; off <= 2; off <<= 1) {
            sum0 += __shfl_xor_sync(0xffffffffu, sum0, off);
            sum1 += __shfl_xor_sync(0xffffffffu, sum1, off);
        }
        l0 = l0 * fac0 + sum0;
        l1 = l1 * fac1 + sum1;
        m0 = mn0; m1 = mn1;
        #pragma unroll
        for (int nt = 0; nt < 8; nt++) {
            o[nt][0] *= fac0; o[nt][1] *= fac0;
            o[nt][2] *= fac1; o[nt][3] *= fac1;
        }

        // ---- O += P V (3 split terms), V via ldmatrix.trans ----
        #pragma unroll
        for (int ks2 = 0; ks2 < 4; ks2++) {
            uint32_t pah[4], pal[4];
            split2(s[2*ks2][0],   s[2*ks2][1],   pah[0], pal[0]);
            split2(s[2*ks2][2],   s[2*ks2][3],   pah[1], pal[1]);
            split2(s[2*ks2+1][0], s[2*ks2+1][1], pah[2], pal[2]);
            split2(s[2*ks2+1][2], s[2*ks2+1][3], pah[3], pal[3]);
            uint32_t vf[8][2];
            #pragma unroll
            for (int np = 0; np < 4; np++) {
                uint32_t off = stg + 16384 + SWZ128(ks2 * 16 + lr, np * 2 + lh);
                ldsm4t(off, vf[2*np][0], vf[2*np][1], vf[2*np+1][0], vf[2*np+1][1]);
            }
            #pragma unroll
            for (int nt = 0; nt < 8; nt++) mma_bf16(o[nt], pah, vf[nt]);
            #pragma unroll
            for (int nt = 0; nt < 8; nt++) mma_bf16(o[nt], pal, vf[nt]);
            #pragma unroll
            for (int np = 0; np < 4; np++) {
                uint32_t off = stg + 24576 + SWZ128(ks2 * 16 + lr, np * 2 + lh);
                ldsm4t(off, vf[2*np][0], vf[2*np][1], vf[2*np+1][0], vf[2*np+1][1]);
            }
            #pragma unroll
            for (int nt = 0; nt < 8; nt++) mma_bf16(o[nt], pah, vf[nt]);
        }
        __syncthreads();
    }

    // ---- finalize: /l, write bf16 hi/lo ----
    const float inv0 = 1.0f / l0, inv1 = 1.0f / l1;
    #pragma unroll
    for (int nt = 0; nt < 8; nt++) {
        const int c0 = nt * 8 + (lane & 3) * 2;
        uint32_t hi0, lo0, hi1, lo1;
        split2(o[nt][0] * inv0, o[nt][1] * inv0, hi0, lo0);
        split2(o[nt][2] * inv1, o[nt][3] * inv1, hi1, lo1);
        size_t base0 = (size_t)(b * SS + q0 + r0) * DD + h * HDIM + c0;
        size_t base1 = (size_t)(b * SS + q0 + r0 + 8) * DD + h * HDIM + c0;
        *(uint32_t*)(outh + base0) = hi0;
        *(uint32_t*)(outl + base0) = lo0;
        *(uint32_t*)(outh + base1) = hi1;
        *(uint32_t*)(outl + base1) = lo1;
    }
}

// ================= launch =================
extern "C" void kernel_launch(void* const* d_in, const int* in_sizes, int n_in,
                              void* d_out, int out_size)
{
    const float*         inp   = (const float*)d_in[0];
    const unsigned char* amask = (const unsigned char*)d_in[1];
    const int*           relm  = (const int*)d_in[2];
    const float*         qkv_w = (const float*)d_in[3];
    const float*         relA  = (const float*)d_in[4];
    const float*         o_w   = (const float*)d_in[5];
    const float*         w1    = (const float*)d_in[6];
    const float*         b1    = (const float*)d_in[7];
    const float*         w2    = (const float*)d_in[8];
    const float*         b2    = (const float*)d_in[9];
    const float*         ln1g  = (const float*)d_in[10];
    const float*         ln1b  = (const float*)d_in[11];
    const float*         ln2g  = (const float*)d_in[12];
    const float*         ln2b  = (const float*)d_in[13];
    float* out = (float*)d_out;

    float *x1;
    __nv_bfloat16 *qsh, *qsl, *xlnh, *xlnl, *hh, *hl, *ah, *al, *ffh, *ffl;
    __nv_bfloat16 *wqh, *wql, *woh, *wol, *w1h, *w1l, *w2h, *w2l;
    cudaGetSymbolAddress((void**)&x1,   g_x1);
    cudaGetSymbolAddress((void**)&qsh,  g_qkvs_h);cudaGetSymbolAddress((void**)&qsl,  g_qkvs_l);
    cudaGetSymbolAddress((void**)&xlnh, g_xln_h); cudaGetSymbolAddress((void**)&xlnl, g_xln_l);
    cudaGetSymbolAddress((void**)&hh,   g_h_h);   cudaGetSymbolAddress((void**)&hl,   g_h_l);
    cudaGetSymbolAddress((void**)&ah,   g_attn_h);cudaGetSymbolAddress((void**)&al,   g_attn_l);
    cudaGetSymbolAddress((void**)&ffh,  g_ff_h);  cudaGetSymbolAddress((void**)&ffl,  g_ff_l);
    cudaGetSymbolAddress((void**)&wqh,  g_wqkv_h);cudaGetSymbolAddress((void**)&wql,  g_wqkv_l);
    cudaGetSymbolAddress((void**)&woh,  g_wo_h);  cudaGetSymbolAddress((void**)&wol,  g_wo_l);
    cudaGetSymbolAddress((void**)&w1h,  g_w1_h);  cudaGetSymbolAddress((void**)&w1l,  g_w1_l);
    cudaGetSymbolAddress((void**)&w2h,  g_w2_h);  cudaGetSymbolAddress((void**)&w2l,  g_w2_l);

    const int SMEM = 65536;
    const int ASMEM = 98816;
    cudaFuncSetAttribute(mma_gemm<false,false,false,true >, cudaFuncAttributeMaxDynamicSharedMemorySize, SMEM);
    cudaFuncSetAttribute(mma_gemm<false,false,true ,false>, cudaFuncAttributeMaxDynamicSharedMemorySize, SMEM);
    cudaFuncSetAttribute(mma_gemm<true ,true ,false,true >, cudaFuncAttributeMaxDynamicSharedMemorySize, SMEM);
    cudaFuncSetAttribute(mma_gemm<false,true ,true ,false>, cudaFuncAttributeMaxDynamicSharedMemorySize, SMEM);
    cudaFuncSetAttribute(attn_mma_kernel, cudaFuncAttributeMaxDynamicSharedMemorySize, ASMEM);

    // 0) split weights to bf16 hi/lo
    split_kernel<<<(D3*DD/4 + 255)/256, 256>>>(qkv_w, wqh, wql, D3*DD);
    split_kernel<<<(DD*DD/4 + 255)/256, 256>>>(o_w,   woh, wol, DD*DD);
    split_kernel<<<(DFF*DD/4 + 255)/256, 256>>>(w1,   w1h, w1l, DFF*DD);
    split_kernel<<<(DD*DFF/4 + 255)/256, 256>>>(w2,   w2h, w2l, DD*DFF);

    // 1) LN1 -> xln (bf16 split)
    ln_kernel<<<NROW, 256>>>(inp, ln1g, ln1b, xlnh, xlnl);

    // 2) QKV = xln @ qkv_w^T  -> bf16 hi/lo
    mma_gemm<false,false,false,true><<<dim3(D3/128, NROW/128), 256, SMEM>>>(
        xlnh, xlnl, wqh, wql, nullptr, nullptr, nullptr, qsh, qsl, NROW, D3, DD);

    // 3) attention (HMMA) -> attn bf16 hi/lo
    attn_mma_kernel<<<dim3(SS/128, HH, BB), 256, ASMEM>>>(
        qsh, qsl, relm, amask, relA, ah, al);

    // 4) x1 = inp + attn @ o_w^T  (fp32 out)
    mma_gemm<false,false,true,false><<<dim3(DD/128, NROW/128), 256, SMEM>>>(
        ah, al, woh, wol, nullptr, inp, x1, nullptr, nullptr, NROW, DD, DD);

    // 5) LN2 -> h (bf16 split)
    ln_kernel<<<NROW, 256>>>(x1, ln2g, ln2b, hh, hl);

    // 6) ff = relu(h @ w1^T + b1) -> bf16 hi/lo
    mma_gemm<true,true,false,true><<<dim3(DFF/128, NROW/128), 256, SMEM>>>(
        hh, hl, w1h, w1l, b1, nullptr, nullptr, ffh, ffl, NROW, DFF, DD);

    // 7) out = x1 + ff @ w2^T + b2 (fp32 out)
    mma_gemm<false,true,true,false><<<dim3(DD/128, NROW/128), 256, SMEM>>>(
        ffh, ffl, w2h, w2l, b2, x1, out, nullptr, nullptr, NROW, DD, DFF);
}

// round 6
// speedup vs baseline: 3.6413x; 1.0722x over previous
#include <cuda_runtime.h>
#include <cuda_bf16.h>
#include <cstdint>

// ---------------- problem constants ----------------
#define BB   2
#define SS   1024
#define DD   768
#define HH   12
#define HDIM 64
#define DFF  3072
#define NROW (BB*SS)        // 2048
#define D3   (3*DD)         // 2304

// ---------------- scratch (device globals, no allocs) ----------------
__device__ __align__(16) float g_x1  [NROW*DD];
__device__ __align__(16) unsigned char g_rel8[NROW*SS];

__device__ __align__(16) __nv_bfloat16 g_qkvs_h[NROW*D3], g_qkvs_l[NROW*D3];
__device__ __align__(16) __nv_bfloat16 g_xln_h [NROW*DD],  g_xln_l [NROW*DD];
__device__ __align__(16) __nv_bfloat16 g_h_h   [NROW*DD],  g_h_l   [NROW*DD];
__device__ __align__(16) __nv_bfloat16 g_attn_h[NROW*DD],  g_attn_l[NROW*DD];
__device__ __align__(16) __nv_bfloat16 g_ff_h  [NROW*DFF], g_ff_l  [NROW*DFF];
__device__ __align__(16) __nv_bfloat16 g_wqkv_h[D3*DD],    g_wqkv_l[D3*DD];
__device__ __align__(16) __nv_bfloat16 g_wo_h  [DD*DD],    g_wo_l  [DD*DD];
__device__ __align__(16) __nv_bfloat16 g_w1_h  [DFF*DD],   g_w1_l  [DFF*DD];
__device__ __align__(16) __nv_bfloat16 g_w2_h  [DD*DFF],   g_w2_l  [DD*DFF];

// ================= helpers =================
__device__ __forceinline__ uint32_t smem_u32(const void* p) {
    uint32_t a;
    asm("{ .reg .u64 t; cvta.to.shared.u64 t, %1; cvt.u32.u64 %0, t; }" : "=r"(a) : "l"(p));
    return a;
}
__device__ __forceinline__ void cp_async16(uint32_t dst, const void* src) {
    asm volatile("cp.async.cg.shared.global [%0], [%1], 16;\n" :: "r"(dst), "l"(src));
}
__device__ __forceinline__ void cp_commit() { asm volatile("cp.async.commit_group;\n" ::: "memory"); }

__device__ __forceinline__ void ldsm4(uint32_t addr, uint32_t& r0, uint32_t& r1, uint32_t& r2, uint32_t& r3) {
    asm volatile("ldmatrix.sync.aligned.m8n8.x4.shared.b16 {%0,%1,%2,%3}, [%4];"
                 : "=r"(r0), "=r"(r1), "=r"(r2), "=r"(r3) : "r"(addr));
}
__device__ __forceinline__ void ldsm4t(uint32_t addr, uint32_t& r0, uint32_t& r1, uint32_t& r2, uint32_t& r3) {
    asm volatile("ldmatrix.sync.aligned.m8n8.x4.trans.shared.b16 {%0,%1,%2,%3}, [%4];"
                 : "=r"(r0), "=r"(r1), "=r"(r2), "=r"(r3) : "r"(addr));
}
__device__ __forceinline__ void mma_bf16(float* c, const uint32_t* a, const uint32_t* b) {
    asm volatile("mma.sync.aligned.m16n8k16.row.col.f32.bf16.bf16.f32 "
                 "{%0,%1,%2,%3}, {%4,%5,%6,%7}, {%8,%9}, {%0,%1,%2,%3};"
                 : "+f"(c[0]), "+f"(c[1]), "+f"(c[2]), "+f"(c[3])
                 : "r"(a[0]), "r"(a[1]), "r"(a[2]), "r"(a[3]), "r"(b[0]), "r"(b[1]));
}
__device__ __forceinline__ void split2(float a, float b, uint32_t& hi, uint32_t& lo) {
    __nv_bfloat16 ha = __float2bfloat16(a), hb = __float2bfloat16(b);
    __nv_bfloat162 hh; hh.x = ha; hh.y = hb;
    __nv_bfloat162 ll;
    ll.x = __float2bfloat16(a - __bfloat162float(ha));
    ll.y = __float2bfloat16(b - __bfloat162float(hb));
    hi = *(uint32_t*)&hh; lo = *(uint32_t*)&ll;
}
__device__ __forceinline__ float pick3(float a, float b, float c, int i) {
    return i == 0 ? a : (i == 1 ? b : c);
}

// ================= fp32 -> bf16 hi/lo split (weights) =================
__global__ void __launch_bounds__(256) split_kernel(
    const float* __restrict__ x, __nv_bfloat16* __restrict__ hi,
    __nv_bfloat16* __restrict__ lo, int n)
{
    int i = (blockIdx.x * 256 + threadIdx.x) * 4;
    if (i >= n) return;
    float4 v = *(const float4*)(x + i);
    uint32_t h0, l0, h1, l1;
    split2(v.x, v.y, h0, l0);
    split2(v.z, v.w, h1, l1);
    *(uint32_t*)(hi + i)     = h0;
    *(uint32_t*)(hi + i + 2) = h1;
    *(uint32_t*)(lo + i)     = l0;
    *(uint32_t*)(lo + i + 2) = l1;
}

// ================= relm int32 -> uint8 (idx+1) =================
__global__ void __launch_bounds__(256) rel8_kernel(
    const int* __restrict__ relm, unsigned char* __restrict__ out)
{
    int i = blockIdx.x * 256 + threadIdx.x;
    int4 v = ((const int4*)relm)[i];
    uchar4 o;
    o.x = (unsigned char)(v.x + 1); o.y = (unsigned char)(v.y + 1);
    o.z = (unsigned char)(v.z + 1); o.w = (unsigned char)(v.w + 1);
    ((uchar4*)out)[i] = o;
}

// ================= LayerNorm (fused bf16 hi/lo split output) =================
__global__ void __launch_bounds__(256) ln_kernel(
    const float* __restrict__ x, const float* __restrict__ g,
    const float* __restrict__ bt, __nv_bfloat16* __restrict__ yh,
    __nv_bfloat16* __restrict__ yl)
{
    __shared__ float red[8];
    __shared__ float red2[8];
    const int row = blockIdx.x;
    const int tid = threadIdx.x;
    const float* xr = x + (size_t)row * DD;

    float v0 = xr[tid], v1 = xr[tid + 256], v2 = xr[tid + 512];
    float s = v0 + v1 + v2;
    #pragma unroll
    for (int off = 16; off >= 1; off >>= 1)
        s += __shfl_xor_sync(0xffffffffu, s, off);
    if ((tid & 31) == 0) red[tid >> 5] = s;
    __syncthreads();
    float tot = 0.f;
    #pragma unroll
    for (int i = 0; i < 8; i++) tot += red[i];
    const float mean = tot * (1.0f / DD);

    float d0 = v0 - mean, d1 = v1 - mean, d2 = v2 - mean;
    float ss = d0*d0 + d1*d1 + d2*d2;
    #pragma unroll
    for (int off = 16; off >= 1; off >>= 1)
        ss += __shfl_xor_sync(0xffffffffu, ss, off);
    if ((tid & 31) == 0) red2[tid >> 5] = ss;
    __syncthreads();
    float vtot = 0.f;
    #pragma unroll
    for (int i = 0; i < 8; i++) vtot += red2[i];
    const float rstd = rsqrtf(vtot * (1.0f / DD) + 1e-5f);

    #pragma unroll
    for (int j = 0; j < 3; j++) {
        int c = tid + j * 256;
        float dv = (j == 0 ? d0 : (j == 1 ? d1 : d2));
        float val = dv * rstd * g[c] + bt[c];
        __nv_bfloat16 h = __float2bfloat16(val);
        yh[(size_t)row * DD + c] = h;
        yl[(size_t)row * DD + c] = __float2bfloat16(val - __bfloat162float(h));
    }
}

// ================= HMMA GEMM: 3-stage pipeline, 1 sync/iter ==================
#define SWZOFF(row, ch) ((uint32_t)((row) * 64 + (((ch) ^ (((row) >> 1) & 3)) * 16)))

template<bool RELU, bool BIAS, bool RESID, bool SPLIT>
__global__ void __launch_bounds__(256, 1) mma_gemm(
    const __nv_bfloat16* __restrict__ Ahi, const __nv_bfloat16* __restrict__ Alo,
    const __nv_bfloat16* __restrict__ Bhi, const __nv_bfloat16* __restrict__ Blo,
    const float* __restrict__ bias, const float* __restrict__ resid,
    float* __restrict__ C, __nv_bfloat16* __restrict__ Chi, __nv_bfloat16* __restrict__ Clo,
    int M, int N, int K)
{
    extern __shared__ __align__(128) char smem[];
    const uint32_t sb = smem_u32(smem);

    const int tid = threadIdx.x;
    const int wid = tid >> 5, lane = tid & 31;
    const int warp_m = wid & 3, warp_n = wid >> 2;
    const int m0 = blockIdx.y * 128, n0 = blockIdx.x * 128;

    float acc[2][8][4];
    #pragma unroll
    for (int mt = 0; mt < 2; mt++)
        #pragma unroll
        for (int nt = 0; nt < 8; nt++)
            #pragma unroll
            for (int j = 0; j < 4; j++) acc[mt][nt][j] = 0.f;

    const int niter = K >> 5;

    auto load_stage = [&](int buf, int k0) {
        uint32_t base = sb + buf * 32768;
        #pragma unroll
        for (int t = 0; t < 8; t++) {
            int lin  = tid + t * 256;
            int tile = lin >> 9;
            int w    = lin & 511;
            int row  = w >> 2, ch = w & 3;
            uint32_t so = base + tile * 8192 + SWZOFF(row, ch);
            const __nv_bfloat16* src;
            if      (tile == 0) src = Ahi + (size_t)(m0 + row) * K + k0 + ch * 8;
            else if (tile == 1) src = Alo + (size_t)(m0 + row) * K + k0 + ch * 8;
            else if (tile == 2) src = Bhi + (size_t)(n0 + row) * K + k0 + ch * 8;
            else                src = Blo + (size_t)(n0 + row) * K + k0 + ch * 8;
            cp_async16(so, src);
        }
        cp_commit();
    };

    load_stage(0, 0);
    load_stage(1, 32);

    const int lr = lane & 15, lh = lane >> 4;

    int buf = 0;
    for (int it = 0; it < niter; it++) {
        if (it + 1 < niter) {
            asm volatile("cp.async.wait_group 1;\n" ::: "memory");
        } else {
            asm volatile("cp.async.wait_group 0;\n" ::: "memory");
        }
        __syncthreads();
        if (it + 2 < niter) {
            int nb = buf + 2; if (nb >= 3) nb -= 3;
            load_stage(nb, (it + 2) * 32);
        }

        const uint32_t base = sb + buf * 32768;
        #pragma unroll
        for (int ks = 0; ks < 2; ks++) {
            const int ch = ks * 2 + lh;
            uint32_t ah[2][4], alo[2][4];
            #pragma unroll
            for (int mt = 0; mt < 2; mt++) {
                int row = warp_m * 32 + mt * 16 + lr;
                uint32_t off = SWZOFF(row, ch);
                ldsm4(base + off,        ah[mt][0],  ah[mt][1],  ah[mt][2],  ah[mt][3]);
                ldsm4(base + 8192 + off, alo[mt][0], alo[mt][1], alo[mt][2], alo[mt][3]);
            }
            uint32_t bh[8][2];
            #pragma unroll
            for (int np = 0; np < 4; np++) {
                int row = warp_n * 64 + np * 16 + lr;
                uint32_t off = base + 16384 + SWZOFF(row, ch);
                ldsm4(off, bh[2*np][0], bh[2*np+1][0], bh[2*np][1], bh[2*np+1][1]);
            }
            #pragma unroll
            for (int mt = 0; mt < 2; mt++)
                #pragma unroll
                for (int nt = 0; nt < 8; nt++)
                    mma_bf16(acc[mt][nt], ah[mt], bh[nt]);
            #pragma unroll
            for (int mt = 0; mt < 2; mt++)
                #pragma unroll
                for (int nt = 0; nt < 8; nt++)
                    mma_bf16(acc[mt][nt], alo[mt], bh[nt]);
            uint32_t bl[8][2];
            #pragma unroll
            for (int np = 0; np < 4; np++) {
                int row = warp_n * 64 + np * 16 + lr;
                uint32_t off = base + 24576 + SWZOFF(row, ch);
                ldsm4(off, bl[2*np][0], bl[2*np+1][0], bl[2*np][1], bl[2*np+1][1]);
            }
            #pragma unroll
            for (int mt = 0; mt < 2; mt++)
                #pragma unroll
                for (int nt = 0; nt < 8; nt++)
                    mma_bf16(acc[mt][nt], ah[mt], bl[nt]);
        }
        if (++buf >= 3) buf = 0;
    }

    #pragma unroll
    for (int mt = 0; mt < 2; mt++) {
        #pragma unroll
        for (int half = 0; half < 2; half++) {
            const int m = m0 + warp_m * 32 + mt * 16 + (lane >> 2) + half * 8;
            #pragma unroll
            for (int nt = 0; nt < 8; nt++) {
                const int n = n0 + warp_n * 64 + nt * 8 + (lane & 3) * 2;
                float v0 = acc[mt][nt][half * 2 + 0];
                float v1 = acc[mt][nt][half * 2 + 1];
                if (BIAS) { v0 += bias[n]; v1 += bias[n + 1]; }
                if (RELU) { v0 = fmaxf(v0, 0.f); v1 = fmaxf(v1, 0.f); }
                if (RESID) {
                    float2 rv = *(const float2*)(resid + (size_t)m * N + n);
                    v0 += rv.x; v1 += rv.y;
                }
                if (SPLIT) {
                    uint32_t hi, lo;
                    split2(v0, v1, hi, lo);
                    *(uint32_t*)(Chi + (size_t)m * N + n) = hi;
                    *(uint32_t*)(Clo + (size_t)m * N + n) = lo;
                } else {
                    float2 o2; o2.x = v0; o2.y = v1;
                    *(float2*)(C + (size_t)m * N + n) = o2;
                }
            }
        }
    }
}

// ================= HMMA flash attention with relative bias ==================
// CTA: 128 q rows of one (b,h). 8 warps x 16 rows. Key tiles of 64.
// 1 sync per tile; next-KV cp.async issued after the sync, hidden by compute.
#define SWZ128(row, ch) ((uint32_t)((row) * 128 + (((ch) ^ ((row) & 7)) * 16)))

__global__ void __launch_bounds__(256) attn_mma_kernel(
    const __nv_bfloat16* __restrict__ qkvh, const __nv_bfloat16* __restrict__ qkvl,
    const unsigned char* __restrict__ rel8, const unsigned char* __restrict__ amask,
    const float* __restrict__ relA,
    __nv_bfloat16* __restrict__ outh, __nv_bfloat16* __restrict__ outl)
{
    extern __shared__ __align__(128) char smem[];
    const uint32_t sQh = smem_u32(smem);
    const uint32_t sQl = sQh + 16384;
    const uint32_t sStage = sQh + 32768;            // + stage*32768: Kh,Kl,Vh,Vl
    float* mb = (float*)(smem + 98304);             // [2][64]

    const int tid = threadIdx.x, wid = tid >> 5, lane = tid & 31;
    const int lr = lane & 15, lh = lane >> 4;
    const int b = blockIdx.z, h = blockIdx.y;
    const int q0 = blockIdx.x * 128;

    // ---- Q tiles (hi/lo) via cp.async ----
    #pragma unroll
    for (int t = 0; t < 8; t++) {
        int lin = tid + t * 256;
        int half = lin >> 10;
        int w = lin & 1023;
        int row = w >> 3, ch = w & 7;
        uint32_t off = (half ? sQl : sQh) + SWZ128(row, ch);
        const __nv_bfloat16* src = (half ? qkvl : qkvh)
            + (size_t)(b * SS + q0 + row) * D3 + h * HDIM + ch * 8;
        cp_async16(off, src);
    }
    cp_commit();

    auto load_kv = [&](int stage, int kt) {
        const int k0 = kt * 64;
        uint32_t base = sStage + stage * 32768;
        #pragma unroll
        for (int t = 0; t < 8; t++) {
            int lin = tid + t * 256;
            int tensor = lin >> 9;        // 0:Kh 1:Kl 2:Vh 3:Vl
            int w = lin & 511;
            int row = w >> 3, ch = w & 7;
            uint32_t off = base + tensor * 8192 + SWZ128(row, ch);
            size_t g = (size_t)(b * SS + k0 + row) * D3 + h * HDIM + ch * 8;
            const __nv_bfloat16* src;
            if      (tensor == 0) src = qkvh + g + DD;
            else if (tensor == 1) src = qkvl + g + DD;
            else if (tensor == 2) src = qkvh + g + 2 * DD;
            else                  src = qkvl + g + 2 * DD;
            cp_async16(off, src);
        }
        if (tid < 64) mb[stage * 64 + tid] = amask[b * SS + k0 + tid] ? -1e30f : 0.f;
        cp_commit();
    };

    load_kv(0, 0);

    asm volatile("cp.async.wait_group 1;\n" ::: "memory");  // Q ready
    __syncthreads();

    // ---- Q fragments (registers, persist) ----
    uint32_t qh[4][4], ql[4][4];
    #pragma unroll
    for (int ks = 0; ks < 4; ks++) {
        uint32_t off = SWZ128(wid * 16 + lr, ks * 2 + lh);
        ldsm4(sQh + off, qh[ks][0], qh[ks][1], qh[ks][2], qh[ks][3]);
        ldsm4(sQl + off, ql[ks][0], ql[ks][1], ql[ks][2], ql[ks][3]);
    }

    // ---- per-row relative logits rs[3] (quad-cooperative over d) ----
    const int r0 = wid * 16 + (lane >> 2);
    float rs00 = 0.f, rs01 = 0.f, rs02 = 0.f;
    float rs10 = 0.f, rs11 = 0.f, rs12 = 0.f;
    {
        const int dbase = (lane & 3) * 16;
        #pragma unroll
        for (int dd = 0; dd < 16; dd++) {
            int d = dbase + dd;
            uint32_t boff = SWZ128(r0, d >> 3) + (d & 7) * 2;
            uint32_t boff1 = SWZ128(r0 + 8, d >> 3) + (d & 7) * 2;
            float q0v = __bfloat162float(*(const __nv_bfloat16*)(smem + boff))
                      + __bfloat162float(*(const __nv_bfloat16*)(smem + 16384 + boff));
            float q1v = __bfloat162float(*(const __nv_bfloat16*)(smem + boff1))
                      + __bfloat162float(*(const __nv_bfloat16*)(smem + 16384 + boff1));
            float a0 = relA[d], a1 = relA[64 + d], a2 = relA[128 + d];
            rs00 += q0v * a0; rs01 += q0v * a1; rs02 += q0v * a2;
            rs10 += q1v * a0; rs11 += q1v * a1; rs12 += q1v * a2;
        }
        #pragma unroll
        for (int off = 1; off <= 2; off <<= 1) {
            rs00 += __shfl_xor_sync(0xffffffffu, rs00, off);
            rs01 += __shfl_xor_sync(0xffffffffu, rs01, off);
            rs02 += __shfl_xor_sync(0xffffffffu, rs02, off);
            rs10 += __shfl_xor_sync(0xffffffffu, rs10, off);
            rs11 += __shfl_xor_sync(0xffffffffu, rs11, off);
            rs12 += __shfl_xor_sync(0xffffffffu, rs12, off);
        }
    }

    float o[8][4];
    #pragma unroll
    for (int nt = 0; nt < 8; nt++)
        #pragma unroll
        for (int j = 0; j < 4; j++) o[nt][j] = 0.f;
    float m0 = -1e30f, m1 = -1e30f, l0 = 0.f, l1 = 0.f;

    for (int kt = 0; kt < SS / 64; kt++) {
        const int cur = kt & 1;
        asm volatile("cp.async.wait_group 0;\n" ::: "memory");  // stage kt ready
        __syncthreads();                                         // + prev compute retired
        if (kt + 1 < SS / 64) load_kv((kt + 1) & 1, kt + 1);

        const uint32_t stg = sStage + cur * 32768;
        const float* mbc = mb + cur * 64;
        const int k0 = kt * 64;

        // ---- S = Q K^T (3 split terms) ----
        float s[8][4];
        #pragma unroll
        for (int nt = 0; nt < 8; nt++)
            #pragma unroll
            for (int j = 0; j < 4; j++) s[nt][j] = 0.f;

        #pragma unroll
        for (int ks = 0; ks < 4; ks++) {
            uint32_t kf[8][2];
            #pragma unroll
            for (int np = 0; np < 4; np++) {
                uint32_t off = stg + SWZ128(np * 16 + lr, ks * 2 + lh);
                ldsm4(off, kf[2*np][0], kf[2*np+1][0], kf[2*np][1], kf[2*np+1][1]);
            }
            #pragma unroll
            for (int nt = 0; nt < 8; nt++) mma_bf16(s[nt], qh[ks], kf[nt]);
            #pragma unroll
            for (int nt = 0; nt < 8; nt++) mma_bf16(s[nt], ql[ks], kf[nt]);
            #pragma unroll
            for (int np = 0; np < 4; np++) {
                uint32_t off = stg + 8192 + SWZ128(np * 16 + lr, ks * 2 + lh);
                ldsm4(off, kf[2*np][0], kf[2*np+1][0], kf[2*np][1], kf[2*np+1][1]);
            }
            #pragma unroll
            for (int nt = 0; nt < 8; nt++) mma_bf16(s[nt], qh[ks], kf[nt]);
        }

        // ---- bias + online softmax ----
        float mx0 = -1e30f, mx1 = -1e30f;
        #pragma unroll
        for (int nt = 0; nt < 8; nt++) {
            const int c0 = nt * 8 + (lane & 3) * 2;
            uchar2 i0 = *(const uchar2*)(rel8 + (size_t)(b * SS + q0 + r0) * SS + k0 + c0);
            uchar2 i1 = *(const uchar2*)(rel8 + (size_t)(b * SS + q0 + r0 + 8) * SS + k0 + c0);
            float mb0 = mbc[c0], mb1 = mbc[c0 + 1];
            s[nt][0] = (s[nt][0] + pick3(rs00, rs01, rs02, i0.x)) * 0.125f + mb0;
            s[nt][1] = (s[nt][1] + pick3(rs00, rs01, rs02, i0.y)) * 0.125f + mb1;
            s[nt][2] = (s[nt][2] + pick3(rs10, rs11, rs12, i1.x)) * 0.125f + mb0;
            s[nt][3] = (s[nt][3] + pick3(rs10, rs11, rs12, i1.y)) * 0.125f + mb1;
            mx0 = fmaxf(mx0, fmaxf(s[nt][0], s[nt][1]));
            mx1 = fmaxf(mx1, fmaxf(s[nt][2], s[nt][3]));
        }
        #pragma unroll
        for (int off = 1; off <= 2; off <<= 1) {
            mx0 = fmaxf(mx0, __shfl_xor_sync(0xffffffffu, mx0, off));
            mx1 = fmaxf(mx1, __shfl_xor_sync(0xffffffffu, mx1, off));
        }
        const float mn0 = fmaxf(m0, mx0), mn1 = fmaxf(m1, mx1);
        const float fac0 = __expf(m0 - mn0), fac1 = __expf(m1 - mn1);
        float sum0 = 0.f, sum1 = 0.f;
        #pragma unroll
        for (int nt = 0; nt < 8; nt++) {
            s[nt][0] = __expf(s[nt][0] - mn0);
            s[nt][1] = __expf(s[nt][1] - mn0);
            s[nt][2] = __expf(s[nt][2] - mn1);
            s[nt][3] = __expf(s[nt][3] - mn1);
            sum0 += s[nt][0] + s[nt][1];
            sum1 += s[nt][2] + s[nt][3];
        }
        #pragma unroll
        for (int off = 1; off <= 2; off <<= 1) {
            sum0 += __shfl_xor_sync(0xffffffffu, sum0, off);
            sum1 += __shfl_xor_sync(0xffffffffu, sum1, off);
        }
        l0 = l0 * fac0 + sum0;
        l1 = l1 * fac1 + sum1;
        m0 = mn0; m1 = mn1;
        #pragma unroll
        for (int nt = 0; nt < 8; nt++) {
            o[nt][0] *= fac0; o[nt][1] *= fac0;
            o[nt][2] *= fac1; o[nt][3] *= fac1;
        }

        // ---- O += P V (3 split terms), V via ldmatrix.trans ----
        #pragma unroll
        for (int ks2 = 0; ks2 < 4; ks2++) {
            uint32_t pah[4], pal[4];
            split2(s[2*ks2][0],   s[2*ks2][1],   pah[0], pal[0]);
            split2(s[2*ks2][2],   s[2*ks2][3],   pah[1], pal[1]);
            split2(s[2*ks2+1][0], s[2*ks2+1][1], pah[2], pal[2]);
            split2(s[2*ks2+1][2], s[2*ks2+1][3], pah[3], pal[3]);
            uint32_t vf[8][2];
            #pragma unroll
            for (int np = 0; np < 4; np++) {
                uint32_t off = stg + 16384 + SWZ128(ks2 * 16 + lr, np * 2 + lh);
                ldsm4t(off, vf[2*np][0], vf[2*np][1], vf[2*np+1][0], vf[2*np+1][1]);
            }
            #pragma unroll
            for (int nt = 0; nt < 8; nt++) mma_bf16(o[nt], pah, vf[nt]);
            #pragma unroll
            for (int nt = 0; nt < 8; nt++) mma_bf16(o[nt], pal, vf[nt]);
            #pragma unroll
            for (int np = 0; np < 4; np++) {
                uint32_t off = stg + 24576 + SWZ128(ks2 * 16 + lr, np * 2 + lh);
                ldsm4t(off, vf[2*np][0], vf[2*np][1], vf[2*np+1][0], vf[2*np+1][1]);
            }
            #pragma unroll
            for (int nt = 0; nt < 8; nt++) mma_bf16(o[nt], pah, vf[nt]);
        }
    }

    // ---- finalize: /l, write bf16 hi/lo ----
    const float inv0 = 1.0f / l0, inv1 = 1.0f / l1;
    #pragma unroll
    for (int nt = 0; nt < 8; nt++) {
        const int c0 = nt * 8 + (lane & 3) * 2;
        uint32_t hi0, lo0, hi1, lo1;
        split2(o[nt][0] * inv0, o[nt][1] * inv0, hi0, lo0);
        split2(o[nt][2] * inv1, o[nt][3] * inv1, hi1, lo1);
        size_t base0 = (size_t)(b * SS + q0 + r0) * DD + h * HDIM + c0;
        size_t base1 = (size_t)(b * SS + q0 + r0 + 8) * DD + h * HDIM + c0;
        *(uint32_t*)(outh + base0) = hi0;
        *(uint32_t*)(outl + base0) = lo0;
        *(uint32_t*)(outh + base1) = hi1;
        *(uint32_t*)(outl + base1) = lo1;
    }
}

// ================= launch =================
extern "C" void kernel_launch(void* const* d_in, const int* in_sizes, int n_in,
                              void* d_out, int out_size)
{
    const float*         inp   = (const float*)d_in[0];
    const unsigned char* amask = (const unsigned char*)d_in[1];
    const int*           relm  = (const int*)d_in[2];
    const float*         qkv_w = (const float*)d_in[3];
    const float*         relA  = (const float*)d_in[4];
    const float*         o_w   = (const float*)d_in[5];
    const float*         w1    = (const float*)d_in[6];
    const float*         b1    = (const float*)d_in[7];
    const float*         w2    = (const float*)d_in[8];
    const float*         b2    = (const float*)d_in[9];
    const float*         ln1g  = (const float*)d_in[10];
    const float*         ln1b  = (const float*)d_in[11];
    const float*         ln2g  = (const float*)d_in[12];
    const float*         ln2b  = (const float*)d_in[13];
    float* out = (float*)d_out;

    float *x1;
    unsigned char* rel8;
    __nv_bfloat16 *qsh, *qsl, *xlnh, *xlnl, *hh, *hl, *ah, *al, *ffh, *ffl;
    __nv_bfloat16 *wqh, *wql, *woh, *wol, *w1h, *w1l, *w2h, *w2l;
    cudaGetSymbolAddress((void**)&x1,   g_x1);
    cudaGetSymbolAddress((void**)&rel8, g_rel8);
    cudaGetSymbolAddress((void**)&qsh,  g_qkvs_h);cudaGetSymbolAddress((void**)&qsl,  g_qkvs_l);
    cudaGetSymbolAddress((void**)&xlnh, g_xln_h); cudaGetSymbolAddress((void**)&xlnl, g_xln_l);
    cudaGetSymbolAddress((void**)&hh,   g_h_h);   cudaGetSymbolAddress((void**)&hl,   g_h_l);
    cudaGetSymbolAddress((void**)&ah,   g_attn_h);cudaGetSymbolAddress((void**)&al,   g_attn_l);
    cudaGetSymbolAddress((void**)&ffh,  g_ff_h);  cudaGetSymbolAddress((void**)&ffl,  g_ff_l);
    cudaGetSymbolAddress((void**)&wqh,  g_wqkv_h);cudaGetSymbolAddress((void**)&wql,  g_wqkv_l);
    cudaGetSymbolAddress((void**)&woh,  g_wo_h);  cudaGetSymbolAddress((void**)&wol,  g_wo_l);
    cudaGetSymbolAddress((void**)&w1h,  g_w1_h);  cudaGetSymbolAddress((void**)&w1l,  g_w1_l);
    cudaGetSymbolAddress((void**)&w2h,  g_w2_h);  cudaGetSymbolAddress((void**)&w2l,  g_w2_l);

    const int SMEM = 98304;
    const int ASMEM = 98816;
    cudaFuncSetAttribute(mma_gemm<false,false,false,true >, cudaFuncAttributeMaxDynamicSharedMemorySize, SMEM);
    cudaFuncSetAttribute(mma_gemm<false,false,true ,false>, cudaFuncAttributeMaxDynamicSharedMemorySize, SMEM);
    cudaFuncSetAttribute(mma_gemm<true ,true ,false,true >, cudaFuncAttributeMaxDynamicSharedMemorySize, SMEM);
    cudaFuncSetAttribute(mma_gemm<false,true ,true ,false>, cudaFuncAttributeMaxDynamicSharedMemorySize, SMEM);
    cudaFuncSetAttribute(attn_mma_kernel, cudaFuncAttributeMaxDynamicSharedMemorySize, ASMEM);

    // 0) preprocessing: weight splits + relm->uint8
    split_kernel<<<(D3*DD/4 + 255)/256, 256>>>(qkv_w, wqh, wql, D3*DD);
    split_kernel<<<(DD*DD/4 + 255)/256, 256>>>(o_w,   woh, wol, DD*DD);
    split_kernel<<<(DFF*DD/4 + 255)/256, 256>>>(w1,   w1h, w1l, DFF*DD);
    split_kernel<<<(DD*DFF/4 + 255)/256, 256>>>(w2,   w2h, w2l, DD*DFF);
    rel8_kernel<<<NROW*SS/4/256, 256>>>(relm, rel8);

    // 1) LN1 -> xln (bf16 split)
    ln_kernel<<<NROW, 256>>>(inp, ln1g, ln1b, xlnh, xlnl);

    // 2) QKV = xln @ qkv_w^T  -> bf16 hi/lo
    mma_gemm<false,false,false,true><<<dim3(D3/128, NROW/128), 256, SMEM>>>(
        xlnh, xlnl, wqh, wql, nullptr, nullptr, nullptr, qsh, qsl, NROW, D3, DD);

    // 3) attention (HMMA) -> attn bf16 hi/lo
    attn_mma_kernel<<<dim3(SS/128, HH, BB), 256, ASMEM>>>(
        qsh, qsl, rel8, amask, relA, ah, al);

    // 4) x1 = inp + attn @ o_w^T  (fp32 out)
    mma_gemm<false,false,true,false><<<dim3(DD/128, NROW/128), 256, SMEM>>>(
        ah, al, woh, wol, nullptr, inp, x1, nullptr, nullptr, NROW, DD, DD);

    // 5) LN2 -> h (bf16 split)
    ln_kernel<<<NROW, 256>>>(x1, ln2g, ln2b, hh, hl);

    // 6) ff = relu(h @ w1^T + b1) -> bf16 hi/lo
    mma_gemm<true,true,false,true><<<dim3(DFF/128, NROW/128), 256, SMEM>>>(
        hh, hl, w1h, w1l, b1, nullptr, nullptr, ffh, ffl, NROW, DFF, DD);

    // 7) out = x1 + ff @ w2^T + b2 (fp32 out)
    mma_gemm<false,true,true,false><<<dim3(DD/128, NROW/128), 256, SMEM>>>(
        ffh, ffl, w2h, w2l, b2, x1, out, nullptr, nullptr, NROW, DD, DFF);
}

// round 8
// speedup vs baseline: 4.4812x; 1.2306x over previous
#include <cuda_runtime.h>
#include <cuda_bf16.h>
#include <cuda_fp16.h>
#include <cstdint>

// ---------------- problem constants ----------------
#define BB   2
#define SS   1024
#define DD   768
#define HH   12
#define HDIM 64
#define DFF  3072
#define NROW (BB*SS)        // 2048
#define D3   (3*DD)         // 2304

// ---------------- scratch (device globals, no allocs) ----------------
__device__ __align__(16) float g_x1  [NROW*DD];
__device__ __align__(16) unsigned char g_rel8[NROW*SS];

__device__ __align__(16) __half g_xln [NROW*DD];
__device__ __align__(16) __half g_h   [NROW*DD];
__device__ __align__(16) __half g_attn[NROW*DD];
__device__ __align__(16) __half g_ff  [NROW*DFF];
__device__ __align__(16) __nv_bfloat16 g_qkvs_h[NROW*D3], g_qkvs_l[NROW*D3];
__device__ __align__(16) __half g_wqkv_h[D3*DD],  g_wqkv_l[D3*DD];
__device__ __align__(16) __half g_wo_h  [DD*DD],  g_wo_l  [DD*DD];
__device__ __align__(16) __half g_w1_h  [DFF*DD], g_w1_l  [DFF*DD];
__device__ __align__(16) __half g_w2_h  [DD*DFF], g_w2_l  [DD*DFF];

// ================= helpers =================
__device__ __forceinline__ uint32_t smem_u32(const void* p) {
    uint32_t a;
    asm("{ .reg .u64 t; cvta.to.shared.u64 t, %1; cvt.u32.u64 %0, t; }" : "=r"(a) : "l"(p));
    return a;
}
__device__ __forceinline__ void cp_async16(uint32_t dst, const void* src) {
    asm volatile("cp.async.cg.shared.global [%0], [%1], 16;\n" :: "r"(dst), "l"(src));
}
__device__ __forceinline__ void cp_commit() { asm volatile("cp.async.commit_group;\n" ::: "memory"); }

__device__ __forceinline__ void ldsm4(uint32_t addr, uint32_t& r0, uint32_t& r1, uint32_t& r2, uint32_t& r3) {
    asm volatile("ldmatrix.sync.aligned.m8n8.x4.shared.b16 {%0,%1,%2,%3}, [%4];"
                 : "=r"(r0), "=r"(r1), "=r"(r2), "=r"(r3) : "r"(addr));
}
__device__ __forceinline__ void ldsm4t(uint32_t addr, uint32_t& r0, uint32_t& r1, uint32_t& r2, uint32_t& r3) {
    asm volatile("ldmatrix.sync.aligned.m8n8.x4.trans.shared.b16 {%0,%1,%2,%3}, [%4];"
                 : "=r"(r0), "=r"(r1), "=r"(r2), "=r"(r3) : "r"(addr));
}
__device__ __forceinline__ void mma_bf16(float* c, const uint32_t* a, const uint32_t* b) {
    asm volatile("mma.sync.aligned.m16n8k16.row.col.f32.bf16.bf16.f32 "
                 "{%0,%1,%2,%3}, {%4,%5,%6,%7}, {%8,%9}, {%0,%1,%2,%3};"
                 : "+f"(c[0]), "+f"(c[1]), "+f"(c[2]), "+f"(c[3])
                 : "r"(a[0]), "r"(a[1]), "r"(a[2]), "r"(a[3]), "r"(b[0]), "r"(b[1]));
}
__device__ __forceinline__ void mma_f16(float* c, const uint32_t* a, const uint32_t* b) {
    asm volatile("mma.sync.aligned.m16n8k16.row.col.f32.f16.f16.f32 "
                 "{%0,%1,%2,%3}, {%4,%5,%6,%7}, {%8,%9}, {%0,%1,%2,%3};"
                 : "+f"(c[0]), "+f"(c[1]), "+f"(c[2]), "+f"(c[3])
                 : "r"(a[0]), "r"(a[1]), "r"(a[2]), "r"(a[3]), "r"(b[0]), "r"(b[1]));
}
__device__ __forceinline__ void split2b(float a, float b, uint32_t& hi, uint32_t& lo) {
    __nv_bfloat16 ha = __float2bfloat16(a), hb = __float2bfloat16(b);
    __nv_bfloat162 hh; hh.x = ha; hh.y = hb;
    __nv_bfloat162 ll;
    ll.x = __float2bfloat16(a - __bfloat162float(ha));
    ll.y = __float2bfloat16(b - __bfloat162float(hb));
    hi = *(uint32_t*)&hh; lo = *(uint32_t*)&ll;
}
__device__ __forceinline__ void split2h(float a, float b, uint32_t& hi, uint32_t& lo) {
    __half ha = __float2half(a), hb = __float2half(b);
    __half2 hh; hh.x = ha; hh.y = hb;
    __half2 ll;
    ll.x = __float2half(a - __half2float(ha));
    ll.y = __float2half(b - __half2float(hb));
    hi = *(uint32_t*)&hh; lo = *(uint32_t*)&ll;
}
__device__ __forceinline__ uint32_t pack_h2(float a, float b) {
    __half2 h; h.x = __float2half(a); h.y = __float2half(b);
    return *(uint32_t*)&h;
}
__device__ __forceinline__ float pick3(float a, float b, float c, int i) {
    return i == 0 ? a : (i == 1 ? b : c);
}

// ================= fp32 -> fp16 hi/lo split (weights) =================
__global__ void __launch_bounds__(256) splitw_kernel(
    const float* __restrict__ x, __half* __restrict__ hi,
    __half* __restrict__ lo, int n)
{
    int i = (blockIdx.x * 256 + threadIdx.x) * 4;
    if (i >= n) return;
    float4 v = *(const float4*)(x + i);
    uint32_t h0, l0, h1, l1;
    split2h(v.x, v.y, h0, l0);
    split2h(v.z, v.w, h1, l1);
    *(uint32_t*)(hi + i)     = h0;
    *(uint32_t*)(hi + i + 2) = h1;
    *(uint32_t*)(lo + i)     = l0;
    *(uint32_t*)(lo + i + 2) = l1;
}

// ================= relm int32 -> uint8 (idx+1) =================
__global__ void __launch_bounds__(256) rel8_kernel(
    const int* __restrict__ relm, unsigned char* __restrict__ out)
{
    int i = blockIdx.x * 256 + threadIdx.x;
    int4 v = ((const int4*)relm)[i];
    uchar4 o;
    o.x = (unsigned char)(v.x + 1); o.y = (unsigned char)(v.y + 1);
    o.z = (unsigned char)(v.z + 1); o.w = (unsigned char)(v.w + 1);
    ((uchar4*)out)[i] = o;
}

// ================= LayerNorm -> fp16 =================
__global__ void __launch_bounds__(256) ln_kernel(
    const float* __restrict__ x, const float* __restrict__ g,
    const float* __restrict__ bt, __half* __restrict__ y)
{
    __shared__ float red[8];
    __shared__ float red2[8];
    const int row = blockIdx.x;
    const int tid = threadIdx.x;
    const float* xr = x + (size_t)row * DD;

    float v0 = xr[tid], v1 = xr[tid + 256], v2 = xr[tid + 512];
    float s = v0 + v1 + v2;
    #pragma unroll
    for (int off = 16; off >= 1; off >>= 1)
        s += __shfl_xor_sync(0xffffffffu, s, off);
    if ((tid & 31) == 0) red[tid >> 5] = s;
    __syncthreads();
    float tot = 0.f;
    #pragma unroll
    for (int i = 0; i < 8; i++) tot += red[i];
    const float mean = tot * (1.0f / DD);

    float d0 = v0 - mean, d1 = v1 - mean, d2 = v2 - mean;
    float ss = d0*d0 + d1*d1 + d2*d2;
    #pragma unroll
    for (int off = 16; off >= 1; off >>= 1)
        ss += __shfl_xor_sync(0xffffffffu, ss, off);
    if ((tid & 31) == 0) red2[tid >> 5] = ss;
    __syncthreads();
    float vtot = 0.f;
    #pragma unroll
    for (int i = 0; i < 8; i++) vtot += red2[i];
    const float rstd = rsqrtf(vtot * (1.0f / DD) + 1e-5f);

    #pragma unroll
    for (int j = 0; j < 3; j++) {
        int c = tid + j * 256;
        float dv = (j == 0 ? d0 : (j == 1 ? d1 : d2));
        y[(size_t)row * DD + c] = __float2half(dv * rstd * g[c] + bt[c]);
    }
}

// ================= fp16 2-term HMMA GEMM: C = A @ (Wh+Wl)^T ==================
// A fp16 single; W split fp16 hi+lo. 3-stage cp.async pipeline, 1 sync/iter.
// Stage layout: A tile [BM][32] (BM*64 B) + Wh [128][32] (8KB) + Wl [128][32] (8KB).
#define SWZOFF(row, ch) ((uint32_t)((row) * 64 + (((ch) ^ (((row) >> 1) & 3)) * 16)))

template<bool RELU, bool BIAS, bool RESID, int OUT, int BM>
__global__ void __launch_bounds__(256, 1) hgemm(
    const __half* __restrict__ A,
    const __half* __restrict__ Wh, const __half* __restrict__ Wl,
    const float* __restrict__ bias, const float* __restrict__ resid,
    float* __restrict__ C, __half* __restrict__ Ch,
    __nv_bfloat16* __restrict__ Cbh, __nv_bfloat16* __restrict__ Cbl,
    int M, int N, int K)
{
    constexpr int WMW = BM / 32;          // warps along m
    constexpr int WNW = 8 / WMW;          // warps along n
    constexpr int WN  = 128 / WNW;        // cols per warp
    constexpr int NT  = WN / 8;           // 8-col n-tiles per warp
    constexpr int NP  = NT / 2;           // ldsm4 loads per W term
    constexpr int A_BYTES = BM * 64;      // BM rows x 32 fp16
    constexpr int STAGE = A_BYTES + 16384;
    constexpr int CHUNKS = BM * 4 + 1024; // A chunks + 2 W tiles (512 each)
    constexpr int ITERS = CHUNKS / 256;
    static_assert(CHUNKS % 256 == 0, "chunk count must divide");

    extern __shared__ __align__(128) char smem[];
    const uint32_t sb = smem_u32(smem);

    const int tid = threadIdx.x;
    const int wid = tid >> 5, lane = tid & 31;
    const int warp_m = wid & (WMW - 1), warp_n = wid / WMW;
    const int m0 = blockIdx.y * BM, n0 = blockIdx.x * 128;

    float acc[2][NT][4];
    #pragma unroll
    for (int mt = 0; mt < 2; mt++)
        #pragma unroll
        for (int nt = 0; nt < NT; nt++)
            #pragma unroll
            for (int j = 0; j < 4; j++) acc[mt][nt][j] = 0.f;

    const int niter = K >> 5;

    auto load_stage = [&](int buf, int k0) {
        uint32_t base = sb + buf * STAGE;
        #pragma unroll
        for (int t = 0; t < ITERS; t++) {
            int c = tid + t * 256;
            if (c < BM * 4) {
                int row = c >> 2, ch = c & 3;
                cp_async16(base + SWZOFF(row, ch),
                           A + (size_t)(m0 + row) * K + k0 + ch * 8);
            } else {
                int c2 = c - BM * 4;          // 0..1023
                int tile = c2 >> 9;           // 0:Wh 1:Wl
                int w = c2 & 511;
                int row = w >> 2, ch = w & 3;
                const __half* src = (tile ? Wl : Wh) + (size_t)(n0 + row) * K + k0 + ch * 8;
                cp_async16(base + A_BYTES + tile * 8192 + SWZOFF(row, ch), src);
            }
        }
        cp_commit();
    };

    load_stage(0, 0);
    load_stage(1, 32);

    const int lr = lane & 15, lh = lane >> 4;

    int buf = 0;
    for (int it = 0; it < niter; it++) {
        if (it + 1 < niter) {
            asm volatile("cp.async.wait_group 1;\n" ::: "memory");
        } else {
            asm volatile("cp.async.wait_group 0;\n" ::: "memory");
        }
        __syncthreads();
        if (it + 2 < niter) {
            int nb = buf + 2; if (nb >= 3) nb -= 3;
            load_stage(nb, (it + 2) * 32);
        }

        const uint32_t base = sb + buf * STAGE;
        #pragma unroll
        for (int ks = 0; ks < 2; ks++) {
            const int ch = ks * 2 + lh;
            uint32_t af[2][4];
            #pragma unroll
            for (int mt = 0; mt < 2; mt++) {
                int row = warp_m * 32 + mt * 16 + lr;
                ldsm4(base + SWZOFF(row, ch), af[mt][0], af[mt][1], af[mt][2], af[mt][3]);
            }
            uint32_t bh[NT][2];
            #pragma unroll
            for (int np = 0; np < NP; np++) {
                int row = warp_n * WN + np * 16 + lr;
                uint32_t off = base + A_BYTES + SWZOFF(row, ch);
                ldsm4(off, bh[2*np][0], bh[2*np+1][0], bh[2*np][1], bh[2*np+1][1]);
            }
            #pragma unroll
            for (int mt = 0; mt < 2; mt++)
                #pragma unroll
                for (int nt = 0; nt < NT; nt++)
                    mma_f16(acc[mt][nt], af[mt], bh[nt]);
            uint32_t bl[NT][2];
            #pragma unroll
            for (int np = 0; np < NP; np++) {
                int row = warp_n * WN + np * 16 + lr;
                uint32_t off = base + A_BYTES + 8192 + SWZOFF(row, ch);
                ldsm4(off, bl[2*np][0], bl[2*np+1][0], bl[2*np][1], bl[2*np+1][1]);
            }
            #pragma unroll
            for (int mt = 0; mt < 2; mt++)
                #pragma unroll
                for (int nt = 0; nt < NT; nt++)
                    mma_f16(acc[mt][nt], af[mt], bl[nt]);
        }
        if (++buf >= 3) buf = 0;
    }

    #pragma unroll
    for (int mt = 0; mt < 2; mt++) {
        #pragma unroll
        for (int half = 0; half < 2; half++) {
            const int m = m0 + warp_m * 32 + mt * 16 + (lane >> 2) + half * 8;
            #pragma unroll
            for (int nt = 0; nt < NT; nt++) {
                const int n = n0 + warp_n * WN + nt * 8 + (lane & 3) * 2;
                float v0 = acc[mt][nt][half * 2 + 0];
                float v1 = acc[mt][nt][half * 2 + 1];
                if (BIAS) { v0 += bias[n]; v1 += bias[n + 1]; }
                if (RELU) { v0 = fmaxf(v0, 0.f); v1 = fmaxf(v1, 0.f); }
                if (RESID) {
                    float2 rv = *(const float2*)(resid + (size_t)m * N + n);
                    v0 += rv.x; v1 += rv.y;
                }
                if (OUT == 0) {
                    float2 o2; o2.x = v0; o2.y = v1;
                    *(float2*)(C + (size_t)m * N + n) = o2;
                } else if (OUT == 1) {
                    *(uint32_t*)(Ch + (size_t)m * N + n) = pack_h2(v0, v1);
                } else {
                    uint32_t hi, lo;
                    split2b(v0, v1, hi, lo);
                    *(uint32_t*)(Cbh + (size_t)m * N + n) = hi;
                    *(uint32_t*)(Cbl + (size_t)m * N + n) = lo;
                }
            }
        }
    }
}

// ================= HMMA flash attention (3-term bf16, fp16 out) ============
#define SWZ128(row, ch) ((uint32_t)((row) * 128 + (((ch) ^ ((row) & 7)) * 16)))

__global__ void __launch_bounds__(256) attn_mma_kernel(
    const __nv_bfloat16* __restrict__ qkvh, const __nv_bfloat16* __restrict__ qkvl,
    const unsigned char* __restrict__ rel8, const unsigned char* __restrict__ amask,
    const float* __restrict__ relA, __half* __restrict__ outp)
{
    extern __shared__ __align__(128) char smem[];
    const uint32_t sQh = smem_u32(smem);
    const uint32_t sQl = sQh + 16384;
    const uint32_t sStage = sQh + 32768;
    float* mb = (float*)(smem + 98304);

    const int tid = threadIdx.x, wid = tid >> 5, lane = tid & 31;
    const int lr = lane & 15, lh = lane >> 4;
    const int b = blockIdx.z, h = blockIdx.y;
    const int q0 = blockIdx.x * 128;

    #pragma unroll
    for (int t = 0; t < 8; t++) {
        int lin = tid + t * 256;
        int half = lin >> 10;
        int w = lin & 1023;
        int row = w >> 3, ch = w & 7;
        uint32_t off = (half ? sQl : sQh) + SWZ128(row, ch);
        const __nv_bfloat16* src = (half ? qkvl : qkvh)
            + (size_t)(b * SS + q0 + row) * D3 + h * HDIM + ch * 8;
        cp_async16(off, src);
    }
    cp_commit();

    auto load_kv = [&](int stage, int kt) {
        const int k0 = kt * 64;
        uint32_t base = sStage + stage * 32768;
        #pragma unroll
        for (int t = 0; t < 8; t++) {
            int lin = tid + t * 256;
            int tensor = lin >> 9;
            int w = lin & 511;
            int row = w >> 3, ch = w & 7;
            uint32_t off = base + tensor * 8192 + SWZ128(row, ch);
            size_t g = (size_t)(b * SS + k0 + row) * D3 + h * HDIM + ch * 8;
            const __nv_bfloat16* src;
            if      (tensor == 0) src = qkvh + g + DD;
            else if (tensor == 1) src = qkvl + g + DD;
            else if (tensor == 2) src = qkvh + g + 2 * DD;
            else                  src = qkvl + g + 2 * DD;
            cp_async16(off, src);
        }
        if (tid < 64) mb[stage * 64 + tid] = amask[b * SS + k0 + tid] ? -1e30f : 0.f;
        cp_commit();
    };

    load_kv(0, 0);

    asm volatile("cp.async.wait_group 1;\n" ::: "memory");
    __syncthreads();

    uint32_t qh[4][4], ql[4][4];
    #pragma unroll
    for (int ks = 0; ks < 4; ks++) {
        uint32_t off = SWZ128(wid * 16 + lr, ks * 2 + lh);
        ldsm4(sQh + off, qh[ks][0], qh[ks][1], qh[ks][2], qh[ks][3]);
        ldsm4(sQl + off, ql[ks][0], ql[ks][1], ql[ks][2], ql[ks][3]);
    }

    const int r0 = wid * 16 + (lane >> 2);
    float rs00 = 0.f, rs01 = 0.f, rs02 = 0.f;
    float rs10 = 0.f, rs11 = 0.f, rs12 = 0.f;
    {
        const int dbase = (lane & 3) * 16;
        #pragma unroll
        for (int dd = 0; dd < 16; dd++) {
            int d = dbase + dd;
            uint32_t boff = SWZ128(r0, d >> 3) + (d & 7) * 2;
            uint32_t boff1 = SWZ128(r0 + 8, d >> 3) + (d & 7) * 2;
            float q0v = __bfloat162float(*(const __nv_bfloat16*)(smem + boff))
                      + __bfloat162float(*(const __nv_bfloat16*)(smem + 16384 + boff));
            float q1v = __bfloat162float(*(const __nv_bfloat16*)(smem + boff1))
                      + __bfloat162float(*(const __nv_bfloat16*)(smem + 16384 + boff1));
            float a0 = relA[d], a1 = relA[64 + d], a2 = relA[128 + d];
            rs00 += q0v * a0; rs01 += q0v * a1; rs02 += q0v * a2;
            rs10 += q1v * a0; rs11 += q1v * a1; rs12 += q1v * a2;
        }
        #pragma unroll
        for (int off = 1; off <= 2; off <<= 1) {
            rs00 += __shfl_xor_sync(0xffffffffu, rs00, off);
            rs01 += __shfl_xor_sync(0xffffffffu, rs01, off);
            rs02 += __shfl_xor_sync(0xffffffffu, rs02, off);
            rs10 += __shfl_xor_sync(0xffffffffu, rs10, off);
            rs11 += __shfl_xor_sync(0xffffffffu, rs11, off);
            rs12 += __shfl_xor_sync(0xffffffffu, rs12, off);
        }
    }

    float o[8][4];
    #pragma unroll
    for (int nt = 0; nt < 8; nt++)
        #pragma unroll
        for (int j = 0; j < 4; j++) o[nt][j] = 0.f;
    float m0 = -1e30f, m1 = -1e30f, l0 = 0.f, l1 = 0.f;

    for (int kt = 0; kt < SS / 64; kt++) {
        const int cur = kt & 1;
        asm volatile("cp.async.wait_group 0;\n" ::: "memory");
        __syncthreads();
        if (kt + 1 < SS / 64) load_kv((kt + 1) & 1, kt + 1);

        const uint32_t stg = sStage + cur * 32768;
        const float* mbc = mb + cur * 64;
        const int k0 = kt * 64;

        float s[8][4];
        #pragma unroll
        for (int nt = 0; nt < 8; nt++)
            #pragma unroll
            for (int j = 0; j < 4; j++) s[nt][j] = 0.f;

        #pragma unroll
        for (int ks = 0; ks < 4; ks++) {
            uint32_t kf[8][2];
            #pragma unroll
            for (int np = 0; np < 4; np++) {
                uint32_t off = stg + SWZ128(np * 16 + lr, ks * 2 + lh);
                ldsm4(off, kf[2*np][0], kf[2*np+1][0], kf[2*np][1], kf[2*np+1][1]);
            }
            #pragma unroll
            for (int nt = 0; nt < 8; nt++) mma_bf16(s[nt], qh[ks], kf[nt]);
            #pragma unroll
            for (int nt = 0; nt < 8; nt++) mma_bf16(s[nt], ql[ks], kf[nt]);
            #pragma unroll
            for (int np = 0; np < 4; np++) {
                uint32_t off = stg + 8192 + SWZ128(np * 16 + lr, ks * 2 + lh);
                ldsm4(off, kf[2*np][0], kf[2*np+1][0], kf[2*np][1], kf[2*np+1][1]);
            }
            #pragma unroll
            for (int nt = 0; nt < 8; nt++) mma_bf16(s[nt], qh[ks], kf[nt]);
        }

        float mx0 = -1e30f, mx1 = -1e30f;
        #pragma unroll
        for (int nt = 0; nt < 8; nt++) {
            const int c0 = nt * 8 + (lane & 3) * 2;
            uchar2 i0 = *(const uchar2*)(rel8 + (size_t)(b * SS + q0 + r0) * SS + k0 + c0);
            uchar2 i1 = *(const uchar2*)(rel8 + (size_t)(b * SS + q0 + r0 + 8) * SS + k0 + c0);
            float mb0 = mbc[c0], mb1 = mbc[c0 + 1];
            s[nt][0] = (s[nt][0] + pick3(rs00, rs01, rs02, i0.x)) * 0.125f + mb0;
            s[nt][1] = (s[nt][1] + pick3(rs00, rs01, rs02, i0.y)) * 0.125f + mb1;
            s[nt][2] = (s[nt][2] + pick3(rs10, rs11, rs12, i1.x)) * 0.125f + mb0;
            s[nt][3] = (s[nt][3] + pick3(rs10, rs11, rs12, i1.y)) * 0.125f + mb1;
            mx0 = fmaxf(mx0, fmaxf(s[nt][0], s[nt][1]));
            mx1 = fmaxf(mx1, fmaxf(s[nt][2], s[nt][3]));
        }
        #pragma unroll
        for (int off = 1; off <= 2; off <<= 1) {
            mx0 = fmaxf(mx0, __shfl_xor_sync(0xffffffffu, mx0, off));
            mx1 = fmaxf(mx1, __shfl_xor_sync(0xffffffffu, mx1, off));
        }
        const float mn0 = fmaxf(m0, mx0), mn1 = fmaxf(m1, mx1);
        const float fac0 = __expf(m0 - mn0), fac1 = __expf(m1 - mn1);
        float sum0 = 0.f, sum1 = 0.f;
        #pragma unroll
        for (int nt = 0; nt < 8; nt++) {
            s[nt][0] = __expf(s[nt][0] - mn0);
            s[nt][1] = __expf(s[nt][1] - mn0);
            s[nt][2] = __expf(s[nt][2] - mn1);
            s[nt][3] = __expf(s[nt][3] - mn1);
            sum0 += s[nt][0] + s[nt][1];
            sum1 += s[nt][2] + s[nt][3];
        }
        #pragma unroll
        for (int off = 1; off <= 2; off <<= 1) {
            sum0 += __shfl_xor_sync(0xffffffffu, sum0, off);
            sum1 += __shfl_xor_sync(0xffffffffu, sum1, off);
        }
        l0 = l0 * fac0 + sum0;
        l1 = l1 * fac1 + sum1;
        m0 = mn0; m1 = mn1;
        #pragma unroll
        for (int nt = 0; nt < 8; nt++) {
            o[nt][0] *= fac0; o[nt][1] *= fac0;
            o[nt][2] *= fac1; o[nt][3] *= fac1;
        }

        #pragma unroll
        for (int ks2 = 0; ks2 < 4; ks2++) {
            uint32_t pah[4], pal[4];
            split2b(s[2*ks2][0],   s[2*ks2][1],   pah[0], pal[0]);
            split2b(s[2*ks2][2],   s[2*ks2][3],   pah[1], pal[1]);
            split2b(s[2*ks2+1][0], s[2*ks2+1][1], pah[2], pal[2]);
            split2b(s[2*ks2+1][2], s[2*ks2+1][3], pah[3], pal[3]);
            uint32_t vf[8][2];
            #pragma unroll
            for (int np = 0; np < 4; np++) {
                uint32_t off = stg + 16384 + SWZ128(ks2 * 16 + lr, np * 2 + lh);
                ldsm4t(off, vf[2*np][0], vf[2*np][1], vf[2*np+1][0], vf[2*np+1][1]);
            }
            #pragma unroll
            for (int nt = 0; nt < 8; nt++) mma_bf16(o[nt], pah, vf[nt]);
            #pragma unroll
            for (int nt = 0; nt < 8; nt++) mma_bf16(o[nt], pal, vf[nt]);
            #pragma unroll
            for (int np = 0; np < 4; np++) {
                uint32_t off = stg + 24576 + SWZ128(ks2 * 16 + lr, np * 2 + lh);
                ldsm4t(off, vf[2*np][0], vf[2*np][1], vf[2*np+1][0], vf[2*np+1][1]);
            }
            #pragma unroll
            for (int nt = 0; nt < 8; nt++) mma_bf16(o[nt], pah, vf[nt]);
        }
    }

    const float inv0 = 1.0f / l0, inv1 = 1.0f / l1;
    #pragma unroll
    for (int nt = 0; nt < 8; nt++) {
        const int c0 = nt * 8 + (lane & 3) * 2;
        size_t base0 = (size_t)(b * SS + q0 + r0) * DD + h * HDIM + c0;
        size_t base1 = (size_t)(b * SS + q0 + r0 + 8) * DD + h * HDIM + c0;
        *(uint32_t*)(outp + base0) = pack_h2(o[nt][0] * inv0, o[nt][1] * inv0);
        *(uint32_t*)(outp + base1) = pack_h2(o[nt][2] * inv1, o[nt][3] * inv1);
    }
}

// ================= launch =================
extern "C" void kernel_launch(void* const* d_in, const int* in_sizes, int n_in,
                              void* d_out, int out_size)
{
    const float*         inp   = (const float*)d_in[0];
    const unsigned char* amask = (const unsigned char*)d_in[1];
    const int*           relm  = (const int*)d_in[2];
    const float*         qkv_w = (const float*)d_in[3];
    const float*         relA  = (const float*)d_in[4];
    const float*         o_w   = (const float*)d_in[5];
    const float*         w1    = (const float*)d_in[6];
    const float*         b1    = (const float*)d_in[7];
    const float*         w2    = (const float*)d_in[8];
    const float*         b2    = (const float*)d_in[9];
    const float*         ln1g  = (const float*)d_in[10];
    const float*         ln1b  = (const float*)d_in[11];
    const float*         ln2g  = (const float*)d_in[12];
    const float*         ln2b  = (const float*)d_in[13];
    float* out = (float*)d_out;

    float *x1;
    unsigned char* rel8;
    __half *xln, *hbuf, *attn, *ff;
    __half *wqh, *wql, *woh, *wol, *w1h, *w1l, *w2h, *w2l;
    __nv_bfloat16 *qsh, *qsl;
    cudaGetSymbolAddress((void**)&x1,   g_x1);
    cudaGetSymbolAddress((void**)&rel8, g_rel8);
    cudaGetSymbolAddress((void**)&xln,  g_xln);
    cudaGetSymbolAddress((void**)&hbuf, g_h);
    cudaGetSymbolAddress((void**)&attn, g_attn);
    cudaGetSymbolAddress((void**)&ff,   g_ff);
    cudaGetSymbolAddress((void**)&qsh,  g_qkvs_h); cudaGetSymbolAddress((void**)&qsl, g_qkvs_l);
    cudaGetSymbolAddress((void**)&wqh,  g_wqkv_h); cudaGetSymbolAddress((void**)&wql, g_wqkv_l);
    cudaGetSymbolAddress((void**)&woh,  g_wo_h);   cudaGetSymbolAddress((void**)&wol, g_wo_l);
    cudaGetSymbolAddress((void**)&w1h,  g_w1_h);   cudaGetSymbolAddress((void**)&w1l, g_w1_l);
    cudaGetSymbolAddress((void**)&w2h,  g_w2_h);   cudaGetSymbolAddress((void**)&w2l, g_w2_l);

    const int SMEM128 = 3 * (128 * 64 + 16384);   // 73728
    const int SMEM64  = 3 * (64 * 64 + 16384);    // 61440
    const int ASMEM = 98816;
    cudaFuncSetAttribute(hgemm<false,false,false,2,128>, cudaFuncAttributeMaxDynamicSharedMemorySize, SMEM128);
    cudaFuncSetAttribute(hgemm<true ,true ,false,1,128>, cudaFuncAttributeMaxDynamicSharedMemorySize, SMEM128);
    cudaFuncSetAttribute(hgemm<false,false,true ,0,64 >, cudaFuncAttributeMaxDynamicSharedMemorySize, SMEM64);
    cudaFuncSetAttribute(hgemm<false,true ,true ,0,64 >, cudaFuncAttributeMaxDynamicSharedMemorySize, SMEM64);
    cudaFuncSetAttribute(attn_mma_kernel, cudaFuncAttributeMaxDynamicSharedMemorySize, ASMEM);

    // 0) preprocessing
    splitw_kernel<<<(D3*DD/4 + 255)/256, 256>>>(qkv_w, wqh, wql, D3*DD);
    splitw_kernel<<<(DD*DD/4 + 255)/256, 256>>>(o_w,   woh, wol, DD*DD);
    splitw_kernel<<<(DFF*DD/4 + 255)/256, 256>>>(w1,   w1h, w1l, DFF*DD);
    splitw_kernel<<<(DD*DFF/4 + 255)/256, 256>>>(w2,   w2h, w2l, DD*DFF);
    rel8_kernel<<<NROW*SS/4/256, 256>>>(relm, rel8);

    // 1) LN1 -> xln fp16
    ln_kernel<<<NROW, 256>>>(inp, ln1g, ln1b, xln);

    // 2) QKV -> bf16 hi/lo (for attention accuracy)
    hgemm<false,false,false,2,128><<<dim3(D3/128, NROW/128), 256, SMEM128>>>(
        xln, wqh, wql, nullptr, nullptr, nullptr, nullptr, qsh, qsl, NROW, D3, DD);

    // 3) attention -> fp16
    attn_mma_kernel<<<dim3(SS/128, HH, BB), 256, ASMEM>>>(
        qsh, qsl, rel8, amask, relA, attn);

    // 4) x1 = inp + attn @ o_w^T (fp32)   BM=64 -> 192 CTAs
    hgemm<false,false,true,0,64><<<dim3(DD/128, NROW/64), 256, SMEM64>>>(
        attn, woh, wol, nullptr, inp, x1, nullptr, nullptr, nullptr, NROW, DD, DD);

    // 5) LN2 -> h fp16
    ln_kernel<<<NROW, 256>>>(x1, ln2g, ln2b, hbuf);

    // 6) ff = relu(h @ w1^T + b1) -> fp16
    hgemm<true,true,false,1,128><<<dim3(DFF/128, NROW/128), 256, SMEM128>>>(
        hbuf, w1h, w1l, b1, nullptr, nullptr, ff, nullptr, nullptr, NROW, DFF, DD);

    // 7) out = x1 + ff @ w2^T + b2 (fp32)  BM=64 -> 192 CTAs
    hgemm<false,true,true,0,64><<<dim3(DD/128, NROW/64), 256, SMEM64>>>(
        ff, w2h, w2l, b2, x1, out, nullptr, nullptr, nullptr, NROW, DD, DFF);
}

// round 9
// speedup vs baseline: 4.6317x; 1.0336x over previous
#include <cuda_runtime.h>
#include <cuda_fp16.h>
#include <cstdint>

// ---------------- problem constants ----------------
#define BB   2
#define SS   1024
#define DD   768
#define HH   12
#define HDIM 64
#define DFF  3072
#define NROW (BB*SS)        // 2048
#define D3   (3*DD)         // 2304

// ---------------- scratch (device globals, no allocs) ----------------
__device__ __align__(16) float g_x1  [NROW*DD];
__device__ __align__(16) unsigned char g_rel8[NROW*SS];

__device__ __align__(16) __half g_xln [NROW*DD];
__device__ __align__(16) __half g_h   [NROW*DD];
__device__ __align__(16) __half g_attn[NROW*DD];
__device__ __align__(16) __half g_ff  [NROW*DFF];
__device__ __align__(16) __half g_qs  [NROW*DD];                  // Q single fp16
__device__ __align__(16) __half g_kvh [NROW*2*DD], g_kvl[NROW*2*DD];  // K,V fp16 hi/lo
__device__ __align__(16) __half g_wqkv_h[D3*DD],  g_wqkv_l[D3*DD];
__device__ __align__(16) __half g_wo_h  [DD*DD],  g_wo_l  [DD*DD];
__device__ __align__(16) __half g_w1_h  [DFF*DD], g_w1_l  [DFF*DD];
__device__ __align__(16) __half g_w2_h  [DD*DFF], g_w2_l  [DD*DFF];

// ================= helpers =================
__device__ __forceinline__ uint32_t smem_u32(const void* p) {
    uint32_t a;
    asm("{ .reg .u64 t; cvta.to.shared.u64 t, %1; cvt.u32.u64 %0, t; }" : "=r"(a) : "l"(p));
    return a;
}
__device__ __forceinline__ void cp_async16(uint32_t dst, const void* src) {
    asm volatile("cp.async.cg.shared.global [%0], [%1], 16;\n" :: "r"(dst), "l"(src));
}
__device__ __forceinline__ void cp_commit() { asm volatile("cp.async.commit_group;\n" ::: "memory"); }

__device__ __forceinline__ void ldsm4(uint32_t addr, uint32_t& r0, uint32_t& r1, uint32_t& r2, uint32_t& r3) {
    asm volatile("ldmatrix.sync.aligned.m8n8.x4.shared.b16 {%0,%1,%2,%3}, [%4];"
                 : "=r"(r0), "=r"(r1), "=r"(r2), "=r"(r3) : "r"(addr));
}
__device__ __forceinline__ void ldsm4t(uint32_t addr, uint32_t& r0, uint32_t& r1, uint32_t& r2, uint32_t& r3) {
    asm volatile("ldmatrix.sync.aligned.m8n8.x4.trans.shared.b16 {%0,%1,%2,%3}, [%4];"
                 : "=r"(r0), "=r"(r1), "=r"(r2), "=r"(r3) : "r"(addr));
}
__device__ __forceinline__ void mma_f16(float* c, const uint32_t* a, const uint32_t* b) {
    asm volatile("mma.sync.aligned.m16n8k16.row.col.f32.f16.f16.f32 "
                 "{%0,%1,%2,%3}, {%4,%5,%6,%7}, {%8,%9}, {%0,%1,%2,%3};"
                 : "+f"(c[0]), "+f"(c[1]), "+f"(c[2]), "+f"(c[3])
                 : "r"(a[0]), "r"(a[1]), "r"(a[2]), "r"(a[3]), "r"(b[0]), "r"(b[1]));
}
__device__ __forceinline__ void split2h(float a, float b, uint32_t& hi, uint32_t& lo) {
    __half ha = __float2half(a), hb = __float2half(b);
    __half2 hh; hh.x = ha; hh.y = hb;
    __half2 ll;
    ll.x = __float2half(a - __half2float(ha));
    ll.y = __float2half(b - __half2float(hb));
    hi = *(uint32_t*)&hh; lo = *(uint32_t*)&ll;
}
__device__ __forceinline__ uint32_t pack_h2(float a, float b) {
    __half2 h; h.x = __float2half(a); h.y = __float2half(b);
    return *(uint32_t*)&h;
}
__device__ __forceinline__ float pick3(float a, float b, float c, int i) {
    return i == 0 ? a : (i == 1 ? b : c);
}

// ================= fp32 -> fp16 hi/lo split (weights), 16 elems/thread ======
__global__ void __launch_bounds__(256) splitw_kernel(
    const float* __restrict__ x, __half* __restrict__ hi,
    __half* __restrict__ lo, int n)
{
    int base = (blockIdx.x * 256 + threadIdx.x) * 16;
    float4 v[4];
    #pragma unroll
    for (int j = 0; j < 4; j++) {
        int i = base + j * 4;
        if (i < n) v[j] = *(const float4*)(x + i);
    }
    #pragma unroll
    for (int j = 0; j < 4; j++) {
        int i = base + j * 4;
        if (i < n) {
            uint32_t h0, l0, h1, l1;
            split2h(v[j].x, v[j].y, h0, l0);
            split2h(v[j].z, v[j].w, h1, l1);
            *(uint32_t*)(hi + i)     = h0;
            *(uint32_t*)(hi + i + 2) = h1;
            *(uint32_t*)(lo + i)     = l0;
            *(uint32_t*)(lo + i + 2) = l1;
        }
    }
}

// ================= relm int32 -> uint8 (idx+1) =================
__global__ void __launch_bounds__(256) rel8_kernel(
    const int* __restrict__ relm, unsigned char* __restrict__ out)
{
    int i = blockIdx.x * 256 + threadIdx.x;
    int4 v = ((const int4*)relm)[i];
    uchar4 o;
    o.x = (unsigned char)(v.x + 1); o.y = (unsigned char)(v.y + 1);
    o.z = (unsigned char)(v.z + 1); o.w = (unsigned char)(v.w + 1);
    ((uchar4*)out)[i] = o;
}

// ================= LayerNorm -> fp16 =================
__global__ void __launch_bounds__(256) ln_kernel(
    const float* __restrict__ x, const float* __restrict__ g,
    const float* __restrict__ bt, __half* __restrict__ y)
{
    __shared__ float red[8];
    __shared__ float red2[8];
    const int row = blockIdx.x;
    const int tid = threadIdx.x;
    const float* xr = x + (size_t)row * DD;

    float v0 = xr[tid], v1 = xr[tid + 256], v2 = xr[tid + 512];
    float s = v0 + v1 + v2;
    #pragma unroll
    for (int off = 16; off >= 1; off >>= 1)
        s += __shfl_xor_sync(0xffffffffu, s, off);
    if ((tid & 31) == 0) red[tid >> 5] = s;
    __syncthreads();
    float tot = 0.f;
    #pragma unroll
    for (int i = 0; i < 8; i++) tot += red[i];
    const float mean = tot * (1.0f / DD);

    float d0 = v0 - mean, d1 = v1 - mean, d2 = v2 - mean;
    float ss = d0*d0 + d1*d1 + d2*d2;
    #pragma unroll
    for (int off = 16; off >= 1; off >>= 1)
        ss += __shfl_xor_sync(0xffffffffu, ss, off);
    if ((tid & 31) == 0) red2[tid >> 5] = ss;
    __syncthreads();
    float vtot = 0.f;
    #pragma unroll
    for (int i = 0; i < 8; i++) vtot += red2[i];
    const float rstd = rsqrtf(vtot * (1.0f / DD) + 1e-5f);

    #pragma unroll
    for (int j = 0; j < 3; j++) {
        int c = tid + j * 256;
        float dv = (j == 0 ? d0 : (j == 1 ? d1 : d2));
        y[(size_t)row * DD + c] = __float2half(dv * rstd * g[c] + bt[c]);
    }
}

// ================= fp16 2-term HMMA GEMM: C = A @ (Wh+Wl)^T ==================
// OUT: 0 fp32(+resid), 1 fp16, 3 QKV special (Q->fp16 single, K/V->fp16 hi/lo)
#define SWZOFF(row, ch) ((uint32_t)((row) * 64 + (((ch) ^ (((row) >> 1) & 3)) * 16)))

template<bool RELU, bool BIAS, bool RESID, int OUT, int BM>
__global__ void __launch_bounds__(256, 1) hgemm(
    const __half* __restrict__ A,
    const __half* __restrict__ Wh, const __half* __restrict__ Wl,
    const float* __restrict__ bias, const float* __restrict__ resid,
    float* __restrict__ C, __half* __restrict__ Ch,
    __half* __restrict__ Cbh, __half* __restrict__ Cbl,
    int M, int N, int K)
{
    constexpr int WMW = BM / 32;
    constexpr int WNW = 8 / WMW;
    constexpr int WN  = 128 / WNW;
    constexpr int NT  = WN / 8;
    constexpr int NP  = NT / 2;
    constexpr int A_BYTES = BM * 64;
    constexpr int STAGE = A_BYTES + 16384;
    constexpr int CHUNKS = BM * 4 + 1024;
    constexpr int ITERS = CHUNKS / 256;
    static_assert(CHUNKS % 256 == 0, "chunk count must divide");

    extern __shared__ __align__(128) char smem[];
    const uint32_t sb = smem_u32(smem);

    const int tid = threadIdx.x;
    const int wid = tid >> 5, lane = tid & 31;
    const int warp_m = wid & (WMW - 1), warp_n = wid / WMW;
    const int m0 = blockIdx.y * BM, n0 = blockIdx.x * 128;

    float acc[2][NT][4];
    #pragma unroll
    for (int mt = 0; mt < 2; mt++)
        #pragma unroll
        for (int nt = 0; nt < NT; nt++)
            #pragma unroll
            for (int j = 0; j < 4; j++) acc[mt][nt][j] = 0.f;

    const int niter = K >> 5;

    auto load_stage = [&](int buf, int k0) {
        uint32_t base = sb + buf * STAGE;
        #pragma unroll
        for (int t = 0; t < ITERS; t++) {
            int c = tid + t * 256;
            if (c < BM * 4) {
                int row = c >> 2, ch = c & 3;
                cp_async16(base + SWZOFF(row, ch),
                           A + (size_t)(m0 + row) * K + k0 + ch * 8);
            } else {
                int c2 = c - BM * 4;
                int tile = c2 >> 9;
                int w = c2 & 511;
                int row = w >> 2, ch = w & 3;
                const __half* src = (tile ? Wl : Wh) + (size_t)(n0 + row) * K + k0 + ch * 8;
                cp_async16(base + A_BYTES + tile * 8192 + SWZOFF(row, ch), src);
            }
        }
        cp_commit();
    };

    load_stage(0, 0);
    load_stage(1, 32);

    const int lr = lane & 15, lh = lane >> 4;

    int buf = 0;
    for (int it = 0; it < niter; it++) {
        if (it + 1 < niter) {
            asm volatile("cp.async.wait_group 1;\n" ::: "memory");
        } else {
            asm volatile("cp.async.wait_group 0;\n" ::: "memory");
        }
        __syncthreads();
        if (it + 2 < niter) {
            int nb = buf + 2; if (nb >= 3) nb -= 3;
            load_stage(nb, (it + 2) * 32);
        }

        const uint32_t base = sb + buf * STAGE;
        #pragma unroll
        for (int ks = 0; ks < 2; ks++) {
            const int ch = ks * 2 + lh;
            uint32_t af[2][4];
            #pragma unroll
            for (int mt = 0; mt < 2; mt++) {
                int row = warp_m * 32 + mt * 16 + lr;
                ldsm4(base + SWZOFF(row, ch), af[mt][0], af[mt][1], af[mt][2], af[mt][3]);
            }
            uint32_t bh[NT][2];
            #pragma unroll
            for (int np = 0; np < NP; np++) {
                int row = warp_n * WN + np * 16 + lr;
                uint32_t off = base + A_BYTES + SWZOFF(row, ch);
                ldsm4(off, bh[2*np][0], bh[2*np+1][0], bh[2*np][1], bh[2*np+1][1]);
            }
            #pragma unroll
            for (int mt = 0; mt < 2; mt++)
                #pragma unroll
                for (int nt = 0; nt < NT; nt++)
                    mma_f16(acc[mt][nt], af[mt], bh[nt]);
            uint32_t bl[NT][2];
            #pragma unroll
            for (int np = 0; np < NP; np++) {
                int row = warp_n * WN + np * 16 + lr;
                uint32_t off = base + A_BYTES + 8192 + SWZOFF(row, ch);
                ldsm4(off, bl[2*np][0], bl[2*np+1][0], bl[2*np][1], bl[2*np+1][1]);
            }
            #pragma unroll
            for (int mt = 0; mt < 2; mt++)
                #pragma unroll
                for (int nt = 0; nt < NT; nt++)
                    mma_f16(acc[mt][nt], af[mt], bl[nt]);
        }
        if (++buf >= 3) buf = 0;
    }

    #pragma unroll
    for (int mt = 0; mt < 2; mt++) {
        #pragma unroll
        for (int half = 0; half < 2; half++) {
            const int m = m0 + warp_m * 32 + mt * 16 + (lane >> 2) + half * 8;
            #pragma unroll
            for (int nt = 0; nt < NT; nt++) {
                const int n = n0 + warp_n * WN + nt * 8 + (lane & 3) * 2;
                float v0 = acc[mt][nt][half * 2 + 0];
                float v1 = acc[mt][nt][half * 2 + 1];
                if (BIAS) { v0 += bias[n]; v1 += bias[n + 1]; }
                if (RELU) { v0 = fmaxf(v0, 0.f); v1 = fmaxf(v1, 0.f); }
                if (RESID) {
                    float2 rv = *(const float2*)(resid + (size_t)m * N + n);
                    v0 += rv.x; v1 += rv.y;
                }
                if (OUT == 0) {
                    float2 o2; o2.x = v0; o2.y = v1;
                    *(float2*)(C + (size_t)m * N + n) = o2;
                } else if (OUT == 1) {
                    *(uint32_t*)(Ch + (size_t)m * N + n) = pack_h2(v0, v1);
                } else {
                    // QKV: Q (n<DD) single fp16; K/V (n>=DD) fp16 hi/lo
                    if (n0 < DD) {
                        *(uint32_t*)(Ch + (size_t)m * DD + n) = pack_h2(v0, v1);
                    } else {
                        uint32_t hi, lo;
                        split2h(v0, v1, hi, lo);
                        *(uint32_t*)(Cbh + (size_t)m * (2 * DD) + (n - DD)) = hi;
                        *(uint32_t*)(Cbl + (size_t)m * (2 * DD) + (n - DD)) = lo;
                    }
                }
            }
        }
    }
}

// ================= HMMA flash attention (fp16 2-term) =======================
// Smem: Q single [128][64] (16KB) + 2 stages of {Kh,Kl,Vh,Vl}[64][64] (32KB each)
#define SWZ128(row, ch) ((uint32_t)((row) * 128 + (((ch) ^ ((row) & 7)) * 16)))

__global__ void __launch_bounds__(256) attn_mma_kernel(
    const __half* __restrict__ qs,
    const __half* __restrict__ kvh, const __half* __restrict__ kvl,
    const unsigned char* __restrict__ rel8, const unsigned char* __restrict__ amask,
    const float* __restrict__ relA, __half* __restrict__ outp)
{
    extern __shared__ __align__(128) char smem[];
    const uint32_t sQ = smem_u32(smem);
    const uint32_t sStage = sQ + 16384;
    float* mb = (float*)(smem + 81920);

    const int tid = threadIdx.x, wid = tid >> 5, lane = tid & 31;
    const int lr = lane & 15, lh = lane >> 4;
    const int b = blockIdx.z, h = blockIdx.y;
    const int q0 = blockIdx.x * 128;

    // ---- Q tile (single fp16) ----
    #pragma unroll
    for (int t = 0; t < 4; t++) {
        int lin = tid + t * 256;          // 0..1023
        int row = lin >> 3, ch = lin & 7;
        cp_async16(sQ + SWZ128(row, ch),
                   qs + (size_t)(b * SS + q0 + row) * DD + h * HDIM + ch * 8);
    }
    cp_commit();

    auto load_kv = [&](int stage, int kt) {
        const int k0 = kt * 64;
        uint32_t base = sStage + stage * 32768;
        #pragma unroll
        for (int t = 0; t < 8; t++) {
            int lin = tid + t * 256;
            int tensor = lin >> 9;        // 0:Kh 1:Kl 2:Vh 3:Vl
            int w = lin & 511;
            int row = w >> 3, ch = w & 7;
            uint32_t off = base + tensor * 8192 + SWZ128(row, ch);
            size_t g = (size_t)(b * SS + k0 + row) * (2 * DD) + h * HDIM + ch * 8;
            const __half* src;
            if      (tensor == 0) src = kvh + g;
            else if (tensor == 1) src = kvl + g;
            else if (tensor == 2) src = kvh + g + DD;
            else                  src = kvl + g + DD;
            cp_async16(off, src);
        }
        if (tid < 64) mb[stage * 64 + tid] = amask[b * SS + k0 + tid] ? -1e30f : 0.f;
        cp_commit();
    };

    load_kv(0, 0);

    asm volatile("cp.async.wait_group 1;\n" ::: "memory");  // Q ready
    __syncthreads();

    // ---- Q fragments ----
    uint32_t qf[4][4];
    #pragma unroll
    for (int ks = 0; ks < 4; ks++) {
        uint32_t off = SWZ128(wid * 16 + lr, ks * 2 + lh);
        ldsm4(sQ + off, qf[ks][0], qf[ks][1], qf[ks][2], qf[ks][3]);
    }

    // ---- per-row relative logits rs[3] (quad-cooperative) ----
    const int r0 = wid * 16 + (lane >> 2);
    float rs00 = 0.f, rs01 = 0.f, rs02 = 0.f;
    float rs10 = 0.f, rs11 = 0.f, rs12 = 0.f;
    {
        const int dbase = (lane & 3) * 16;
        #pragma unroll
        for (int dd = 0; dd < 16; dd++) {
            int d = dbase + dd;
            float q0v = __half2float(*(const __half*)(smem + SWZ128(r0, d >> 3) + (d & 7) * 2));
            float q1v = __half2float(*(const __half*)(smem + SWZ128(r0 + 8, d >> 3) + (d & 7) * 2));
            float a0 = relA[d], a1 = relA[64 + d], a2 = relA[128 + d];
            rs00 += q0v * a0; rs01 += q0v * a1; rs02 += q0v * a2;
            rs10 += q1v * a0; rs11 += q1v * a1; rs12 += q1v * a2;
        }
        #pragma unroll
        for (int off = 1; off <= 2; off <<= 1) {
            rs00 += __shfl_xor_sync(0xffffffffu, rs00, off);
            rs01 += __shfl_xor_sync(0xffffffffu, rs01, off);
            rs02 += __shfl_xor_sync(0xffffffffu, rs02, off);
            rs10 += __shfl_xor_sync(0xffffffffu, rs10, off);
            rs11 += __shfl_xor_sync(0xffffffffu, rs11, off);
            rs12 += __shfl_xor_sync(0xffffffffu, rs12, off);
        }
    }

    float o[8][4];
    #pragma unroll
    for (int nt = 0; nt < 8; nt++)
        #pragma unroll
        for (int j = 0; j < 4; j++) o[nt][j] = 0.f;
    float m0 = -1e30f, m1 = -1e30f, l0 = 0.f, l1 = 0.f;

    for (int kt = 0; kt < SS / 64; kt++) {
        const int cur = kt & 1;
        asm volatile("cp.async.wait_group 0;\n" ::: "memory");
        __syncthreads();
        if (kt + 1 < SS / 64) load_kv((kt + 1) & 1, kt + 1);

        const uint32_t stg = sStage + cur * 32768;
        const float* mbc = mb + cur * 64;
        const int k0 = kt * 64;

        // ---- S = Q (Kh + Kl)^T ----
        float s[8][4];
        #pragma unroll
        for (int nt = 0; nt < 8; nt++)
            #pragma unroll
            for (int j = 0; j < 4; j++) s[nt][j] = 0.f;

        #pragma unroll
        for (int ks = 0; ks < 4; ks++) {
            uint32_t kf[8][2];
            #pragma unroll
            for (int np = 0; np < 4; np++) {
                uint32_t off = stg + SWZ128(np * 16 + lr, ks * 2 + lh);
                ldsm4(off, kf[2*np][0], kf[2*np+1][0], kf[2*np][1], kf[2*np+1][1]);
            }
            #pragma unroll
            for (int nt = 0; nt < 8; nt++) mma_f16(s[nt], qf[ks], kf[nt]);
            #pragma unroll
            for (int np = 0; np < 4; np++) {
                uint32_t off = stg + 8192 + SWZ128(np * 16 + lr, ks * 2 + lh);
                ldsm4(off, kf[2*np][0], kf[2*np+1][0], kf[2*np][1], kf[2*np+1][1]);
            }
            #pragma unroll
            for (int nt = 0; nt < 8; nt++) mma_f16(s[nt], qf[ks], kf[nt]);
        }

        // ---- bias + online softmax ----
        float mx0 = -1e30f, mx1 = -1e30f;
        #pragma unroll
        for (int nt = 0; nt < 8; nt++) {
            const int c0 = nt * 8 + (lane & 3) * 2;
            uchar2 i0 = *(const uchar2*)(rel8 + (size_t)(b * SS + q0 + r0) * SS + k0 + c0);
            uchar2 i1 = *(const uchar2*)(rel8 + (size_t)(b * SS + q0 + r0 + 8) * SS + k0 + c0);
            float mb0 = mbc[c0], mb1 = mbc[c0 + 1];
            s[nt][0] = (s[nt][0] + pick3(rs00, rs01, rs02, i0.x)) * 0.125f + mb0;
            s[nt][1] = (s[nt][1] + pick3(rs00, rs01, rs02, i0.y)) * 0.125f + mb1;
            s[nt][2] = (s[nt][2] + pick3(rs10, rs11, rs12, i1.x)) * 0.125f + mb0;
            s[nt][3] = (s[nt][3] + pick3(rs10, rs11, rs12, i1.y)) * 0.125f + mb1;
            mx0 = fmaxf(mx0, fmaxf(s[nt][0], s[nt][1]));
            mx1 = fmaxf(mx1, fmaxf(s[nt][2], s[nt][3]));
        }
        #pragma unroll
        for (int off = 1; off <= 2; off <<= 1) {
            mx0 = fmaxf(mx0, __shfl_xor_sync(0xffffffffu, mx0, off));
            mx1 = fmaxf(mx1, __shfl_xor_sync(0xffffffffu, mx1, off));
        }
        const float mn0 = fmaxf(m0, mx0), mn1 = fmaxf(m1, mx1);
        const float fac0 = __expf(m0 - mn0), fac1 = __expf(m1 - mn1);
        float sum0 = 0.f, sum1 = 0.f;
        #pragma unroll
        for (int nt = 0; nt < 8; nt++) {
            s[nt][0] = __expf(s[nt][0] - mn0);
            s[nt][1] = __expf(s[nt][1] - mn0);
            s[nt][2] = __expf(s[nt][2] - mn1);
            s[nt][3] = __expf(s[nt][3] - mn1);
            sum0 += s[nt][0] + s[nt][1];
            sum1 += s[nt][2] + s[nt][3];
        }
        #pragma unroll
        for (int off = 1; off <= 2; off <<= 1) {
            sum0 += __shfl_xor_sync(0xffffffffu, sum0, off);
            sum1 += __shfl_xor_sync(0xffffffffu, sum1, off);
        }
        l0 = l0 * fac0 + sum0;
        l1 = l1 * fac1 + sum1;
        m0 = mn0; m1 = mn1;
        #pragma unroll
        for (int nt = 0; nt < 8; nt++) {
            o[nt][0] *= fac0; o[nt][1] *= fac0;
            o[nt][2] *= fac1; o[nt][3] *= fac1;
        }

        // ---- O += P (Vh + Vl), P single fp16 ----
        #pragma unroll
        for (int ks2 = 0; ks2 < 4; ks2++) {
            uint32_t pa[4];
            pa[0] = pack_h2(s[2*ks2][0],   s[2*ks2][1]);
            pa[1] = pack_h2(s[2*ks2][2],   s[2*ks2][3]);
            pa[2] = pack_h2(s[2*ks2+1][0], s[2*ks2+1][1]);
            pa[3] = pack_h2(s[2*ks2+1][2], s[2*ks2+1][3]);
            uint32_t vf[8][2];
            #pragma unroll
            for (int np = 0; np < 4; np++) {
                uint32_t off = stg + 16384 + SWZ128(ks2 * 16 + lr, np * 2 + lh);
                ldsm4t(off, vf[2*np][0], vf[2*np][1], vf[2*np+1][0], vf[2*np+1][1]);
            }
            #pragma unroll
            for (int nt = 0; nt < 8; nt++) mma_f16(o[nt], pa, vf[nt]);
            #pragma unroll
            for (int np = 0; np < 4; np++) {
                uint32_t off = stg + 24576 + SWZ128(ks2 * 16 + lr, np * 2 + lh);
                ldsm4t(off, vf[2*np][0], vf[2*np][1], vf[2*np+1][0], vf[2*np+1][1]);
            }
            #pragma unroll
            for (int nt = 0; nt < 8; nt++) mma_f16(o[nt], pa, vf[nt]);
        }
    }

    const float inv0 = 1.0f / l0, inv1 = 1.0f / l1;
    #pragma unroll
    for (int nt = 0; nt < 8; nt++) {
        const int c0 = nt * 8 + (lane & 3) * 2;
        size_t base0 = (size_t)(b * SS + q0 + r0) * DD + h * HDIM + c0;
        size_t base1 = (size_t)(b * SS + q0 + r0 + 8) * DD + h * HDIM + c0;
        *(uint32_t*)(outp + base0) = pack_h2(o[nt][0] * inv0, o[nt][1] * inv0);
        *(uint32_t*)(outp + base1) = pack_h2(o[nt][2] * inv1, o[nt][3] * inv1);
    }
}

// ================= launch =================
extern "C" void kernel_launch(void* const* d_in, const int* in_sizes, int n_in,
                              void* d_out, int out_size)
{
    const float*         inp   = (const float*)d_in[0];
    const unsigned char* amask = (const unsigned char*)d_in[1];
    const int*           relm  = (const int*)d_in[2];
    const float*         qkv_w = (const float*)d_in[3];
    const float*         relA  = (const float*)d_in[4];
    const float*         o_w   = (const float*)d_in[5];
    const float*         w1    = (const float*)d_in[6];
    const float*         b1    = (const float*)d_in[7];
    const float*         w2    = (const float*)d_in[8];
    const float*         b2    = (const float*)d_in[9];
    const float*         ln1g  = (const float*)d_in[10];
    const float*         ln1b  = (const float*)d_in[11];
    const float*         ln2g  = (const float*)d_in[12];
    const float*         ln2b  = (const float*)d_in[13];
    float* out = (float*)d_out;

    float *x1;
    unsigned char* rel8;
    __half *xln, *hbuf, *attn, *ff, *qsp, *kvh, *kvl;
    __half *wqh, *wql, *woh, *wol, *w1h, *w1l, *w2h, *w2l;
    cudaGetSymbolAddress((void**)&x1,   g_x1);
    cudaGetSymbolAddress((void**)&rel8, g_rel8);
    cudaGetSymbolAddress((void**)&xln,  g_xln);
    cudaGetSymbolAddress((void**)&hbuf, g_h);
    cudaGetSymbolAddress((void**)&attn, g_attn);
    cudaGetSymbolAddress((void**)&ff,   g_ff);
    cudaGetSymbolAddress((void**)&qsp,  g_qs);
    cudaGetSymbolAddress((void**)&kvh,  g_kvh);    cudaGetSymbolAddress((void**)&kvl, g_kvl);
    cudaGetSymbolAddress((void**)&wqh,  g_wqkv_h); cudaGetSymbolAddress((void**)&wql, g_wqkv_l);
    cudaGetSymbolAddress((void**)&woh,  g_wo_h);   cudaGetSymbolAddress((void**)&wol, g_wo_l);
    cudaGetSymbolAddress((void**)&w1h,  g_w1_h);   cudaGetSymbolAddress((void**)&w1l, g_w1_l);
    cudaGetSymbolAddress((void**)&w2h,  g_w2_h);   cudaGetSymbolAddress((void**)&w2l, g_w2_l);

    const int SMEM128 = 3 * (128 * 64 + 16384);   // 73728
    const int SMEM64  = 3 * (64 * 64 + 16384);    // 61440
    const int ASMEM = 82432;
    cudaFuncSetAttribute(hgemm<false,false,false,3,128>, cudaFuncAttributeMaxDynamicSharedMemorySize, SMEM128);
    cudaFuncSetAttribute(hgemm<true ,true ,false,1,128>, cudaFuncAttributeMaxDynamicSharedMemorySize, SMEM128);
    cudaFuncSetAttribute(hgemm<false,false,true ,0,64 >, cudaFuncAttributeMaxDynamicSharedMemorySize, SMEM64);
    cudaFuncSetAttribute(hgemm<false,true ,true ,0,64 >, cudaFuncAttributeMaxDynamicSharedMemorySize, SMEM64);
    cudaFuncSetAttribute(attn_mma_kernel, cudaFuncAttributeMaxDynamicSharedMemorySize, ASMEM);

    // 0) preprocessing
    splitw_kernel<<<(D3*DD + 4095)/4096, 256>>>(qkv_w, wqh, wql, D3*DD);
    splitw_kernel<<<(DD*DD + 4095)/4096, 256>>>(o_w,   woh, wol, DD*DD);
    splitw_kernel<<<(DFF*DD + 4095)/4096, 256>>>(w1,   w1h, w1l, DFF*DD);
    splitw_kernel<<<(DD*DFF + 4095)/4096, 256>>>(w2,   w2h, w2l, DD*DFF);
    rel8_kernel<<<NROW*SS/4/256, 256>>>(relm, rel8);

    // 1) LN1 -> xln fp16
    ln_kernel<<<NROW, 256>>>(inp, ln1g, ln1b, xln);

    // 2) QKV: Q -> fp16 single, K/V -> fp16 hi/lo
    hgemm<false,false,false,3,128><<<dim3(D3/128, NROW/128), 256, SMEM128>>>(
        xln, wqh, wql, nullptr, nullptr, nullptr, qsp, kvh, kvl, NROW, D3, DD);

    // 3) attention -> fp16
    attn_mma_kernel<<<dim3(SS/128, HH, BB), 256, ASMEM>>>(
        qsp, kvh, kvl, rel8, amask, relA, attn);

    // 4) x1 = inp + attn @ o_w^T (fp32)   BM=64 -> 192 CTAs
    hgemm<false,false,true,0,64><<<dim3(DD/128, NROW/64), 256, SMEM64>>>(
        attn, woh, wol, nullptr, inp, x1, nullptr, nullptr, nullptr, NROW, DD, DD);

    // 5) LN2 -> h fp16
    ln_kernel<<<NROW, 256>>>(x1, ln2g, ln2b, hbuf);

    // 6) ff = relu(h @ w1^T + b1) -> fp16
    hgemm<true,true,false,1,128><<<dim3(DFF/128, NROW/128), 256, SMEM128>>>(
        hbuf, w1h, w1l, b1, nullptr, nullptr, ff, nullptr, nullptr, NROW, DFF, DD);

    // 7) out = x1 + ff @ w2^T + b2 (fp32)  BM=64 -> 192 CTAs
    hgemm<false,true,true,0,64><<<dim3(DD/128, NROW/64), 256, SMEM64>>>(
        ff, w2h, w2l, b2, x1, out, nullptr, nullptr, nullptr, NROW, DD, DFF);
}

// round 10
// speedup vs baseline: 5.0604x; 1.0925x over previous
#include <cuda_runtime.h>
#include <cuda_fp16.h>
#include <cstdint>

// ---------------- problem constants ----------------
#define BB   2
#define SS   1024
#define DD   768
#define HH   12
#define HDIM 64
#define DFF  3072
#define NROW (BB*SS)        // 2048
#define D3   (3*DD)         // 2304

// ---------------- scratch (device globals, no allocs) ----------------
__device__ __align__(16) float g_x1  [NROW*DD];
__device__ __align__(16) unsigned char g_rel8[NROW*SS];

__device__ __align__(16) __half g_xln [NROW*DD];
__device__ __align__(16) __half g_h   [NROW*DD];
__device__ __align__(16) __half g_attn[NROW*DD];
__device__ __align__(16) __half g_ff  [NROW*DFF];
__device__ __align__(16) __half g_qs  [NROW*DD];                 // Q single fp16
__device__ __align__(16) __half g_kh  [NROW*DD], g_kl[NROW*DD];  // K fp16 hi/lo
__device__ __align__(16) __half g_vs  [NROW*DD];                 // V single fp16
__device__ __align__(16) __half g_wqkv_h[D3*DD],  g_wqkv_l[D3*DD];
__device__ __align__(16) __half g_wo_h  [DD*DD],  g_wo_l  [DD*DD];
__device__ __align__(16) __half g_w1_h  [DFF*DD], g_w1_l  [DFF*DD];
__device__ __align__(16) __half g_w2_h  [DD*DFF], g_w2_l  [DD*DFF];

// ================= helpers =================
__device__ __forceinline__ uint32_t smem_u32(const void* p) {
    uint32_t a;
    asm("{ .reg .u64 t; cvta.to.shared.u64 t, %1; cvt.u32.u64 %0, t; }" : "=r"(a) : "l"(p));
    return a;
}
__device__ __forceinline__ void cp_async16(uint32_t dst, const void* src) {
    asm volatile("cp.async.cg.shared.global [%0], [%1], 16;\n" :: "r"(dst), "l"(src));
}
__device__ __forceinline__ void cp_commit() { asm volatile("cp.async.commit_group;\n" ::: "memory"); }

__device__ __forceinline__ void ldsm4(uint32_t addr, uint32_t& r0, uint32_t& r1, uint32_t& r2, uint32_t& r3) {
    asm volatile("ldmatrix.sync.aligned.m8n8.x4.shared.b16 {%0,%1,%2,%3}, [%4];"
                 : "=r"(r0), "=r"(r1), "=r"(r2), "=r"(r3) : "r"(addr));
}
__device__ __forceinline__ void ldsm4t(uint32_t addr, uint32_t& r0, uint32_t& r1, uint32_t& r2, uint32_t& r3) {
    asm volatile("ldmatrix.sync.aligned.m8n8.x4.trans.shared.b16 {%0,%1,%2,%3}, [%4];"
                 : "=r"(r0), "=r"(r1), "=r"(r2), "=r"(r3) : "r"(addr));
}
__device__ __forceinline__ void mma_f16(float* c, const uint32_t* a, const uint32_t* b) {
    asm volatile("mma.sync.aligned.m16n8k16.row.col.f32.f16.f16.f32 "
                 "{%0,%1,%2,%3}, {%4,%5,%6,%7}, {%8,%9}, {%0,%1,%2,%3};"
                 : "+f"(c[0]), "+f"(c[1]), "+f"(c[2]), "+f"(c[3])
                 : "r"(a[0]), "r"(a[1]), "r"(a[2]), "r"(a[3]), "r"(b[0]), "r"(b[1]));
}
__device__ __forceinline__ void split2h(float a, float b, uint32_t& hi, uint32_t& lo) {
    __half ha = __float2half(a), hb = __float2half(b);
    __half2 hh; hh.x = ha; hh.y = hb;
    __half2 ll;
    ll.x = __float2half(a - __half2float(ha));
    ll.y = __float2half(b - __half2float(hb));
    hi = *(uint32_t*)&hh; lo = *(uint32_t*)&ll;
}
__device__ __forceinline__ uint32_t pack_h2(float a, float b) {
    __half2 h; h.x = __float2half(a); h.y = __float2half(b);
    return *(uint32_t*)&h;
}
__device__ __forceinline__ float pick3(float a, float b, float c, int i) {
    return i == 0 ? a : (i == 1 ? b : c);
}

// ======== fused weight split: all 4 weights in one launch, 4 elems/thread ====
// region boundaries in blocks (1024 elems per block):
// qkv: 1728, o: 576, w1: 2304, w2: 2304  -> total 6912
__global__ void __launch_bounds__(256) splitw_all_kernel(
    const float* __restrict__ qkv_w, const float* __restrict__ o_w,
    const float* __restrict__ w1,    const float* __restrict__ w2,
    __half* __restrict__ qkvh, __half* __restrict__ qkvl,
    __half* __restrict__ oh,   __half* __restrict__ ol,
    __half* __restrict__ w1h,  __half* __restrict__ w1l,
    __half* __restrict__ w2h,  __half* __restrict__ w2l)
{
    int bid = blockIdx.x;
    const float* src; __half *hi, *lo; int base;
    if (bid < 1728)      { src = qkv_w; hi = qkvh; lo = qkvl; base = bid; }
    else if (bid < 2304) { src = o_w;   hi = oh;   lo = ol;   base = bid - 1728; }
    else if (bid < 4608) { src = w1;    hi = w1h;  lo = w1l;  base = bid - 2304; }
    else                 { src = w2;    hi = w2h;  lo = w2l;  base = bid - 4608; }
    int i = base * 1024 + threadIdx.x * 4;
    float4 v = *(const float4*)(src + i);
    uint32_t h0, l0, h1, l1;
    split2h(v.x, v.y, h0, l0);
    split2h(v.z, v.w, h1, l1);
    *(uint32_t*)(hi + i)     = h0;
    *(uint32_t*)(hi + i + 2) = h1;
    *(uint32_t*)(lo + i)     = l0;
    *(uint32_t*)(lo + i + 2) = l1;
}

// ================= relm int32 -> uint8 (idx+1) =================
__global__ void __launch_bounds__(256) rel8_kernel(
    const int* __restrict__ relm, unsigned char* __restrict__ out)
{
    int i = blockIdx.x * 256 + threadIdx.x;
    int4 v = ((const int4*)relm)[i];
    uchar4 o;
    o.x = (unsigned char)(v.x + 1); o.y = (unsigned char)(v.y + 1);
    o.z = (unsigned char)(v.z + 1); o.w = (unsigned char)(v.w + 1);
    ((uchar4*)out)[i] = o;
}

// ================= LayerNorm -> fp16 =================
__global__ void __launch_bounds__(256) ln_kernel(
    const float* __restrict__ x, const float* __restrict__ g,
    const float* __restrict__ bt, __half* __restrict__ y)
{
    __shared__ float red[8];
    __shared__ float red2[8];
    const int row = blockIdx.x;
    const int tid = threadIdx.x;
    const float* xr = x + (size_t)row * DD;

    float v0 = xr[tid], v1 = xr[tid + 256], v2 = xr[tid + 512];
    float s = v0 + v1 + v2;
    #pragma unroll
    for (int off = 16; off >= 1; off >>= 1)
        s += __shfl_xor_sync(0xffffffffu, s, off);
    if ((tid & 31) == 0) red[tid >> 5] = s;
    __syncthreads();
    float tot = 0.f;
    #pragma unroll
    for (int i = 0; i < 8; i++) tot += red[i];
    const float mean = tot * (1.0f / DD);

    float d0 = v0 - mean, d1 = v1 - mean, d2 = v2 - mean;
    float ss = d0*d0 + d1*d1 + d2*d2;
    #pragma unroll
    for (int off = 16; off >= 1; off >>= 1)
        ss += __shfl_xor_sync(0xffffffffu, ss, off);
    if ((tid & 31) == 0) red2[tid >> 5] = ss;
    __syncthreads();
    float vtot = 0.f;
    #pragma unroll
    for (int i = 0; i < 8; i++) vtot += red2[i];
    const float rstd = rsqrtf(vtot * (1.0f / DD) + 1e-5f);

    #pragma unroll
    for (int j = 0; j < 3; j++) {
        int c = tid + j * 256;
        float dv = (j == 0 ? d0 : (j == 1 ? d1 : d2));
        y[(size_t)row * DD + c] = __float2half(dv * rstd * g[c] + bt[c]);
    }
}

// ================= fp16 2-term HMMA GEMM: C = A @ (Wh+Wl)^T ==================
// OUT: 0 fp32(+resid), 1 fp16, 3 QKV (Q single / K hi+lo / V single)
#define SWZOFF(row, ch) ((uint32_t)((row) * 64 + (((ch) ^ (((row) >> 1) & 3)) * 16)))

template<bool RELU, bool BIAS, bool RESID, int OUT, int BM>
__global__ void __launch_bounds__(256, (BM == 64) ? 2 : 1) hgemm(
    const __half* __restrict__ A,
    const __half* __restrict__ Wh, const __half* __restrict__ Wl,
    const float* __restrict__ bias, const float* __restrict__ resid,
    float* __restrict__ C, __half* __restrict__ Ch,
    __half* __restrict__ Cbh, __half* __restrict__ Cbl, __half* __restrict__ Cv,
    int M, int N, int K)
{
    constexpr int WMW = BM / 32;
    constexpr int WNW = 8 / WMW;
    constexpr int WN  = 128 / WNW;
    constexpr int NT  = WN / 8;
    constexpr int NP  = NT / 2;
    constexpr int A_BYTES = BM * 64;
    constexpr int STAGE = A_BYTES + 16384;
    constexpr int CHUNKS = BM * 4 + 1024;
    constexpr int ITERS = CHUNKS / 256;
    static_assert(CHUNKS % 256 == 0, "chunk count must divide");

    extern __shared__ __align__(128) char smem[];
    const uint32_t sb = smem_u32(smem);

    const int tid = threadIdx.x;
    const int wid = tid >> 5, lane = tid & 31;
    const int warp_m = wid & (WMW - 1), warp_n = wid / WMW;
    const int m0 = blockIdx.y * BM, n0 = blockIdx.x * 128;

    float acc[2][NT][4];
    #pragma unroll
    for (int mt = 0; mt < 2; mt++)
        #pragma unroll
        for (int nt = 0; nt < NT; nt++)
            #pragma unroll
            for (int j = 0; j < 4; j++) acc[mt][nt][j] = 0.f;

    const int niter = K >> 5;

    auto load_stage = [&](int buf, int k0) {
        uint32_t base = sb + buf * STAGE;
        #pragma unroll
        for (int t = 0; t < ITERS; t++) {
            int c = tid + t * 256;
            if (c < BM * 4) {
                int row = c >> 2, ch = c & 3;
                cp_async16(base + SWZOFF(row, ch),
                           A + (size_t)(m0 + row) * K + k0 + ch * 8);
            } else {
                int c2 = c - BM * 4;
                int tile = c2 >> 9;
                int w = c2 & 511;
                int row = w >> 2, ch = w & 3;
                const __half* src = (tile ? Wl : Wh) + (size_t)(n0 + row) * K + k0 + ch * 8;
                cp_async16(base + A_BYTES + tile * 8192 + SWZOFF(row, ch), src);
            }
        }
        cp_commit();
    };

    load_stage(0, 0);
    load_stage(1, 32);

    const int lr = lane & 15, lh = lane >> 4;

    int buf = 0;
    for (int it = 0; it < niter; it++) {
        if (it + 1 < niter) {
            asm volatile("cp.async.wait_group 1;\n" ::: "memory");
        } else {
            asm volatile("cp.async.wait_group 0;\n" ::: "memory");
        }
        __syncthreads();
        if (it + 2 < niter) {
            int nb = buf + 2; if (nb >= 3) nb -= 3;
            load_stage(nb, (it + 2) * 32);
        }

        const uint32_t base = sb + buf * STAGE;
        #pragma unroll
        for (int ks = 0; ks < 2; ks++) {
            const int ch = ks * 2 + lh;
            uint32_t af[2][4];
            #pragma unroll
            for (int mt = 0; mt < 2; mt++) {
                int row = warp_m * 32 + mt * 16 + lr;
                ldsm4(base + SWZOFF(row, ch), af[mt][0], af[mt][1], af[mt][2], af[mt][3]);
            }
            uint32_t bh[NT][2];
            #pragma unroll
            for (int np = 0; np < NP; np++) {
                int row = warp_n * WN + np * 16 + lr;
                uint32_t off = base + A_BYTES + SWZOFF(row, ch);
                ldsm4(off, bh[2*np][0], bh[2*np+1][0], bh[2*np][1], bh[2*np+1][1]);
            }
            #pragma unroll
            for (int mt = 0; mt < 2; mt++)
                #pragma unroll
                for (int nt = 0; nt < NT; nt++)
                    mma_f16(acc[mt][nt], af[mt], bh[nt]);
            uint32_t bl[NT][2];
            #pragma unroll
            for (int np = 0; np < NP; np++) {
                int row = warp_n * WN + np * 16 + lr;
                uint32_t off = base + A_BYTES + 8192 + SWZOFF(row, ch);
                ldsm4(off, bl[2*np][0], bl[2*np+1][0], bl[2*np][1], bl[2*np+1][1]);
            }
            #pragma unroll
            for (int mt = 0; mt < 2; mt++)
                #pragma unroll
                for (int nt = 0; nt < NT; nt++)
                    mma_f16(acc[mt][nt], af[mt], bl[nt]);
        }
        if (++buf >= 3) buf = 0;
    }

    #pragma unroll
    for (int mt = 0; mt < 2; mt++) {
        #pragma unroll
        for (int half = 0; half < 2; half++) {
            const int m = m0 + warp_m * 32 + mt * 16 + (lane >> 2) + half * 8;
            #pragma unroll
            for (int nt = 0; nt < NT; nt++) {
                const int n = n0 + warp_n * WN + nt * 8 + (lane & 3) * 2;
                float v0 = acc[mt][nt][half * 2 + 0];
                float v1 = acc[mt][nt][half * 2 + 1];
                if (BIAS) { v0 += bias[n]; v1 += bias[n + 1]; }
                if (RELU) { v0 = fmaxf(v0, 0.f); v1 = fmaxf(v1, 0.f); }
                if (RESID) {
                    float2 rv = *(const float2*)(resid + (size_t)m * N + n);
                    v0 += rv.x; v1 += rv.y;
                }
                if (OUT == 0) {
                    float2 o2; o2.x = v0; o2.y = v1;
                    *(float2*)(C + (size_t)m * N + n) = o2;
                } else if (OUT == 1) {
                    *(uint32_t*)(Ch + (size_t)m * N + n) = pack_h2(v0, v1);
                } else {
                    if (n0 < DD) {
                        *(uint32_t*)(Ch + (size_t)m * DD + n) = pack_h2(v0, v1);
                    } else if (n0 < 2 * DD) {
                        uint32_t hi, lo;
                        split2h(v0, v1, hi, lo);
                        *(uint32_t*)(Cbh + (size_t)m * DD + (n - DD)) = hi;
                        *(uint32_t*)(Cbl + (size_t)m * DD + (n - DD)) = lo;
                    } else {
                        *(uint32_t*)(Cv + (size_t)m * DD + (n - 2 * DD)) = pack_h2(v0, v1);
                    }
                }
            }
        }
    }
}

// ================= HMMA flash attention (K 2-term, V single) ================
// Smem: Q [128][64] 16KB + 2 stages of {Kh,Kl,Vh}[64][64] 24KB each + mb
#define SWZ128(row, ch) ((uint32_t)((row) * 128 + (((ch) ^ ((row) & 7)) * 16)))

__global__ void __launch_bounds__(256) attn_mma_kernel(
    const __half* __restrict__ qs,
    const __half* __restrict__ kh, const __half* __restrict__ kl,
    const __half* __restrict__ vs,
    const unsigned char* __restrict__ rel8, const unsigned char* __restrict__ amask,
    const float* __restrict__ relA, __half* __restrict__ outp)
{
    extern __shared__ __align__(128) char smem[];
    const uint32_t sQ = smem_u32(smem);
    const uint32_t sStage = sQ + 16384;           // +stage*24576: Kh,Kl,Vh
    float* mb = (float*)(smem + 16384 + 49152);   // [2][64]

    const int tid = threadIdx.x, wid = tid >> 5, lane = tid & 31;
    const int lr = lane & 15, lh = lane >> 4;
    const int b = blockIdx.z, h = blockIdx.y;
    const int q0 = blockIdx.x * 128;

    // ---- Q tile ----
    #pragma unroll
    for (int t = 0; t < 4; t++) {
        int lin = tid + t * 256;
        int row = lin >> 3, ch = lin & 7;
        cp_async16(sQ + SWZ128(row, ch),
                   qs + (size_t)(b * SS + q0 + row) * DD + h * HDIM + ch * 8);
    }
    cp_commit();

    auto load_kv = [&](int stage, int kt) {
        const int k0 = kt * 64;
        uint32_t base = sStage + stage * 24576;
        #pragma unroll
        for (int t = 0; t < 6; t++) {
            int lin = tid + t * 256;          // 0..1535
            int tensor = lin >> 9;            // 0:Kh 1:Kl 2:Vh
            int w = lin & 511;
            int row = w >> 3, ch = w & 7;
            uint32_t off = base + tensor * 8192 + SWZ128(row, ch);
            size_t g = (size_t)(b * SS + k0 + row) * DD + h * HDIM + ch * 8;
            const __half* src = (tensor == 0) ? kh : (tensor == 1 ? kl : vs);
            cp_async16(off, src + g);
        }
        if (tid < 64) mb[stage * 64 + tid] = amask[b * SS + k0 + tid] ? -1e30f : 0.f;
        cp_commit();
    };

    load_kv(0, 0);

    asm volatile("cp.async.wait_group 1;\n" ::: "memory");  // Q ready
    __syncthreads();

    uint32_t qf[4][4];
    #pragma unroll
    for (int ks = 0; ks < 4; ks++) {
        uint32_t off = SWZ128(wid * 16 + lr, ks * 2 + lh);
        ldsm4(sQ + off, qf[ks][0], qf[ks][1], qf[ks][2], qf[ks][3]);
    }

    const int r0 = wid * 16 + (lane >> 2);
    float rs00 = 0.f, rs01 = 0.f, rs02 = 0.f;
    float rs10 = 0.f, rs11 = 0.f, rs12 = 0.f;
    {
        const int dbase = (lane & 3) * 16;
        #pragma unroll
        for (int dd = 0; dd < 16; dd++) {
            int d = dbase + dd;
            float q0v = __half2float(*(const __half*)(smem + SWZ128(r0, d >> 3) + (d & 7) * 2));
            float q1v = __half2float(*(const __half*)(smem + SWZ128(r0 + 8, d >> 3) + (d & 7) * 2));
            float a0 = relA[d], a1 = relA[64 + d], a2 = relA[128 + d];
            rs00 += q0v * a0; rs01 += q0v * a1; rs02 += q0v * a2;
            rs10 += q1v * a0; rs11 += q1v * a1; rs12 += q1v * a2;
        }
        #pragma unroll
        for (int off = 1; off <= 2; off <<= 1) {
            rs00 += __shfl_xor_sync(0xffffffffu, rs00, off);
            rs01 += __shfl_xor_sync(0xffffffffu, rs01, off);
            rs02 += __shfl_xor_sync(0xffffffffu, rs02, off);
            rs10 += __shfl_xor_sync(0xffffffffu, rs10, off);
            rs11 += __shfl_xor_sync(0xffffffffu, rs11, off);
            rs12 += __shfl_xor_sync(0xffffffffu, rs12, off);
        }
    }

    float o[8][4];
    #pragma unroll
    for (int nt = 0; nt < 8; nt++)
        #pragma unroll
        for (int j = 0; j < 4; j++) o[nt][j] = 0.f;
    float m0 = -1e30f, m1 = -1e30f, l0 = 0.f, l1 = 0.f;

    for (int kt = 0; kt < SS / 64; kt++) {
        const int cur = kt & 1;
        asm volatile("cp.async.wait_group 0;\n" ::: "memory");
        __syncthreads();
        if (kt + 1 < SS / 64) load_kv((kt + 1) & 1, kt + 1);

        const uint32_t stg = sStage + cur * 24576;
        const float* mbc = mb + cur * 64;
        const int k0 = kt * 64;

        // ---- S = Q (Kh + Kl)^T ----
        float s[8][4];
        #pragma unroll
        for (int nt = 0; nt < 8; nt++)
            #pragma unroll
            for (int j = 0; j < 4; j++) s[nt][j] = 0.f;

        #pragma unroll
        for (int ks = 0; ks < 4; ks++) {
            uint32_t kf[8][2];
            #pragma unroll
            for (int np = 0; np < 4; np++) {
                uint32_t off = stg + SWZ128(np * 16 + lr, ks * 2 + lh);
                ldsm4(off, kf[2*np][0], kf[2*np+1][0], kf[2*np][1], kf[2*np+1][1]);
            }
            #pragma unroll
            for (int nt = 0; nt < 8; nt++) mma_f16(s[nt], qf[ks], kf[nt]);
            #pragma unroll
            for (int np = 0; np < 4; np++) {
                uint32_t off = stg + 8192 + SWZ128(np * 16 + lr, ks * 2 + lh);
                ldsm4(off, kf[2*np][0], kf[2*np+1][0], kf[2*np][1], kf[2*np+1][1]);
            }
            #pragma unroll
            for (int nt = 0; nt < 8; nt++) mma_f16(s[nt], qf[ks], kf[nt]);
        }

        // ---- bias + online softmax ----
        float mx0 = -1e30f, mx1 = -1e30f;
        #pragma unroll
        for (int nt = 0; nt < 8; nt++) {
            const int c0 = nt * 8 + (lane & 3) * 2;
            uchar2 i0 = *(const uchar2*)(rel8 + (size_t)(b * SS + q0 + r0) * SS + k0 + c0);
            uchar2 i1 = *(const uchar2*)(rel8 + (size_t)(b * SS + q0 + r0 + 8) * SS + k0 + c0);
            float mb0 = mbc[c0], mb1 = mbc[c0 + 1];
            s[nt][0] = (s[nt][0] + pick3(rs00, rs01, rs02, i0.x)) * 0.125f + mb0;
            s[nt][1] = (s[nt][1] + pick3(rs00, rs01, rs02, i0.y)) * 0.125f + mb1;
            s[nt][2] = (s[nt][2] + pick3(rs10, rs11, rs12, i1.x)) * 0.125f + mb0;
            s[nt][3] = (s[nt][3] + pick3(rs10, rs11, rs12, i1.y)) * 0.125f + mb1;
            mx0 = fmaxf(mx0, fmaxf(s[nt][0], s[nt][1]));
            mx1 = fmaxf(mx1, fmaxf(s[nt][2], s[nt][3]));
        }
        #pragma unroll
        for (int off = 1; off <= 2; off <<= 1) {
            mx0 = fmaxf(mx0, __shfl_xor_sync(0xffffffffu, mx0, off));
            mx1 = fmaxf(mx1, __shfl_xor_sync(0xffffffffu, mx1, off));
        }
        const float mn0 = fmaxf(m0, mx0), mn1 = fmaxf(m1, mx1);
        const float fac0 = __expf(m0 - mn0), fac1 = __expf(m1 - mn1);
        float sum0 = 0.f, sum1 = 0.f;
        #pragma unroll
        for (int nt = 0; nt < 8; nt++) {
            s[nt][0] = __expf(s[nt][0] - mn0);
            s[nt][1] = __expf(s[nt][1] - mn0);
            s[nt][2] = __expf(s[nt][2] - mn1);
            s[nt][3] = __expf(s[nt][3] - mn1);
            sum0 += s[nt][0] + s[nt][1];
            sum1 += s[nt][2] + s[nt][3];
        }
        #pragma unroll
        for (int off = 1; off <= 2; off <<= 1) {
            sum0 += __shfl_xor_sync(0xffffffffu, sum0, off);
            sum1 += __shfl_xor_sync(0xffffffffu, sum1, off);
        }
        l0 = l0 * fac0 + sum0;
        l1 = l1 * fac1 + sum1;
        m0 = mn0; m1 = mn1;
        #pragma unroll
        for (int nt = 0; nt < 8; nt++) {
            o[nt][0] *= fac0; o[nt][1] *= fac0;
            o[nt][2] *= fac1; o[nt][3] *= fac1;
        }

        // ---- O += P V (single-term) ----
        #pragma unroll
        for (int ks2 = 0; ks2 < 4; ks2++) {
            uint32_t pa[4];
            pa[0] = pack_h2(s[2*ks2][0],   s[2*ks2][1]);
            pa[1] = pack_h2(s[2*ks2][2],   s[2*ks2][3]);
            pa[2] = pack_h2(s[2*ks2+1][0], s[2*ks2+1][1]);
            pa[3] = pack_h2(s[2*ks2+1][2], s[2*ks2+1][3]);
            uint32_t vf[8][2];
            #pragma unroll
            for (int np = 0; np < 4; np++) {
                uint32_t off = stg + 16384 + SWZ128(ks2 * 16 + lr, np * 2 + lh);
                ldsm4t(off, vf[2*np][0], vf[2*np][1], vf[2*np+1][0], vf[2*np+1][1]);
            }
            #pragma unroll
            for (int nt = 0; nt < 8; nt++) mma_f16(o[nt], pa, vf[nt]);
        }
    }

    const float inv0 = 1.0f / l0, inv1 = 1.0f / l1;
    #pragma unroll
    for (int nt = 0; nt < 8; nt++) {
        const int c0 = nt * 8 + (lane & 3) * 2;
        size_t base0 = (size_t)(b * SS + q0 + r0) * DD + h * HDIM + c0;
        size_t base1 = (size_t)(b * SS + q0 + r0 + 8) * DD + h * HDIM + c0;
        *(uint32_t*)(outp + base0) = pack_h2(o[nt][0] * inv0, o[nt][1] * inv0);
        *(uint32_t*)(outp + base1) = pack_h2(o[nt][2] * inv1, o[nt][3] * inv1);
    }
}

// ================= launch =================
extern "C" void kernel_launch(void* const* d_in, const int* in_sizes, int n_in,
                              void* d_out, int out_size)
{
    const float*         inp   = (const float*)d_in[0];
    const unsigned char* amask = (const unsigned char*)d_in[1];
    const int*           relm  = (const int*)d_in[2];
    const float*         qkv_w = (const float*)d_in[3];
    const float*         relA  = (const float*)d_in[4];
    const float*         o_w   = (const float*)d_in[5];
    const float*         w1    = (const float*)d_in[6];
    const float*         b1    = (const float*)d_in[7];
    const float*         w2    = (const float*)d_in[8];
    const float*         b2    = (const float*)d_in[9];
    const float*         ln1g  = (const float*)d_in[10];
    const float*         ln1b  = (const float*)d_in[11];
    const float*         ln2g  = (const float*)d_in[12];
    const float*         ln2b  = (const float*)d_in[13];
    float* out = (float*)d_out;

    float *x1;
    unsigned char* rel8;
    __half *xln, *hbuf, *attn, *ff, *qsp, *khp, *klp, *vsp;
    __half *wqh, *wql, *woh, *wol, *w1h, *w1l, *w2h, *w2l;
    cudaGetSymbolAddress((void**)&x1,   g_x1);
    cudaGetSymbolAddress((void**)&rel8, g_rel8);
    cudaGetSymbolAddress((void**)&xln,  g_xln);
    cudaGetSymbolAddress((void**)&hbuf, g_h);
    cudaGetSymbolAddress((void**)&attn, g_attn);
    cudaGetSymbolAddress((void**)&ff,   g_ff);
    cudaGetSymbolAddress((void**)&qsp,  g_qs);
    cudaGetSymbolAddress((void**)&khp,  g_kh);     cudaGetSymbolAddress((void**)&klp, g_kl);
    cudaGetSymbolAddress((void**)&vsp,  g_vs);
    cudaGetSymbolAddress((void**)&wqh,  g_wqkv_h); cudaGetSymbolAddress((void**)&wql, g_wqkv_l);
    cudaGetSymbolAddress((void**)&woh,  g_wo_h);   cudaGetSymbolAddress((void**)&wol, g_wo_l);
    cudaGetSymbolAddress((void**)&w1h,  g_w1_h);   cudaGetSymbolAddress((void**)&w1l, g_w1_l);
    cudaGetSymbolAddress((void**)&w2h,  g_w2_h);   cudaGetSymbolAddress((void**)&w2l, g_w2_l);

    const int SMEM128 = 3 * (128 * 64 + 16384);   // 73728
    const int SMEM64  = 3 * (64 * 64 + 16384);    // 61440
    const int ASMEM = 16384 + 2 * 24576 + 512;    // 66048
    cudaFuncSetAttribute(hgemm<false,false,false,3,128>, cudaFuncAttributeMaxDynamicSharedMemorySize, SMEM128);
    cudaFuncSetAttribute(hgemm<true ,true ,false,1,128>, cudaFuncAttributeMaxDynamicSharedMemorySize, SMEM128);
    cudaFuncSetAttribute(hgemm<false,false,true ,0,64 >, cudaFuncAttributeMaxDynamicSharedMemorySize, SMEM64);
    cudaFuncSetAttribute(hgemm<false,true ,true ,0,64 >, cudaFuncAttributeMaxDynamicSharedMemorySize, SMEM64);
    cudaFuncSetAttribute(attn_mma_kernel, cudaFuncAttributeMaxDynamicSharedMemorySize, ASMEM);

    // 0) preprocessing (fused weight split + rel8)
    splitw_all_kernel<<<6912, 256>>>(qkv_w, o_w, w1, w2,
                                     wqh, wql, woh, wol, w1h, w1l, w2h, w2l);
    rel8_kernel<<<NROW*SS/4/256, 256>>>(relm, rel8);

    // 1) LN1 -> xln fp16
    ln_kernel<<<NROW, 256>>>(inp, ln1g, ln1b, xln);

    // 2) QKV: Q fp16 single, K fp16 hi/lo, V fp16 single
    hgemm<false,false,false,3,128><<<dim3(D3/128, NROW/128), 256, SMEM128>>>(
        xln, wqh, wql, nullptr, nullptr, nullptr, qsp, khp, klp, vsp, NROW, D3, DD);

    // 3) attention -> fp16
    attn_mma_kernel<<<dim3(SS/128, HH, BB), 256, ASMEM>>>(
        qsp, khp, klp, vsp, rel8, amask, relA, attn);

    // 4) x1 = inp + attn @ o_w^T (fp32)   BM=64, occ 2
    hgemm<false,false,true,0,64><<<dim3(DD/128, NROW/64), 256, SMEM64>>>(
        attn, woh, wol, nullptr, inp, x1, nullptr, nullptr, nullptr, nullptr, NROW, DD, DD);

    // 5) LN2 -> h fp16
    ln_kernel<<<NROW, 256>>>(x1, ln2g, ln2b, hbuf);

    // 6) ff = relu(h @ w1^T + b1) -> fp16
    hgemm<true,true,false,1,128><<<dim3(DFF/128, NROW/128), 256, SMEM128>>>(
        hbuf, w1h, w1l, b1, nullptr, nullptr, ff, nullptr, nullptr, nullptr, NROW, DFF, DD);

    // 7) out = x1 + ff @ w2^T + b2 (fp32)  BM=64, occ 2
    hgemm<false,true,true,0,64><<<dim3(DD/128, NROW/64), 256, SMEM64>>>(
        ff, w2h, w2l, b2, x1, out, nullptr, nullptr, nullptr, nullptr, NROW, DD, DFF);
}

// round 11
// speedup vs baseline: 5.6545x; 1.1174x over previous
#include <cuda_runtime.h>
#include <cuda_fp16.h>
#include <cstdint>

// ---------------- problem constants ----------------
#define BB   2
#define SS   1024
#define DD   768
#define HH   12
#define HDIM 64
#define DFF  3072
#define NROW (BB*SS)        // 2048
#define D3   (3*DD)         // 2304

// ---------------- scratch (device globals, no allocs) ----------------
__device__ __align__(16) float g_x1  [NROW*DD];
__device__ __align__(16) unsigned char g_rel8[NROW*SS];

__device__ __align__(16) __half g_xln [NROW*DD];
__device__ __align__(16) __half g_h   [NROW*DD];
__device__ __align__(16) __half g_attn[NROW*DD];
__device__ __align__(16) __half g_ff  [NROW*DFF];
__device__ __align__(16) __half g_qs  [NROW*DD];                 // Q single fp16
__device__ __align__(16) __half g_kh  [NROW*DD], g_kl[NROW*DD];  // K fp16 hi/lo
__device__ __align__(16) __half g_vs  [NROW*DD];                 // V single fp16
__device__ __align__(16) __half g_wqkv_h[D3*DD],  g_wqkv_l[D3*DD];
__device__ __align__(16) __half g_wo_h  [DD*DD],  g_wo_l  [DD*DD];
__device__ __align__(16) __half g_w1_h  [DFF*DD], g_w1_l  [DFF*DD];
__device__ __align__(16) __half g_w2_h  [DD*DFF], g_w2_l  [DD*DFF];

// ================= helpers =================
__device__ __forceinline__ uint32_t smem_u32(const void* p) {
    uint32_t a;
    asm("{ .reg .u64 t; cvta.to.shared.u64 t, %1; cvt.u32.u64 %0, t; }" : "=r"(a) : "l"(p));
    return a;
}
__device__ __forceinline__ void cp_async16(uint32_t dst, const void* src) {
    asm volatile("cp.async.cg.shared.global [%0], [%1], 16;\n" :: "r"(dst), "l"(src));
}
__device__ __forceinline__ void cp_commit() { asm volatile("cp.async.commit_group;\n" ::: "memory"); }

__device__ __forceinline__ void ldsm4(uint32_t addr, uint32_t& r0, uint32_t& r1, uint32_t& r2, uint32_t& r3) {
    asm volatile("ldmatrix.sync.aligned.m8n8.x4.shared.b16 {%0,%1,%2,%3}, [%4];"
                 : "=r"(r0), "=r"(r1), "=r"(r2), "=r"(r3) : "r"(addr));
}
__device__ __forceinline__ void ldsm4t(uint32_t addr, uint32_t& r0, uint32_t& r1, uint32_t& r2, uint32_t& r3) {
    asm volatile("ldmatrix.sync.aligned.m8n8.x4.trans.shared.b16 {%0,%1,%2,%3}, [%4];"
                 : "=r"(r0), "=r"(r1), "=r"(r2), "=r"(r3) : "r"(addr));
}
__device__ __forceinline__ void mma_f16(float* c, const uint32_t* a, const uint32_t* b) {
    asm volatile("mma.sync.aligned.m16n8k16.row.col.f32.f16.f16.f32 "
                 "{%0,%1,%2,%3}, {%4,%5,%6,%7}, {%8,%9}, {%0,%1,%2,%3};"
                 : "+f"(c[0]), "+f"(c[1]), "+f"(c[2]), "+f"(c[3])
                 : "r"(a[0]), "r"(a[1]), "r"(a[2]), "r"(a[3]), "r"(b[0]), "r"(b[1]));
}
__device__ __forceinline__ void split2h(float a, float b, uint32_t& hi, uint32_t& lo) {
    __half ha = __float2half(a), hb = __float2half(b);
    __half2 hh; hh.x = ha; hh.y = hb;
    __half2 ll;
    ll.x = __float2half(a - __half2float(ha));
    ll.y = __float2half(b - __half2float(hb));
    hi = *(uint32_t*)&hh; lo = *(uint32_t*)&ll;
}
__device__ __forceinline__ uint32_t pack_h2(float a, float b) {
    __half2 h; h.x = __float2half(a); h.y = __float2half(b);
    return *(uint32_t*)&h;
}
__device__ __forceinline__ float pick3(float a, float b, float c, int i) {
    return i == 0 ? a : (i == 1 ? b : c);
}

// ======== fused weight split: all 4 weights in one launch, 4 elems/thread ====
__global__ void __launch_bounds__(256) splitw_all_kernel(
    const float* __restrict__ qkv_w, const float* __restrict__ o_w,
    const float* __restrict__ w1,    const float* __restrict__ w2,
    __half* __restrict__ qkvh, __half* __restrict__ qkvl,
    __half* __restrict__ oh,   __half* __restrict__ ol,
    __half* __restrict__ w1h,  __half* __restrict__ w1l,
    __half* __restrict__ w2h,  __half* __restrict__ w2l)
{
    int bid = blockIdx.x;
    const float* src; __half *hi, *lo; int base;
    if (bid < 1728)      { src = qkv_w; hi = qkvh; lo = qkvl; base = bid; }
    else if (bid < 2304) { src = o_w;   hi = oh;   lo = ol;   base = bid - 1728; }
    else if (bid < 4608) { src = w1;    hi = w1h;  lo = w1l;  base = bid - 2304; }
    else                 { src = w2;    hi = w2h;  lo = w2l;  base = bid - 4608; }
    int i = base * 1024 + threadIdx.x * 4;
    float4 v = *(const float4*)(src + i);
    uint32_t h0, l0, h1, l1;
    split2h(v.x, v.y, h0, l0);
    split2h(v.z, v.w, h1, l1);
    *(uint32_t*)(hi + i)     = h0;
    *(uint32_t*)(hi + i + 2) = h1;
    *(uint32_t*)(lo + i)     = l0;
    *(uint32_t*)(lo + i + 2) = l1;
}

// ================= relm int32 -> uint8 (idx+1) =================
__global__ void __launch_bounds__(256) rel8_kernel(
    const int* __restrict__ relm, unsigned char* __restrict__ out)
{
    int i = blockIdx.x * 256 + threadIdx.x;
    int4 v = ((const int4*)relm)[i];
    uchar4 o;
    o.x = (unsigned char)(v.x + 1); o.y = (unsigned char)(v.y + 1);
    o.z = (unsigned char)(v.z + 1); o.w = (unsigned char)(v.w + 1);
    ((uchar4*)out)[i] = o;
}

// ================= LayerNorm -> fp16 =================
__global__ void __launch_bounds__(256) ln_kernel(
    const float* __restrict__ x, const float* __restrict__ g,
    const float* __restrict__ bt, __half* __restrict__ y)
{
    __shared__ float red[8];
    __shared__ float red2[8];
    const int row = blockIdx.x;
    const int tid = threadIdx.x;
    const float* xr = x + (size_t)row * DD;

    float v0 = xr[tid], v1 = xr[tid + 256], v2 = xr[tid + 512];
    float s = v0 + v1 + v2;
    #pragma unroll
    for (int off = 16; off >= 1; off >>= 1)
        s += __shfl_xor_sync(0xffffffffu, s, off);
    if ((tid & 31) == 0) red[tid >> 5] = s;
    __syncthreads();
    float tot = 0.f;
    #pragma unroll
    for (int i = 0; i < 8; i++) tot += red[i];
    const float mean = tot * (1.0f / DD);

    float d0 = v0 - mean, d1 = v1 - mean, d2 = v2 - mean;
    float ss = d0*d0 + d1*d1 + d2*d2;
    #pragma unroll
    for (int off = 16; off >= 1; off >>= 1)
        ss += __shfl_xor_sync(0xffffffffu, ss, off);
    if ((tid & 31) == 0) red2[tid >> 5] = ss;
    __syncthreads();
    float vtot = 0.f;
    #pragma unroll
    for (int i = 0; i < 8; i++) vtot += red2[i];
    const float rstd = rsqrtf(vtot * (1.0f / DD) + 1e-5f);

    #pragma unroll
    for (int j = 0; j < 3; j++) {
        int c = tid + j * 256;
        float dv = (j == 0 ? d0 : (j == 1 ? d1 : d2));
        y[(size_t)row * DD + c] = __float2half(dv * rstd * g[c] + bt[c]);
    }
}

// ================= fp16 2-term HMMA GEMM: C = A @ (Wh+Wl)^T ==================
// OUT: 0 fp32(+resid), 1 fp16, 3 QKV (Q single / K hi+lo / V single)
// occupancy 2 CTAs/SM for both BM variants (regs capped at 128).
#define SWZOFF(row, ch) ((uint32_t)((row) * 64 + (((ch) ^ (((row) >> 1) & 3)) * 16)))

template<bool RELU, bool BIAS, bool RESID, int OUT, int BM>
__global__ void __launch_bounds__(256, 2) hgemm(
    const __half* __restrict__ A,
    const __half* __restrict__ Wh, const __half* __restrict__ Wl,
    const float* __restrict__ bias, const float* __restrict__ resid,
    float* __restrict__ C, __half* __restrict__ Ch,
    __half* __restrict__ Cbh, __half* __restrict__ Cbl, __half* __restrict__ Cv,
    int M, int N, int K)
{
    constexpr int WMW = BM / 32;
    constexpr int WNW = 8 / WMW;
    constexpr int WN  = 128 / WNW;
    constexpr int NT  = WN / 8;
    constexpr int NP  = NT / 2;
    constexpr int A_BYTES = BM * 64;
    constexpr int STAGE = A_BYTES + 16384;
    constexpr int CHUNKS = BM * 4 + 1024;
    constexpr int ITERS = CHUNKS / 256;
    static_assert(CHUNKS % 256 == 0, "chunk count must divide");

    extern __shared__ __align__(128) char smem[];
    const uint32_t sb = smem_u32(smem);

    const int tid = threadIdx.x;
    const int wid = tid >> 5, lane = tid & 31;
    const int warp_m = wid & (WMW - 1), warp_n = wid / WMW;
    const int m0 = blockIdx.y * BM, n0 = blockIdx.x * 128;

    float acc[2][NT][4];
    #pragma unroll
    for (int mt = 0; mt < 2; mt++)
        #pragma unroll
        for (int nt = 0; nt < NT; nt++)
            #pragma unroll
            for (int j = 0; j < 4; j++) acc[mt][nt][j] = 0.f;

    const int niter = K >> 5;

    auto load_stage = [&](int buf, int k0) {
        uint32_t base = sb + buf * STAGE;
        #pragma unroll
        for (int t = 0; t < ITERS; t++) {
            int c = tid + t * 256;
            if (c < BM * 4) {
                int row = c >> 2, ch = c & 3;
                cp_async16(base + SWZOFF(row, ch),
                           A + (size_t)(m0 + row) * K + k0 + ch * 8);
            } else {
                int c2 = c - BM * 4;
                int tile = c2 >> 9;
                int w = c2 & 511;
                int row = w >> 2, ch = w & 3;
                const __half* src = (tile ? Wl : Wh) + (size_t)(n0 + row) * K + k0 + ch * 8;
                cp_async16(base + A_BYTES + tile * 8192 + SWZOFF(row, ch), src);
            }
        }
        cp_commit();
    };

    load_stage(0, 0);
    load_stage(1, 32);

    const int lr = lane & 15, lh = lane >> 4;

    int buf = 0;
    for (int it = 0; it < niter; it++) {
        if (it + 1 < niter) {
            asm volatile("cp.async.wait_group 1;\n" ::: "memory");
        } else {
            asm volatile("cp.async.wait_group 0;\n" ::: "memory");
        }
        __syncthreads();
        if (it + 2 < niter) {
            int nb = buf + 2; if (nb >= 3) nb -= 3;
            load_stage(nb, (it + 2) * 32);
        }

        const uint32_t base = sb + buf * STAGE;
        #pragma unroll
        for (int ks = 0; ks < 2; ks++) {
            const int ch = ks * 2 + lh;
            uint32_t af[2][4];
            #pragma unroll
            for (int mt = 0; mt < 2; mt++) {
                int row = warp_m * 32 + mt * 16 + lr;
                ldsm4(base + SWZOFF(row, ch), af[mt][0], af[mt][1], af[mt][2], af[mt][3]);
            }
            uint32_t bh[NT][2];
            #pragma unroll
            for (int np = 0; np < NP; np++) {
                int row = warp_n * WN + np * 16 + lr;
                uint32_t off = base + A_BYTES + SWZOFF(row, ch);
                ldsm4(off, bh[2*np][0], bh[2*np+1][0], bh[2*np][1], bh[2*np+1][1]);
            }
            #pragma unroll
            for (int mt = 0; mt < 2; mt++)
                #pragma unroll
                for (int nt = 0; nt < NT; nt++)
                    mma_f16(acc[mt][nt], af[mt], bh[nt]);
            uint32_t bl[NT][2];
            #pragma unroll
            for (int np = 0; np < NP; np++) {
                int row = warp_n * WN + np * 16 + lr;
                uint32_t off = base + A_BYTES + 8192 + SWZOFF(row, ch);
                ldsm4(off, bl[2*np][0], bl[2*np+1][0], bl[2*np][1], bl[2*np+1][1]);
            }
            #pragma unroll
            for (int mt = 0; mt < 2; mt++)
                #pragma unroll
                for (int nt = 0; nt < NT; nt++)
                    mma_f16(acc[mt][nt], af[mt], bl[nt]);
        }
        if (++buf >= 3) buf = 0;
    }

    #pragma unroll
    for (int mt = 0; mt < 2; mt++) {
        #pragma unroll
        for (int half = 0; half < 2; half++) {
            const int m = m0 + warp_m * 32 + mt * 16 + (lane >> 2) + half * 8;
            #pragma unroll
            for (int nt = 0; nt < NT; nt++) {
                const int n = n0 + warp_n * WN + nt * 8 + (lane & 3) * 2;
                float v0 = acc[mt][nt][half * 2 + 0];
                float v1 = acc[mt][nt][half * 2 + 1];
                if (BIAS) { v0 += bias[n]; v1 += bias[n + 1]; }
                if (RELU) { v0 = fmaxf(v0, 0.f); v1 = fmaxf(v1, 0.f); }
                if (RESID) {
                    float2 rv = *(const float2*)(resid + (size_t)m * N + n);
                    v0 += rv.x; v1 += rv.y;
                }
                if (OUT == 0) {
                    float2 o2; o2.x = v0; o2.y = v1;
                    *(float2*)(C + (size_t)m * N + n) = o2;
                } else if (OUT == 1) {
                    *(uint32_t*)(Ch + (size_t)m * N + n) = pack_h2(v0, v1);
                } else {
                    if (n0 < DD) {
                        *(uint32_t*)(Ch + (size_t)m * DD + n) = pack_h2(v0, v1);
                    } else if (n0 < 2 * DD) {
                        uint32_t hi, lo;
                        split2h(v0, v1, hi, lo);
                        *(uint32_t*)(Cbh + (size_t)m * DD + (n - DD)) = hi;
                        *(uint32_t*)(Cbl + (size_t)m * DD + (n - DD)) = lo;
                    } else {
                        *(uint32_t*)(Cv + (size_t)m * DD + (n - 2 * DD)) = pack_h2(v0, v1);
                    }
                }
            }
        }
    }
}

// ================= HMMA flash attention (K 2-term, V single), occ 2 =========
#define SWZ128(row, ch) ((uint32_t)((row) * 128 + (((ch) ^ ((row) & 7)) * 16)))

__global__ void __launch_bounds__(256, 2) attn_mma_kernel(
    const __half* __restrict__ qs,
    const __half* __restrict__ kh, const __half* __restrict__ kl,
    const __half* __restrict__ vs,
    const unsigned char* __restrict__ rel8, const unsigned char* __restrict__ amask,
    const float* __restrict__ relA, __half* __restrict__ outp)
{
    extern __shared__ __align__(128) char smem[];
    const uint32_t sQ = smem_u32(smem);
    const uint32_t sStage = sQ + 16384;           // +stage*24576: Kh,Kl,Vh
    float* mb = (float*)(smem + 16384 + 49152);   // [2][64]

    const int tid = threadIdx.x, wid = tid >> 5, lane = tid & 31;
    const int lr = lane & 15, lh = lane >> 4;
    const int b = blockIdx.z, h = blockIdx.y;
    const int q0 = blockIdx.x * 128;

    // ---- Q tile ----
    #pragma unroll
    for (int t = 0; t < 4; t++) {
        int lin = tid + t * 256;
        int row = lin >> 3, ch = lin & 7;
        cp_async16(sQ + SWZ128(row, ch),
                   qs + (size_t)(b * SS + q0 + row) * DD + h * HDIM + ch * 8);
    }
    cp_commit();

    auto load_kv = [&](int stage, int kt) {
        const int k0 = kt * 64;
        uint32_t base = sStage + stage * 24576;
        #pragma unroll
        for (int t = 0; t < 6; t++) {
            int lin = tid + t * 256;          // 0..1535
            int tensor = lin >> 9;            // 0:Kh 1:Kl 2:Vh
            int w = lin & 511;
            int row = w >> 3, ch = w & 7;
            uint32_t off = base + tensor * 8192 + SWZ128(row, ch);
            size_t g = (size_t)(b * SS + k0 + row) * DD + h * HDIM + ch * 8;
            const __half* src = (tensor == 0) ? kh : (tensor == 1 ? kl : vs);
            cp_async16(off, src + g);
        }
        if (tid < 64) mb[stage * 64 + tid] = amask[b * SS + k0 + tid] ? -1e30f : 0.f;
        cp_commit();
    };

    load_kv(0, 0);

    asm volatile("cp.async.wait_group 1;\n" ::: "memory");  // Q ready
    __syncthreads();

    uint32_t qf[4][4];
    #pragma unroll
    for (int ks = 0; ks < 4; ks++) {
        uint32_t off = SWZ128(wid * 16 + lr, ks * 2 + lh);
        ldsm4(sQ + off, qf[ks][0], qf[ks][1], qf[ks][2], qf[ks][3]);
    }

    const int r0 = wid * 16 + (lane >> 2);
    float rs00 = 0.f, rs01 = 0.f, rs02 = 0.f;
    float rs10 = 0.f, rs11 = 0.f, rs12 = 0.f;
    {
        const int dbase = (lane & 3) * 16;
        #pragma unroll
        for (int dd = 0; dd < 16; dd++) {
            int d = dbase + dd;
            float q0v = __half2float(*(const __half*)(smem + SWZ128(r0, d >> 3) + (d & 7) * 2));
            float q1v = __half2float(*(const __half*)(smem + SWZ128(r0 + 8, d >> 3) + (d & 7) * 2));
            float a0 = relA[d], a1 = relA[64 + d], a2 = relA[128 + d];
            rs00 += q0v * a0; rs01 += q0v * a1; rs02 += q0v * a2;
            rs10 += q1v * a0; rs11 += q1v * a1; rs12 += q1v * a2;
        }
        #pragma unroll
        for (int off = 1; off <= 2; off <<= 1) {
            rs00 += __shfl_xor_sync(0xffffffffu, rs00, off);
            rs01 += __shfl_xor_sync(0xffffffffu, rs01, off);
            rs02 += __shfl_xor_sync(0xffffffffu, rs02, off);
            rs10 += __shfl_xor_sync(0xffffffffu, rs10, off);
            rs11 += __shfl_xor_sync(0xffffffffu, rs11, off);
            rs12 += __shfl_xor_sync(0xffffffffu, rs12, off);
        }
    }

    float o[8][4];
    #pragma unroll
    for (int nt = 0; nt < 8; nt++)
        #pragma unroll
        for (int j = 0; j < 4; j++) o[nt][j] = 0.f;
    float m0 = -1e30f, m1 = -1e30f, l0 = 0.f, l1 = 0.f;

    for (int kt = 0; kt < SS / 64; kt++) {
        const int cur = kt & 1;
        asm volatile("cp.async.wait_group 0;\n" ::: "memory");
        __syncthreads();
        if (kt + 1 < SS / 64) load_kv((kt + 1) & 1, kt + 1);

        const uint32_t stg = sStage + cur * 24576;
        const float* mbc = mb + cur * 64;
        const int k0 = kt * 64;

        // ---- S = Q (Kh + Kl)^T ----
        float s[8][4];
        #pragma unroll
        for (int nt = 0; nt < 8; nt++)
            #pragma unroll
            for (int j = 0; j < 4; j++) s[nt][j] = 0.f;

        #pragma unroll
        for (int ks = 0; ks < 4; ks++) {
            uint32_t kf[8][2];
            #pragma unroll
            for (int np = 0; np < 4; np++) {
                uint32_t off = stg + SWZ128(np * 16 + lr, ks * 2 + lh);
                ldsm4(off, kf[2*np][0], kf[2*np+1][0], kf[2*np][1], kf[2*np+1][1]);
            }
            #pragma unroll
            for (int nt = 0; nt < 8; nt++) mma_f16(s[nt], qf[ks], kf[nt]);
            #pragma unroll
            for (int np = 0; np < 4; np++) {
                uint32_t off = stg + 8192 + SWZ128(np * 16 + lr, ks * 2 + lh);
                ldsm4(off, kf[2*np][0], kf[2*np+1][0], kf[2*np][1], kf[2*np+1][1]);
            }
            #pragma unroll
            for (int nt = 0; nt < 8; nt++) mma_f16(s[nt], qf[ks], kf[nt]);
        }

        // ---- bias + online softmax ----
        float mx0 = -1e30f, mx1 = -1e30f;
        #pragma unroll
        for (int nt = 0; nt < 8; nt++) {
            const int c0 = nt * 8 + (lane & 3) * 2;
            uchar2 i0 = *(const uchar2*)(rel8 + (size_t)(b * SS + q0 + r0) * SS + k0 + c0);
            uchar2 i1 = *(const uchar2*)(rel8 + (size_t)(b * SS + q0 + r0 + 8) * SS + k0 + c0);
            float mb0 = mbc[c0], mb1 = mbc[c0 + 1];
            s[nt][0] = (s[nt][0] + pick3(rs00, rs01, rs02, i0.x)) * 0.125f + mb0;
            s[nt][1] = (s[nt][1] + pick3(rs00, rs01, rs02, i0.y)) * 0.125f + mb1;
            s[nt][2] = (s[nt][2] + pick3(rs10, rs11, rs12, i1.x)) * 0.125f + mb0;
            s[nt][3] = (s[nt][3] + pick3(rs10, rs11, rs12, i1.y)) * 0.125f + mb1;
            mx0 = fmaxf(mx0, fmaxf(s[nt][0], s[nt][1]));
            mx1 = fmaxf(mx1, fmaxf(s[nt][2], s[nt][3]));
        }
        #pragma unroll
        for (int off = 1; off <= 2; off <<= 1) {
            mx0 = fmaxf(mx0, __shfl_xor_sync(0xffffffffu, mx0, off));
            mx1 = fmaxf(mx1, __shfl_xor_sync(0xffffffffu, mx1, off));
        }
        const float mn0 = fmaxf(m0, mx0), mn1 = fmaxf(m1, mx1);
        const float fac0 = __expf(m0 - mn0), fac1 = __expf(m1 - mn1);
        float sum0 = 0.f, sum1 = 0.f;
        #pragma unroll
        for (int nt = 0; nt < 8; nt++) {
            s[nt][0] = __expf(s[nt][0] - mn0);
            s[nt][1] = __expf(s[nt][1] - mn0);
            s[nt][2] = __expf(s[nt][2] - mn1);
            s[nt][3] = __expf(s[nt][3] - mn1);
            sum0 += s[nt][0] + s[nt][1];
            sum1 += s[nt][2] + s[nt][3];
        }
        #pragma unroll
        for (int off = 1; off <= 2; off <<= 1) {
            sum0 += __shfl_xor_sync(0xffffffffu, sum0, off);
            sum1 += __shfl_xor_sync(0xffffffffu, sum1, off);
        }
        l0 = l0 * fac0 + sum0;
        l1 = l1 * fac1 + sum1;
        m0 = mn0; m1 = mn1;
        #pragma unroll
        for (int nt = 0; nt < 8; nt++) {
            o[nt][0] *= fac0; o[nt][1] *= fac0;
            o[nt][2] *= fac1; o[nt][3] *= fac1;
        }

        // ---- O += P V (single-term) ----
        #pragma unroll
        for (int ks2 = 0; ks2 < 4; ks2++) {
            uint32_t pa[4];
            pa[0] = pack_h2(s[2*ks2][0],   s[2*ks2][1]);
            pa[1] = pack_h2(s[2*ks2][2],   s[2*ks2][3]);
            pa[2] = pack_h2(s[2*ks2+1][0], s[2*ks2+1][1]);
            pa[3] = pack_h2(s[2*ks2+1][2], s[2*ks2+1][3]);
            uint32_t vf[8][2];
            #pragma unroll
            for (int np = 0; np < 4; np++) {
                uint32_t off = stg + 16384 + SWZ128(ks2 * 16 + lr, np * 2 + lh);
                ldsm4t(off, vf[2*np][0], vf[2*np][1], vf[2*np+1][0], vf[2*np+1][1]);
            }
            #pragma unroll
            for (int nt = 0; nt < 8; nt++) mma_f16(o[nt], pa, vf[nt]);
        }
    }

    const float inv0 = 1.0f / l0, inv1 = 1.0f / l1;
    #pragma unroll
    for (int nt = 0; nt < 8; nt++) {
        const int c0 = nt * 8 + (lane & 3) * 2;
        size_t base0 = (size_t)(b * SS + q0 + r0) * DD + h * HDIM + c0;
        size_t base1 = (size_t)(b * SS + q0 + r0 + 8) * DD + h * HDIM + c0;
        *(uint32_t*)(outp + base0) = pack_h2(o[nt][0] * inv0, o[nt][1] * inv0);
        *(uint32_t*)(outp + base1) = pack_h2(o[nt][2] * inv1, o[nt][3] * inv1);
    }
}

// ================= launch =================
extern "C" void kernel_launch(void* const* d_in, const int* in_sizes, int n_in,
                              void* d_out, int out_size)
{
    const float*         inp   = (const float*)d_in[0];
    const unsigned char* amask = (const unsigned char*)d_in[1];
    const int*           relm  = (const int*)d_in[2];
    const float*         qkv_w = (const float*)d_in[3];
    const float*         relA  = (const float*)d_in[4];
    const float*         o_w   = (const float*)d_in[5];
    const float*         w1    = (const float*)d_in[6];
    const float*         b1    = (const float*)d_in[7];
    const float*         w2    = (const float*)d_in[8];
    const float*         b2    = (const float*)d_in[9];
    const float*         ln1g  = (const float*)d_in[10];
    const float*         ln1b  = (const float*)d_in[11];
    const float*         ln2g  = (const float*)d_in[12];
    const float*         ln2b  = (const float*)d_in[13];
    float* out = (float*)d_out;

    float *x1;
    unsigned char* rel8;
    __half *xln, *hbuf, *attn, *ff, *qsp, *khp, *klp, *vsp;
    __half *wqh, *wql, *woh, *wol, *w1h, *w1l, *w2h, *w2l;
    cudaGetSymbolAddress((void**)&x1,   g_x1);
    cudaGetSymbolAddress((void**)&rel8, g_rel8);
    cudaGetSymbolAddress((void**)&xln,  g_xln);
    cudaGetSymbolAddress((void**)&hbuf, g_h);
    cudaGetSymbolAddress((void**)&attn, g_attn);
    cudaGetSymbolAddress((void**)&ff,   g_ff);
    cudaGetSymbolAddress((void**)&qsp,  g_qs);
    cudaGetSymbolAddress((void**)&khp,  g_kh);     cudaGetSymbolAddress((void**)&klp, g_kl);
    cudaGetSymbolAddress((void**)&vsp,  g_vs);
    cudaGetSymbolAddress((void**)&wqh,  g_wqkv_h); cudaGetSymbolAddress((void**)&wql, g_wqkv_l);
    cudaGetSymbolAddress((void**)&woh,  g_wo_h);   cudaGetSymbolAddress((void**)&wol, g_wo_l);
    cudaGetSymbolAddress((void**)&w1h,  g_w1_h);   cudaGetSymbolAddress((void**)&w1l, g_w1_l);
    cudaGetSymbolAddress((void**)&w2h,  g_w2_h);   cudaGetSymbolAddress((void**)&w2l, g_w2_l);

    const int SMEM128 = 3 * (128 * 64 + 16384);   // 73728
    const int SMEM64  = 3 * (64 * 64 + 16384);    // 61440
    const int ASMEM = 16384 + 2 * 24576 + 512;    // 66048
    cudaFuncSetAttribute(hgemm<false,false,false,3,128>, cudaFuncAttributeMaxDynamicSharedMemorySize, SMEM128);
    cudaFuncSetAttribute(hgemm<true ,true ,false,1,128>, cudaFuncAttributeMaxDynamicSharedMemorySize, SMEM128);
    cudaFuncSetAttribute(hgemm<false,false,true ,0,64 >, cudaFuncAttributeMaxDynamicSharedMemorySize, SMEM64);
    cudaFuncSetAttribute(hgemm<false,true ,true ,0,64 >, cudaFuncAttributeMaxDynamicSharedMemorySize, SMEM64);
    cudaFuncSetAttribute(attn_mma_kernel, cudaFuncAttributeMaxDynamicSharedMemorySize, ASMEM);

    // 0) preprocessing (fused weight split + rel8)
    splitw_all_kernel<<<6912, 256>>>(qkv_w, o_w, w1, w2,
                                     wqh, wql, woh, wol, w1h, w1l, w2h, w2l);
    rel8_kernel<<<NROW*SS/4/256, 256>>>(relm, rel8);

    // 1) LN1 -> xln fp16
    ln_kernel<<<NROW, 256>>>(inp, ln1g, ln1b, xln);

    // 2) QKV: Q fp16 single, K fp16 hi/lo, V fp16 single
    hgemm<false,false,false,3,128><<<dim3(D3/128, NROW/128), 256, SMEM128>>>(
        xln, wqh, wql, nullptr, nullptr, nullptr, qsp, khp, klp, vsp, NROW, D3, DD);

    // 3) attention -> fp16
    attn_mma_kernel<<<dim3(SS/128, HH, BB), 256, ASMEM>>>(
        qsp, khp, klp, vsp, rel8, amask, relA, attn);

    // 4) x1 = inp + attn @ o_w^T (fp32)   BM=64, occ 2
    hgemm<false,false,true,0,64><<<dim3(DD/128, NROW/64), 256, SMEM64>>>(
        attn, woh, wol, nullptr, inp, x1, nullptr, nullptr, nullptr, nullptr, NROW, DD, DD);

    // 5) LN2 -> h fp16
    ln_kernel<<<NROW, 256>>>(x1, ln2g, ln2b, hbuf);

    // 6) ff = relu(h @ w1^T + b1) -> fp16
    hgemm<true,true,false,1,128><<<dim3(DFF/128, NROW/128), 256, SMEM128>>>(
        hbuf, w1h, w1l, b1, nullptr, nullptr, ff, nullptr, nullptr, nullptr, NROW, DFF, DD);

    // 7) out = x1 + ff @ w2^T + b2 (fp32)  BM=64, occ 2
    hgemm<false,true,true,0,64><<<dim3(DD/128, NROW/64), 256, SMEM64>>>(
        ff, w2h, w2l, b2, x1, out, nullptr, nullptr, nullptr, nullptr, NROW, DD, DFF);
}

// round 12
// speedup vs baseline: 6.1462x; 1.0870x over previous
#include <cuda_runtime.h>
#include <cuda_fp16.h>
#include <cstdint>

// ---------------- problem constants ----------------
#define BB   2
#define SS   1024
#define DD   768
#define HH   12
#define HDIM 64
#define DFF  3072
#define NROW (BB*SS)        // 2048
#define D3   (3*DD)         // 2304

// 0.125 * log2(e)
#define C1F 0.18033688011112042f

// ---------------- scratch (device globals, no allocs) ----------------
__device__ __align__(16) float g_x1  [NROW*DD];
__device__ __align__(16) unsigned char g_rel8[NROW*SS];

__device__ __align__(16) __half g_xln [NROW*DD];
__device__ __align__(16) __half g_h   [NROW*DD];
__device__ __align__(16) __half g_attn[NROW*DD];
__device__ __align__(16) __half g_ff  [NROW*DFF];
__device__ __align__(16) __half g_qs  [NROW*DD];                 // Q single fp16
__device__ __align__(16) __half g_kh  [NROW*DD], g_kl[NROW*DD];  // K fp16 hi/lo
__device__ __align__(16) __half g_vs  [NROW*DD];                 // V single fp16
__device__ __align__(16) __half g_wqkv_h[D3*DD],  g_wqkv_l[D3*DD];
__device__ __align__(16) __half g_wo_h  [DD*DD],  g_wo_l  [DD*DD];
__device__ __align__(16) __half g_w1_h  [DFF*DD], g_w1_l  [DFF*DD];
__device__ __align__(16) __half g_w2_h  [DD*DFF], g_w2_l  [DD*DFF];

// ================= helpers =================
__device__ __forceinline__ uint32_t smem_u32(const void* p) {
    uint32_t a;
    asm("{ .reg .u64 t; cvta.to.shared.u64 t, %1; cvt.u32.u64 %0, t; }" : "=r"(a) : "l"(p));
    return a;
}
__device__ __forceinline__ void cp_async16(uint32_t dst, const void* src) {
    asm volatile("cp.async.cg.shared.global [%0], [%1], 16;\n" :: "r"(dst), "l"(src));
}
__device__ __forceinline__ void cp_commit() { asm volatile("cp.async.commit_group;\n" ::: "memory"); }

__device__ __forceinline__ void ldsm4(uint32_t addr, uint32_t& r0, uint32_t& r1, uint32_t& r2, uint32_t& r3) {
    asm volatile("ldmatrix.sync.aligned.m8n8.x4.shared.b16 {%0,%1,%2,%3}, [%4];"
                 : "=r"(r0), "=r"(r1), "=r"(r2), "=r"(r3) : "r"(addr));
}
__device__ __forceinline__ void ldsm4t(uint32_t addr, uint32_t& r0, uint32_t& r1, uint32_t& r2, uint32_t& r3) {
    asm volatile("ldmatrix.sync.aligned.m8n8.x4.trans.shared.b16 {%0,%1,%2,%3}, [%4];"
                 : "=r"(r0), "=r"(r1), "=r"(r2), "=r"(r3) : "r"(addr));
}
__device__ __forceinline__ void mma_f16(float* c, const uint32_t* a, const uint32_t* b) {
    asm volatile("mma.sync.aligned.m16n8k16.row.col.f32.f16.f16.f32 "
                 "{%0,%1,%2,%3}, {%4,%5,%6,%7}, {%8,%9}, {%0,%1,%2,%3};"
                 : "+f"(c[0]), "+f"(c[1]), "+f"(c[2]), "+f"(c[3])
                 : "r"(a[0]), "r"(a[1]), "r"(a[2]), "r"(a[3]), "r"(b[0]), "r"(b[1]));
}
__device__ __forceinline__ void split2h(float a, float b, uint32_t& hi, uint32_t& lo) {
    __half ha = __float2half(a), hb = __float2half(b);
    __half2 hh; hh.x = ha; hh.y = hb;
    __half2 ll;
    ll.x = __float2half(a - __half2float(ha));
    ll.y = __float2half(b - __half2float(hb));
    hi = *(uint32_t*)&hh; lo = *(uint32_t*)&ll;
}
__device__ __forceinline__ uint32_t pack_h2(float a, float b) {
    __half2 h; h.x = __float2half(a); h.y = __float2half(b);
    return *(uint32_t*)&h;
}
// half2{lo, hi} = 2^{lo_arg}, 2^{hi_arg}
__device__ __forceinline__ uint32_t exp2_h2(float lo, float hi) {
    uint32_t r;
    asm("{ .reg .b32 t; cvt.rn.f16x2.f32 t, %2, %1; ex2.approx.f16x2 %0, t; }"
        : "=r"(r) : "f"(lo), "f"(hi));
    return r;
}
__device__ __forceinline__ float pick3(float a, float b, float c, int i) {
    return i == 0 ? a : (i == 1 ? b : c);
}

// ======== fused weight split ====
__global__ void __launch_bounds__(256) splitw_all_kernel(
    const float* __restrict__ qkv_w, const float* __restrict__ o_w,
    const float* __restrict__ w1,    const float* __restrict__ w2,
    __half* __restrict__ qkvh, __half* __restrict__ qkvl,
    __half* __restrict__ oh,   __half* __restrict__ ol,
    __half* __restrict__ w1h,  __half* __restrict__ w1l,
    __half* __restrict__ w2h,  __half* __restrict__ w2l)
{
    int bid = blockIdx.x;
    const float* src; __half *hi, *lo; int base;
    if (bid < 1728)      { src = qkv_w; hi = qkvh; lo = qkvl; base = bid; }
    else if (bid < 2304) { src = o_w;   hi = oh;   lo = ol;   base = bid - 1728; }
    else if (bid < 4608) { src = w1;    hi = w1h;  lo = w1l;  base = bid - 2304; }
    else                 { src = w2;    hi = w2h;  lo = w2l;  base = bid - 4608; }
    int i = base * 1024 + threadIdx.x * 4;
    float4 v = *(const float4*)(src + i);
    uint32_t h0, l0, h1, l1;
    split2h(v.x, v.y, h0, l0);
    split2h(v.z, v.w, h1, l1);
    *(uint32_t*)(hi + i)     = h0;
    *(uint32_t*)(hi + i + 2) = h1;
    *(uint32_t*)(lo + i)     = l0;
    *(uint32_t*)(lo + i + 2) = l1;
}

// ================= relm int32 -> uint8 (idx+1) =================
__global__ void __launch_bounds__(256) rel8_kernel(
    const int* __restrict__ relm, unsigned char* __restrict__ out)
{
    int i = blockIdx.x * 256 + threadIdx.x;
    int4 v = ((const int4*)relm)[i];
    uchar4 o;
    o.x = (unsigned char)(v.x + 1); o.y = (unsigned char)(v.y + 1);
    o.z = (unsigned char)(v.z + 1); o.w = (unsigned char)(v.w + 1);
    ((uchar4*)out)[i] = o;
}

// ================= LayerNorm -> fp16 =================
__global__ void __launch_bounds__(256) ln_kernel(
    const float* __restrict__ x, const float* __restrict__ g,
    const float* __restrict__ bt, __half* __restrict__ y)
{
    __shared__ float red[8];
    __shared__ float red2[8];
    const int row = blockIdx.x;
    const int tid = threadIdx.x;
    const float* xr = x + (size_t)row * DD;

    float v0 = xr[tid], v1 = xr[tid + 256], v2 = xr[tid + 512];
    float s = v0 + v1 + v2;
    #pragma unroll
    for (int off = 16; off >= 1; off >>= 1)
        s += __shfl_xor_sync(0xffffffffu, s, off);
    if ((tid & 31) == 0) red[tid >> 5] = s;
    __syncthreads();
    float tot = 0.f;
    #pragma unroll
    for (int i = 0; i < 8; i++) tot += red[i];
    const float mean = tot * (1.0f / DD);

    float d0 = v0 - mean, d1 = v1 - mean, d2 = v2 - mean;
    float ss = d0*d0 + d1*d1 + d2*d2;
    #pragma unroll
    for (int off = 16; off >= 1; off >>= 1)
        ss += __shfl_xor_sync(0xffffffffu, ss, off);
    if ((tid & 31) == 0) red2[tid >> 5] = ss;
    __syncthreads();
    float vtot = 0.f;
    #pragma unroll
    for (int i = 0; i < 8; i++) vtot += red2[i];
    const float rstd = rsqrtf(vtot * (1.0f / DD) + 1e-5f);

    #pragma unroll
    for (int j = 0; j < 3; j++) {
        int c = tid + j * 256;
        float dv = (j == 0 ? d0 : (j == 1 ? d1 : d2));
        y[(size_t)row * DD + c] = __float2half(dv * rstd * g[c] + bt[c]);
    }
}

// 128-byte-row swizzle (8 x 16B chunks per row)
#define SWZ128(row, ch) ((uint32_t)((row) * 128 + (((ch) ^ ((row) & 7)) * 16)))

// ================= fp16 2-term HMMA GEMM, BK=64, 2-stage, occ 2 =============
// OUT: 0 fp32(+resid), 1 fp16, 3 QKV (Q single / K hi+lo / V single)
template<bool RELU, bool BIAS, bool RESID, int OUT, int BM>
__global__ void __launch_bounds__(256, 2) hgemm(
    const __half* __restrict__ A,
    const __half* __restrict__ Wh, const __half* __restrict__ Wl,
    const float* __restrict__ bias, const float* __restrict__ resid,
    float* __restrict__ C, __half* __restrict__ Ch,
    __half* __restrict__ Cbh, __half* __restrict__ Cbl, __half* __restrict__ Cv,
    int M, int N, int K)
{
    constexpr int WMW = BM / 32;
    constexpr int WNW = 8 / WMW;
    constexpr int WN  = 128 / WNW;
    constexpr int NT  = WN / 8;
    constexpr int NP  = NT / 2;
    constexpr int A_BYTES = BM * 128;           // BM rows x 64 fp16
    constexpr int STAGE = A_BYTES + 32768;      // + Wh 16KB + Wl 16KB
    constexpr int CHUNKS = BM * 8 + 2048;
    constexpr int ITERS = CHUNKS / 256;
    static_assert(CHUNKS % 256 == 0, "chunk count must divide");

    extern __shared__ __align__(128) char smem[];
    const uint32_t sb = smem_u32(smem);

    const int tid = threadIdx.x;
    const int wid = tid >> 5, lane = tid & 31;
    const int warp_m = wid & (WMW - 1), warp_n = wid / WMW;
    const int m0 = blockIdx.y * BM, n0 = blockIdx.x * 128;

    float acc[2][NT][4];
    #pragma unroll
    for (int mt = 0; mt < 2; mt++)
        #pragma unroll
        for (int nt = 0; nt < NT; nt++)
            #pragma unroll
            for (int j = 0; j < 4; j++) acc[mt][nt][j] = 0.f;

    const int niter = K >> 6;

    auto load_stage = [&](int buf, int k0) {
        uint32_t base = sb + buf * STAGE;
        #pragma unroll
        for (int t = 0; t < ITERS; t++) {
            int c = tid + t * 256;
            if (c < BM * 8) {
                int row = c >> 3, ch = c & 7;
                cp_async16(base + SWZ128(row, ch),
                           A + (size_t)(m0 + row) * K + k0 + ch * 8);
            } else {
                int c2 = c - BM * 8;              // 0..2047
                int tile = c2 >> 10;              // 0:Wh 1:Wl
                int w = c2 & 1023;
                int row = w >> 3, ch = w & 7;
                const __half* src = (tile ? Wl : Wh) + (size_t)(n0 + row) * K + k0 + ch * 8;
                cp_async16(base + A_BYTES + tile * 16384 + SWZ128(row, ch), src);
            }
        }
        cp_commit();
    };

    load_stage(0, 0);

    const int lr = lane & 15, lh = lane >> 4;

    for (int it = 0; it < niter; it++) {
        asm volatile("cp.async.wait_group 0;\n" ::: "memory");
        __syncthreads();
        if (it + 1 < niter) load_stage((it + 1) & 1, (it + 1) * 64);

        const uint32_t base = sb + (it & 1) * STAGE;
        #pragma unroll
        for (int ks = 0; ks < 4; ks++) {
            const int ch = ks * 2 + lh;
            uint32_t af[2][4];
            #pragma unroll
            for (int mt = 0; mt < 2; mt++) {
                int row = warp_m * 32 + mt * 16 + lr;
                ldsm4(base + SWZ128(row, ch), af[mt][0], af[mt][1], af[mt][2], af[mt][3]);
            }
            uint32_t bh[NT][2];
            #pragma unroll
            for (int np = 0; np < NP; np++) {
                int row = warp_n * WN + np * 16 + lr;
                uint32_t off = base + A_BYTES + SWZ128(row, ch);
                ldsm4(off, bh[2*np][0], bh[2*np+1][0], bh[2*np][1], bh[2*np+1][1]);
            }
            #pragma unroll
            for (int mt = 0; mt < 2; mt++)
                #pragma unroll
                for (int nt = 0; nt < NT; nt++)
                    mma_f16(acc[mt][nt], af[mt], bh[nt]);
            uint32_t bl[NT][2];
            #pragma unroll
            for (int np = 0; np < NP; np++) {
                int row = warp_n * WN + np * 16 + lr;
                uint32_t off = base + A_BYTES + 16384 + SWZ128(row, ch);
                ldsm4(off, bl[2*np][0], bl[2*np+1][0], bl[2*np][1], bl[2*np+1][1]);
            }
            #pragma unroll
            for (int mt = 0; mt < 2; mt++)
                #pragma unroll
                for (int nt = 0; nt < NT; nt++)
                    mma_f16(acc[mt][nt], af[mt], bl[nt]);
        }
    }

    #pragma unroll
    for (int mt = 0; mt < 2; mt++) {
        #pragma unroll
        for (int half = 0; half < 2; half++) {
            const int m = m0 + warp_m * 32 + mt * 16 + (lane >> 2) + half * 8;
            #pragma unroll
            for (int nt = 0; nt < NT; nt++) {
                const int n = n0 + warp_n * WN + nt * 8 + (lane & 3) * 2;
                float v0 = acc[mt][nt][half * 2 + 0];
                float v1 = acc[mt][nt][half * 2 + 1];
                if (BIAS) { v0 += bias[n]; v1 += bias[n + 1]; }
                if (RELU) { v0 = fmaxf(v0, 0.f); v1 = fmaxf(v1, 0.f); }
                if (RESID) {
                    float2 rv = *(const float2*)(resid + (size_t)m * N + n);
                    v0 += rv.x; v1 += rv.y;
                }
                if (OUT == 0) {
                    float2 o2; o2.x = v0; o2.y = v1;
                    *(float2*)(C + (size_t)m * N + n) = o2;
                } else if (OUT == 1) {
                    *(uint32_t*)(Ch + (size_t)m * N + n) = pack_h2(v0, v1);
                } else {
                    if (n0 < DD) {
                        *(uint32_t*)(Ch + (size_t)m * DD + n) = pack_h2(v0, v1);
                    } else if (n0 < 2 * DD) {
                        uint32_t hi, lo;
                        split2h(v0, v1, hi, lo);
                        *(uint32_t*)(Cbh + (size_t)m * DD + (n - DD)) = hi;
                        *(uint32_t*)(Cbl + (size_t)m * DD + (n - DD)) = lo;
                    } else {
                        *(uint32_t*)(Cv + (size_t)m * DD + (n - 2 * DD)) = pack_h2(v0, v1);
                    }
                }
            }
        }
    }
}

// ====== HMMA flash attention: K 2-term, V single, exp2-f16x2 softmax ========
// l computed exactly via ones-column MMA on the fp16 P fragments.
__global__ void __launch_bounds__(256, 2) attn_mma_kernel(
    const __half* __restrict__ qs,
    const __half* __restrict__ kh, const __half* __restrict__ kl,
    const __half* __restrict__ vs,
    const unsigned char* __restrict__ rel8, const unsigned char* __restrict__ amask,
    const float* __restrict__ relA, __half* __restrict__ outp)
{
    extern __shared__ __align__(128) char smem[];
    const uint32_t sQ = smem_u32(smem);
    const uint32_t sStage = sQ + 16384;           // +stage*24576: Kh,Kl,Vh
    float* mb = (float*)(smem + 16384 + 49152);   // [2][64]

    const int tid = threadIdx.x, wid = tid >> 5, lane = tid & 31;
    const int lr = lane & 15, lh = lane >> 4;
    const int b = blockIdx.z, h = blockIdx.y;
    const int q0 = blockIdx.x * 128;

    // ---- Q tile ----
    #pragma unroll
    for (int t = 0; t < 4; t++) {
        int lin = tid + t * 256;
        int row = lin >> 3, ch = lin & 7;
        cp_async16(sQ + SWZ128(row, ch),
                   qs + (size_t)(b * SS + q0 + row) * DD + h * HDIM + ch * 8);
    }
    cp_commit();

    auto load_kv = [&](int stage, int kt) {
        const int k0 = kt * 64;
        uint32_t base = sStage + stage * 24576;
        #pragma unroll
        for (int t = 0; t < 6; t++) {
            int lin = tid + t * 256;
            int tensor = lin >> 9;
            int w = lin & 511;
            int row = w >> 3, ch = w & 7;
            uint32_t off = base + tensor * 8192 + SWZ128(row, ch);
            size_t g = (size_t)(b * SS + k0 + row) * DD + h * HDIM + ch * 8;
            const __half* src = (tensor == 0) ? kh : (tensor == 1 ? kl : vs);
            cp_async16(off, src + g);
        }
        if (tid < 64) mb[stage * 64 + tid] = amask[b * SS + k0 + tid] ? -1e30f : 0.f;
        cp_commit();
    };

    load_kv(0, 0);

    asm volatile("cp.async.wait_group 1;\n" ::: "memory");  // Q ready
    __syncthreads();

    uint32_t qf[4][4];
    #pragma unroll
    for (int ks = 0; ks < 4; ks++) {
        uint32_t off = SWZ128(wid * 16 + lr, ks * 2 + lh);
        ldsm4(sQ + off, qf[ks][0], qf[ks][1], qf[ks][2], qf[ks][3]);
    }

    // per-row relative logits, pre-scaled into exp2 domain: rsc = (q.A_c) * C1F
    const int r0 = wid * 16 + (lane >> 2);
    float rs00 = 0.f, rs01 = 0.f, rs02 = 0.f;
    float rs10 = 0.f, rs11 = 0.f, rs12 = 0.f;
    {
        const int dbase = (lane & 3) * 16;
        #pragma unroll
        for (int dd = 0; dd < 16; dd++) {
            int d = dbase + dd;
            float q0v = __half2float(*(const __half*)(smem + SWZ128(r0, d >> 3) + (d & 7) * 2));
            float q1v = __half2float(*(const __half*)(smem + SWZ128(r0 + 8, d >> 3) + (d & 7) * 2));
            float a0 = relA[d], a1 = relA[64 + d], a2 = relA[128 + d];
            rs00 += q0v * a0; rs01 += q0v * a1; rs02 += q0v * a2;
            rs10 += q1v * a0; rs11 += q1v * a1; rs12 += q1v * a2;
        }
        #pragma unroll
        for (int off = 1; off <= 2; off <<= 1) {
            rs00 += __shfl_xor_sync(0xffffffffu, rs00, off);
            rs01 += __shfl_xor_sync(0xffffffffu, rs01, off);
            rs02 += __shfl_xor_sync(0xffffffffu, rs02, off);
            rs10 += __shfl_xor_sync(0xffffffffu, rs10, off);
            rs11 += __shfl_xor_sync(0xffffffffu, rs11, off);
            rs12 += __shfl_xor_sync(0xffffffffu, rs12, off);
        }
        rs00 *= C1F; rs01 *= C1F; rs02 *= C1F;
        rs10 *= C1F; rs11 *= C1F; rs12 *= C1F;
    }

    // ones-column B fragment: B[k][0] = 1 for all k
    uint32_t ones_b[2];
    ones_b[0] = ones_b[1] = (lane < 4) ? 0x3C003C00u : 0u;

    float o[8][4];
    #pragma unroll
    for (int nt = 0; nt < 8; nt++)
        #pragma unroll
        for (int j = 0; j < 4; j++) o[nt][j] = 0.f;
    float lacc[4] = {0.f, 0.f, 0.f, 0.f};
    float m0 = -1e30f, m1 = -1e30f;

    for (int kt = 0; kt < SS / 64; kt++) {
        const int cur = kt & 1;
        asm volatile("cp.async.wait_group 0;\n" ::: "memory");
        __syncthreads();
        if (kt + 1 < SS / 64) load_kv((kt + 1) & 1, kt + 1);

        const uint32_t stg = sStage + cur * 24576;
        const float* mbc = mb + cur * 64;
        const int k0 = kt * 64;

        // prefetch rel8 class indices (consumed after the S MMAs)
        uchar2 iv0[8], iv1[8];
        #pragma unroll
        for (int nt = 0; nt < 8; nt++) {
            const int c0 = nt * 8 + (lane & 3) * 2;
            iv0[nt] = *(const uchar2*)(rel8 + (size_t)(b * SS + q0 + r0) * SS + k0 + c0);
            iv1[nt] = *(const uchar2*)(rel8 + (size_t)(b * SS + q0 + r0 + 8) * SS + k0 + c0);
        }

        // ---- S = Q (Kh + Kl)^T ----
        float s[8][4];
        #pragma unroll
        for (int nt = 0; nt < 8; nt++)
            #pragma unroll
            for (int j = 0; j < 4; j++) s[nt][j] = 0.f;

        #pragma unroll
        for (int ks = 0; ks < 4; ks++) {
            uint32_t kf[8][2];
            #pragma unroll
            for (int np = 0; np < 4; np++) {
                uint32_t off = stg + SWZ128(np * 16 + lr, ks * 2 + lh);
                ldsm4(off, kf[2*np][0], kf[2*np+1][0], kf[2*np][1], kf[2*np+1][1]);
            }
            #pragma unroll
            for (int nt = 0; nt < 8; nt++) mma_f16(s[nt], qf[ks], kf[nt]);
            #pragma unroll
            for (int np = 0; np < 4; np++) {
                uint32_t off = stg + 8192 + SWZ128(np * 16 + lr, ks * 2 + lh);
                ldsm4(off, kf[2*np][0], kf[2*np+1][0], kf[2*np][1], kf[2*np+1][1]);
            }
            #pragma unroll
            for (int nt = 0; nt < 8; nt++) mma_f16(s[nt], qf[ks], kf[nt]);
        }

        // ---- exp2-domain args + max ----
        float mx0 = -1e30f, mx1 = -1e30f;
        #pragma unroll
        for (int nt = 0; nt < 8; nt++) {
            const int c0 = nt * 8 + (lane & 3) * 2;
            float mb0 = mbc[c0], mb1 = mbc[c0 + 1];
            s[nt][0] = fmaf(s[nt][0], C1F, pick3(rs00, rs01, rs02, iv0[nt].x) + mb0);
            s[nt][1] = fmaf(s[nt][1], C1F, pick3(rs00, rs01, rs02, iv0[nt].y) + mb1);
            s[nt][2] = fmaf(s[nt][2], C1F, pick3(rs10, rs11, rs12, iv1[nt].x) + mb0);
            s[nt][3] = fmaf(s[nt][3], C1F, pick3(rs10, rs11, rs12, iv1[nt].y) + mb1);
            mx0 = fmaxf(mx0, fmaxf(s[nt][0], s[nt][1]));
            mx1 = fmaxf(mx1, fmaxf(s[nt][2], s[nt][3]));
        }
        #pragma unroll
        for (int off = 1; off <= 2; off <<= 1) {
            mx0 = fmaxf(mx0, __shfl_xor_sync(0xffffffffu, mx0, off));
            mx1 = fmaxf(mx1, __shfl_xor_sync(0xffffffffu, mx1, off));
        }
        const float mn0 = fmaxf(m0, mx0), mn1 = fmaxf(m1, mx1);
        const float fac0 = exp2f(m0 - mn0), fac1 = exp2f(m1 - mn1);
        m0 = mn0; m1 = mn1;

        lacc[0] *= fac0; lacc[1] *= fac0;
        lacc[2] *= fac1; lacc[3] *= fac1;
        #pragma unroll
        for (int nt = 0; nt < 8; nt++) {
            o[nt][0] *= fac0; o[nt][1] *= fac0;
            o[nt][2] *= fac1; o[nt][3] *= fac1;
        }

        // ---- P = 2^(arg - m) as half2 fragments ----
        uint32_t ph[8], pl[8];
        #pragma unroll
        for (int nt = 0; nt < 8; nt++) {
            ph[nt] = exp2_h2(s[nt][0] - mn0, s[nt][1] - mn0);
            pl[nt] = exp2_h2(s[nt][2] - mn1, s[nt][3] - mn1);
        }

        // ---- l += P @ ones  and  O += P V ----
        #pragma unroll
        for (int ks2 = 0; ks2 < 4; ks2++) {
            uint32_t pa[4];
            pa[0] = ph[2*ks2];   pa[1] = pl[2*ks2];
            pa[2] = ph[2*ks2+1]; pa[3] = pl[2*ks2+1];
            mma_f16(lacc, pa, ones_b);
            uint32_t vf[8][2];
            #pragma unroll
            for (int np = 0; np < 4; np++) {
                uint32_t off = stg + 16384 + SWZ128(ks2 * 16 + lr, np * 2 + lh);
                ldsm4t(off, vf[2*np][0], vf[2*np][1], vf[2*np+1][0], vf[2*np+1][1]);
            }
            #pragma unroll
            for (int nt = 0; nt < 8; nt++) mma_f16(o[nt], pa, vf[nt]);
        }
    }

    // l lives in col 0 -> lane%4==0 threads; broadcast within each quad
    const float l0 = __shfl_sync(0xffffffffu, lacc[0], 0, 4);
    const float l1 = __shfl_sync(0xffffffffu, lacc[2], 0, 4);
    const float inv0 = 1.0f / l0, inv1 = 1.0f / l1;
    #pragma unroll
    for (int nt = 0; nt < 8; nt++) {
        const int c0 = nt * 8 + (lane & 3) * 2;
        size_t base0 = (size_t)(b * SS + q0 + r0) * DD + h * HDIM + c0;
        size_t base1 = (size_t)(b * SS + q0 + r0 + 8) * DD + h * HDIM + c0;
        *(uint32_t*)(outp + base0) = pack_h2(o[nt][0] * inv0, o[nt][1] * inv0);
        *(uint32_t*)(outp + base1) = pack_h2(o[nt][2] * inv1, o[nt][3] * inv1);
    }
}

// ================= launch =================
extern "C" void kernel_launch(void* const* d_in, const int* in_sizes, int n_in,
                              void* d_out, int out_size)
{
    const float*         inp   = (const float*)d_in[0];
    const unsigned char* amask = (const unsigned char*)d_in[1];
    const int*           relm  = (const int*)d_in[2];
    const float*         qkv_w = (const float*)d_in[3];
    const float*         relA  = (const float*)d_in[4];
    const float*         o_w   = (const float*)d_in[5];
    const float*         w1    = (const float*)d_in[6];
    const float*         b1    = (const float*)d_in[7];
    const float*         w2    = (const float*)d_in[8];
    const float*         b2    = (const float*)d_in[9];
    const float*         ln1g  = (const float*)d_in[10];
    const float*         ln1b  = (const float*)d_in[11];
    const float*         ln2g  = (const float*)d_in[12];
    const float*         ln2b  = (const float*)d_in[13];
    float* out = (float*)d_out;

    float *x1;
    unsigned char* rel8;
    __half *xln, *hbuf, *attn, *ff, *qsp, *khp, *klp, *vsp;
    __half *wqh, *wql, *woh, *wol, *w1h, *w1l, *w2h, *w2l;
    cudaGetSymbolAddress((void**)&x1,   g_x1);
    cudaGetSymbolAddress((void**)&rel8, g_rel8);
    cudaGetSymbolAddress((void**)&xln,  g_xln);
    cudaGetSymbolAddress((void**)&hbuf, g_h);
    cudaGetSymbolAddress((void**)&attn, g_attn);
    cudaGetSymbolAddress((void**)&ff,   g_ff);
    cudaGetSymbolAddress((void**)&qsp,  g_qs);
    cudaGetSymbolAddress((void**)&khp,  g_kh);     cudaGetSymbolAddress((void**)&klp, g_kl);
    cudaGetSymbolAddress((void**)&vsp,  g_vs);
    cudaGetSymbolAddress((void**)&wqh,  g_wqkv_h); cudaGetSymbolAddress((void**)&wql, g_wqkv_l);
    cudaGetSymbolAddress((void**)&woh,  g_wo_h);   cudaGetSymbolAddress((void**)&wol, g_wo_l);
    cudaGetSymbolAddress((void**)&w1h,  g_w1_h);   cudaGetSymbolAddress((void**)&w1l, g_w1_l);
    cudaGetSymbolAddress((void**)&w2h,  g_w2_h);   cudaGetSymbolAddress((void**)&w2l, g_w2_l);

    const int SMEM128 = 2 * (128 * 128 + 32768);   // 98304
    const int SMEM64  = 2 * (64 * 128 + 32768);    // 81920
    const int ASMEM = 16384 + 2 * 24576 + 512;     // 66048
    cudaFuncSetAttribute(hgemm<false,false,false,3,128>, cudaFuncAttributeMaxDynamicSharedMemorySize, SMEM128);
    cudaFuncSetAttribute(hgemm<true ,true ,false,1,128>, cudaFuncAttributeMaxDynamicSharedMemorySize, SMEM128);
    cudaFuncSetAttribute(hgemm<false,false,true ,0,64 >, cudaFuncAttributeMaxDynamicSharedMemorySize, SMEM64);
    cudaFuncSetAttribute(hgemm<false,true ,true ,0,64 >, cudaFuncAttributeMaxDynamicSharedMemorySize, SMEM64);
    cudaFuncSetAttribute(attn_mma_kernel, cudaFuncAttributeMaxDynamicSharedMemorySize, ASMEM);

    // 0) preprocessing
    splitw_all_kernel<<<6912, 256>>>(qkv_w, o_w, w1, w2,
                                     wqh, wql, woh, wol, w1h, w1l, w2h, w2l);
    rel8_kernel<<<NROW*SS/4/256, 256>>>(relm, rel8);

    // 1) LN1 -> xln fp16
    ln_kernel<<<NROW, 256>>>(inp, ln1g, ln1b, xln);

    // 2) QKV: Q fp16 single, K fp16 hi/lo, V fp16 single
    hgemm<false,false,false,3,128><<<dim3(D3/128, NROW/128), 256, SMEM128>>>(
        xln, wqh, wql, nullptr, nullptr, nullptr, qsp, khp, klp, vsp, NROW, D3, DD);

    // 3) attention -> fp16
    attn_mma_kernel<<<dim3(SS/128, HH, BB), 256, ASMEM>>>(
        qsp, khp, klp, vsp, rel8, amask, relA, attn);

    // 4) x1 = inp + attn @ o_w^T (fp32)
    hgemm<false,false,true,0,64><<<dim3(DD/128, NROW/64), 256, SMEM64>>>(
        attn, woh, wol, nullptr, inp, x1, nullptr, nullptr, nullptr, nullptr, NROW, DD, DD);

    // 5) LN2 -> h fp16
    ln_kernel<<<NROW, 256>>>(x1, ln2g, ln2b, hbuf);

    // 6) ff = relu(h @ w1^T + b1) -> fp16
    hgemm<true,true,false,1,128><<<dim3(DFF/128, NROW/128), 256, SMEM128>>>(
        hbuf, w1h, w1l, b1, nullptr, nullptr, ff, nullptr, nullptr, nullptr, NROW, DFF, DD);

    // 7) out = x1 + ff @ w2^T + b2 (fp32)
    hgemm<false,true,true,0,64><<<dim3(DD/128, NROW/64), 256, SMEM64>>>(
        ff, w2h, w2l, b2, x1, out, nullptr, nullptr, nullptr, nullptr, NROW, DD, DFF);
}

// round 13
// speedup vs baseline: 8.3381x; 1.3566x over previous
#include <cuda_runtime.h>
#include <cuda_fp16.h>
#include <cstdint>

// ---------------- problem constants ----------------
#define BB   2
#define SS   1024
#define DD   768
#define HH   12
#define HDIM 64
#define DFF  3072
#define NROW (BB*SS)        // 2048
#define D3   (3*DD)         // 2304

// 0.125 * log2(e)
#define C1F 0.18033688011112042f

// ---------------- scratch (device globals, no allocs) ----------------
__device__ __align__(16) float g_x1  [NROW*DD];
__device__ __align__(16) unsigned char g_rel8[NROW*SS];

__device__ __align__(16) __half g_xln [NROW*DD];
__device__ __align__(16) __half g_h   [NROW*DD];
__device__ __align__(16) __half g_attn[NROW*DD];
__device__ __align__(16) __half g_ff  [NROW*DFF];
__device__ __align__(16) __half g_qs  [NROW*DD];                 // Q single fp16
__device__ __align__(16) __half g_kh  [NROW*DD], g_kl[NROW*DD];  // K fp16 hi/lo
__device__ __align__(16) __half g_vs  [NROW*DD];                 // V single fp16
__device__ __align__(16) __half g_wqkv[D3*DD];
__device__ __align__(16) __half g_wo  [DD*DD];
__device__ __align__(16) __half g_w1  [DFF*DD];
__device__ __align__(16) __half g_w2  [DD*DFF];

// ================= helpers =================
__device__ __forceinline__ uint32_t smem_u32(const void* p) {
    uint32_t a;
    asm("{ .reg .u64 t; cvta.to.shared.u64 t, %1; cvt.u32.u64 %0, t; }" : "=r"(a) : "l"(p));
    return a;
}
__device__ __forceinline__ void cp_async16(uint32_t dst, const void* src) {
    asm volatile("cp.async.cg.shared.global [%0], [%1], 16;\n" :: "r"(dst), "l"(src));
}
__device__ __forceinline__ void cp_commit() { asm volatile("cp.async.commit_group;\n" ::: "memory"); }

__device__ __forceinline__ void ldsm4(uint32_t addr, uint32_t& r0, uint32_t& r1, uint32_t& r2, uint32_t& r3) {
    asm volatile("ldmatrix.sync.aligned.m8n8.x4.shared.b16 {%0,%1,%2,%3}, [%4];"
                 : "=r"(r0), "=r"(r1), "=r"(r2), "=r"(r3) : "r"(addr));
}
__device__ __forceinline__ void ldsm4t(uint32_t addr, uint32_t& r0, uint32_t& r1, uint32_t& r2, uint32_t& r3) {
    asm volatile("ldmatrix.sync.aligned.m8n8.x4.trans.shared.b16 {%0,%1,%2,%3}, [%4];"
                 : "=r"(r0), "=r"(r1), "=r"(r2), "=r"(r3) : "r"(addr));
}
__device__ __forceinline__ void mma_f16(float* c, const uint32_t* a, const uint32_t* b) {
    asm volatile("mma.sync.aligned.m16n8k16.row.col.f32.f16.f16.f32 "
                 "{%0,%1,%2,%3}, {%4,%5,%6,%7}, {%8,%9}, {%0,%1,%2,%3};"
                 : "+f"(c[0]), "+f"(c[1]), "+f"(c[2]), "+f"(c[3])
                 : "r"(a[0]), "r"(a[1]), "r"(a[2]), "r"(a[3]), "r"(b[0]), "r"(b[1]));
}
__device__ __forceinline__ void split2h(float a, float b, uint32_t& hi, uint32_t& lo) {
    __half ha = __float2half(a), hb = __float2half(b);
    __half2 hh; hh.x = ha; hh.y = hb;
    __half2 ll;
    ll.x = __float2half(a - __half2float(ha));
    ll.y = __float2half(b - __half2float(hb));
    hi = *(uint32_t*)&hh; lo = *(uint32_t*)&ll;
}
__device__ __forceinline__ uint32_t pack_h2(float a, float b) {
    __half2 h; h.x = __float2half(a); h.y = __float2half(b);
    return *(uint32_t*)&h;
}
// half2{lo, hi} = 2^{lo_arg}, 2^{hi_arg}
__device__ __forceinline__ uint32_t exp2_h2(float lo, float hi) {
    uint32_t r;
    asm("{ .reg .b32 t; cvt.rn.f16x2.f32 t, %2, %1; ex2.approx.f16x2 %0, t; }"
        : "=r"(r) : "f"(lo), "f"(hi));
    return r;
}
__device__ __forceinline__ float pick3(float a, float b, float c, int i) {
    return i == 0 ? a : (i == 1 ? b : c);
}

// ======== fused weight convert (fp32 -> fp16 single), all 4 weights ====
__global__ void __launch_bounds__(256) convw_all_kernel(
    const float* __restrict__ qkv_w, const float* __restrict__ o_w,
    const float* __restrict__ w1,    const float* __restrict__ w2,
    __half* __restrict__ qkvo, __half* __restrict__ oo,
    __half* __restrict__ w1o,  __half* __restrict__ w2o)
{
    int bid = blockIdx.x;
    const float* src; __half* dst; int base;
    if (bid < 1728)      { src = qkv_w; dst = qkvo; base = bid; }
    else if (bid < 2304) { src = o_w;   dst = oo;   base = bid - 1728; }
    else if (bid < 4608) { src = w1;    dst = w1o;  base = bid - 2304; }
    else                 { src = w2;    dst = w2o;  base = bid - 4608; }
    int i = base * 1024 + threadIdx.x * 4;
    float4 v = *(const float4*)(src + i);
    *(uint32_t*)(dst + i)     = pack_h2(v.x, v.y);
    *(uint32_t*)(dst + i + 2) = pack_h2(v.z, v.w);
}

// ================= relm int32 -> uint8 (idx+1) =================
__global__ void __launch_bounds__(256) rel8_kernel(
    const int* __restrict__ relm, unsigned char* __restrict__ out)
{
    int i = blockIdx.x * 256 + threadIdx.x;
    int4 v = ((const int4*)relm)[i];
    uchar4 o;
    o.x = (unsigned char)(v.x + 1); o.y = (unsigned char)(v.y + 1);
    o.z = (unsigned char)(v.z + 1); o.w = (unsigned char)(v.w + 1);
    ((uchar4*)out)[i] = o;
}

// ================= LayerNorm -> fp16 =================
__global__ void __launch_bounds__(256) ln_kernel(
    const float* __restrict__ x, const float* __restrict__ g,
    const float* __restrict__ bt, __half* __restrict__ y)
{
    __shared__ float red[8];
    __shared__ float red2[8];
    const int row = blockIdx.x;
    const int tid = threadIdx.x;
    const float* xr = x + (size_t)row * DD;

    float v0 = xr[tid], v1 = xr[tid + 256], v2 = xr[tid + 512];
    float s = v0 + v1 + v2;
    #pragma unroll
    for (int off = 16; off >= 1; off >>= 1)
        s += __shfl_xor_sync(0xffffffffu, s, off);
    if ((tid & 31) == 0) red[tid >> 5] = s;
    __syncthreads();
    float tot = 0.f;
    #pragma unroll
    for (int i = 0; i < 8; i++) tot += red[i];
    const float mean = tot * (1.0f / DD);

    float d0 = v0 - mean, d1 = v1 - mean, d2 = v2 - mean;
    float ss = d0*d0 + d1*d1 + d2*d2;
    #pragma unroll
    for (int off = 16; off >= 1; off >>= 1)
        ss += __shfl_xor_sync(0xffffffffu, ss, off);
    if ((tid & 31) == 0) red2[tid >> 5] = ss;
    __syncthreads();
    float vtot = 0.f;
    #pragma unroll
    for (int i = 0; i < 8; i++) vtot += red2[i];
    const float rstd = rsqrtf(vtot * (1.0f / DD) + 1e-5f);

    #pragma unroll
    for (int j = 0; j < 3; j++) {
        int c = tid + j * 256;
        float dv = (j == 0 ? d0 : (j == 1 ? d1 : d2));
        y[(size_t)row * DD + c] = __float2half(dv * rstd * g[c] + bt[c]);
    }
}

// 128-byte-row swizzle (8 x 16B chunks per row)
#define SWZ128(row, ch) ((uint32_t)((row) * 128 + (((ch) ^ ((row) & 7)) * 16)))

// ========== fp16 single-W HMMA GEMM, BK=64, 2-stage, occ 2 ==========
// OUT: 0 fp32(+resid), 1 fp16, 3 QKV (Q single / K hi+lo / V single)
template<bool RELU, bool BIAS, bool RESID, int OUT, int BM>
__global__ void __launch_bounds__(256, 2) hgemm(
    const __half* __restrict__ A, const __half* __restrict__ W,
    const float* __restrict__ bias, const float* __restrict__ resid,
    float* __restrict__ C, __half* __restrict__ Ch,
    __half* __restrict__ Cbh, __half* __restrict__ Cbl, __half* __restrict__ Cv,
    int M, int N, int K)
{
    constexpr int WMW = BM / 32;
    constexpr int WNW = 8 / WMW;
    constexpr int WN  = 128 / WNW;
    constexpr int NT  = WN / 8;
    constexpr int NP  = NT / 2;
    constexpr int A_BYTES = BM * 128;           // BM rows x 64 fp16
    constexpr int STAGE = A_BYTES + 16384;      // + W 16KB
    constexpr int CHUNKS = BM * 8 + 1024;
    constexpr int ITERS = CHUNKS / 256;
    static_assert(CHUNKS % 256 == 0, "chunk count must divide");

    extern __shared__ __align__(128) char smem[];
    const uint32_t sb = smem_u32(smem);

    const int tid = threadIdx.x;
    const int wid = tid >> 5, lane = tid & 31;
    const int warp_m = wid & (WMW - 1), warp_n = wid / WMW;
    const int m0 = blockIdx.y * BM, n0 = blockIdx.x * 128;

    float acc[2][NT][4];
    #pragma unroll
    for (int mt = 0; mt < 2; mt++)
        #pragma unroll
        for (int nt = 0; nt < NT; nt++)
            #pragma unroll
            for (int j = 0; j < 4; j++) acc[mt][nt][j] = 0.f;

    const int niter = K >> 6;

    auto load_stage = [&](int buf, int k0) {
        uint32_t base = sb + buf * STAGE;
        #pragma unroll
        for (int t = 0; t < ITERS; t++) {
            int c = tid + t * 256;
            if (c < BM * 8) {
                int row = c >> 3, ch = c & 7;
                cp_async16(base + SWZ128(row, ch),
                           A + (size_t)(m0 + row) * K + k0 + ch * 8);
            } else {
                int w = c - BM * 8;               // 0..1023
                int row = w >> 3, ch = w & 7;
                cp_async16(base + A_BYTES + SWZ128(row, ch),
                           W + (size_t)(n0 + row) * K + k0 + ch * 8);
            }
        }
        cp_commit();
    };

    load_stage(0, 0);

    const int lr = lane & 15, lh = lane >> 4;

    for (int it = 0; it < niter; it++) {
        asm volatile("cp.async.wait_group 0;\n" ::: "memory");
        __syncthreads();
        if (it + 1 < niter) load_stage((it + 1) & 1, (it + 1) * 64);

        const uint32_t base = sb + (it & 1) * STAGE;
        #pragma unroll
        for (int ks = 0; ks < 4; ks++) {
            const int ch = ks * 2 + lh;
            uint32_t af[2][4];
            #pragma unroll
            for (int mt = 0; mt < 2; mt++) {
                int row = warp_m * 32 + mt * 16 + lr;
                ldsm4(base + SWZ128(row, ch), af[mt][0], af[mt][1], af[mt][2], af[mt][3]);
            }
            uint32_t bh[NT][2];
            #pragma unroll
            for (int np = 0; np < NP; np++) {
                int row = warp_n * WN + np * 16 + lr;
                uint32_t off = base + A_BYTES + SWZ128(row, ch);
                ldsm4(off, bh[2*np][0], bh[2*np+1][0], bh[2*np][1], bh[2*np+1][1]);
            }
            #pragma unroll
            for (int mt = 0; mt < 2; mt++)
                #pragma unroll
                for (int nt = 0; nt < NT; nt++)
                    mma_f16(acc[mt][nt], af[mt], bh[nt]);
        }
    }

    #pragma unroll
    for (int mt = 0; mt < 2; mt++) {
        #pragma unroll
        for (int half = 0; half < 2; half++) {
            const int m = m0 + warp_m * 32 + mt * 16 + (lane >> 2) + half * 8;
            #pragma unroll
            for (int nt = 0; nt < NT; nt++) {
                const int n = n0 + warp_n * WN + nt * 8 + (lane & 3) * 2;
                float v0 = acc[mt][nt][half * 2 + 0];
                float v1 = acc[mt][nt][half * 2 + 1];
                if (BIAS) { v0 += bias[n]; v1 += bias[n + 1]; }
                if (RELU) { v0 = fmaxf(v0, 0.f); v1 = fmaxf(v1, 0.f); }
                if (RESID) {
                    float2 rv = *(const float2*)(resid + (size_t)m * N + n);
                    v0 += rv.x; v1 += rv.y;
                }
                if (OUT == 0) {
                    float2 o2; o2.x = v0; o2.y = v1;
                    *(float2*)(C + (size_t)m * N + n) = o2;
                } else if (OUT == 1) {
                    *(uint32_t*)(Ch + (size_t)m * N + n) = pack_h2(v0, v1);
                } else {
                    if (n0 < DD) {
                        *(uint32_t*)(Ch + (size_t)m * DD + n) = pack_h2(v0, v1);
                    } else if (n0 < 2 * DD) {
                        uint32_t hi, lo;
                        split2h(v0, v1, hi, lo);
                        *(uint32_t*)(Cbh + (size_t)m * DD + (n - DD)) = hi;
                        *(uint32_t*)(Cbl + (size_t)m * DD + (n - DD)) = lo;
                    } else {
                        *(uint32_t*)(Cv + (size_t)m * DD + (n - 2 * DD)) = pack_h2(v0, v1);
                    }
                }
            }
        }
    }
}

// ====== HMMA flash attention: K 2-term, V single, exp2-f16x2 softmax ========
__global__ void __launch_bounds__(256, 2) attn_mma_kernel(
    const __half* __restrict__ qs,
    const __half* __restrict__ kh, const __half* __restrict__ kl,
    const __half* __restrict__ vs,
    const unsigned char* __restrict__ rel8, const unsigned char* __restrict__ amask,
    const float* __restrict__ relA, __half* __restrict__ outp)
{
    extern __shared__ __align__(128) char smem[];
    const uint32_t sQ = smem_u32(smem);
    const uint32_t sStage = sQ + 16384;           // +stage*24576: Kh,Kl,Vh
    float* mb = (float*)(smem + 16384 + 49152);   // [2][64]

    const int tid = threadIdx.x, wid = tid >> 5, lane = tid & 31;
    const int lr = lane & 15, lh = lane >> 4;
    const int b = blockIdx.z, h = blockIdx.y;
    const int q0 = blockIdx.x * 128;

    // ---- Q tile ----
    #pragma unroll
    for (int t = 0; t < 4; t++) {
        int lin = tid + t * 256;
        int row = lin >> 3, ch = lin & 7;
        cp_async16(sQ + SWZ128(row, ch),
                   qs + (size_t)(b * SS + q0 + row) * DD + h * HDIM + ch * 8);
    }
    cp_commit();

    auto load_kv = [&](int stage, int kt) {
        const int k0 = kt * 64;
        uint32_t base = sStage + stage * 24576;
        #pragma unroll
        for (int t = 0; t < 6; t++) {
            int lin = tid + t * 256;
            int tensor = lin >> 9;
            int w = lin & 511;
            int row = w >> 3, ch = w & 7;
            uint32_t off = base + tensor * 8192 + SWZ128(row, ch);
            size_t g = (size_t)(b * SS + k0 + row) * DD + h * HDIM + ch * 8;
            const __half* src = (tensor == 0) ? kh : (tensor == 1 ? kl : vs);
            cp_async16(off, src + g);
        }
        if (tid < 64) mb[stage * 64 + tid] = amask[b * SS + k0 + tid] ? -1e30f : 0.f;
        cp_commit();
    };

    load_kv(0, 0);

    asm volatile("cp.async.wait_group 1;\n" ::: "memory");  // Q ready
    __syncthreads();

    uint32_t qf[4][4];
    #pragma unroll
    for (int ks = 0; ks < 4; ks++) {
        uint32_t off = SWZ128(wid * 16 + lr, ks * 2 + lh);
        ldsm4(sQ + off, qf[ks][0], qf[ks][1], qf[ks][2], qf[ks][3]);
    }

    // per-row relative logits, pre-scaled into exp2 domain
    const int r0 = wid * 16 + (lane >> 2);
    float rs00 = 0.f, rs01 = 0.f, rs02 = 0.f;
    float rs10 = 0.f, rs11 = 0.f, rs12 = 0.f;
    {
        const int dbase = (lane & 3) * 16;
        #pragma unroll
        for (int dd = 0; dd < 16; dd++) {
            int d = dbase + dd;
            float q0v = __half2float(*(const __half*)(smem + SWZ128(r0, d >> 3) + (d & 7) * 2));
            float q1v = __half2float(*(const __half*)(smem + SWZ128(r0 + 8, d >> 3) + (d & 7) * 2));
            float a0 = relA[d], a1 = relA[64 + d], a2 = relA[128 + d];
            rs00 += q0v * a0; rs01 += q0v * a1; rs02 += q0v * a2;
            rs10 += q1v * a0; rs11 += q1v * a1; rs12 += q1v * a2;
        }
        #pragma unroll
        for (int off = 1; off <= 2; off <<= 1) {
            rs00 += __shfl_xor_sync(0xffffffffu, rs00, off);
            rs01 += __shfl_xor_sync(0xffffffffu, rs01, off);
            rs02 += __shfl_xor_sync(0xffffffffu, rs02, off);
            rs10 += __shfl_xor_sync(0xffffffffu, rs10, off);
            rs11 += __shfl_xor_sync(0xffffffffu, rs11, off);
            rs12 += __shfl_xor_sync(0xffffffffu, rs12, off);
        }
        rs00 *= C1F; rs01 *= C1F; rs02 *= C1F;
        rs10 *= C1F; rs11 *= C1F; rs12 *= C1F;
    }

    uint32_t ones_b[2];
    ones_b[0] = ones_b[1] = (lane < 4) ? 0x3C003C00u : 0u;

    float o[8][4];
    #pragma unroll
    for (int nt = 0; nt < 8; nt++)
        #pragma unroll
        for (int j = 0; j < 4; j++) o[nt][j] = 0.f;
    float lacc[4] = {0.f, 0.f, 0.f, 0.f};
    float m0 = -1e30f, m1 = -1e30f;

    for (int kt = 0; kt < SS / 64; kt++) {
        const int cur = kt & 1;
        asm volatile("cp.async.wait_group 0;\n" ::: "memory");
        __syncthreads();
        if (kt + 1 < SS / 64) load_kv((kt + 1) & 1, kt + 1);

        const uint32_t stg = sStage + cur * 24576;
        const float* mbc = mb + cur * 64;
        const int k0 = kt * 64;

        uchar2 iv0[8], iv1[8];
        #pragma unroll
        for (int nt = 0; nt < 8; nt++) {
            const int c0 = nt * 8 + (lane & 3) * 2;
            iv0[nt] = *(const uchar2*)(rel8 + (size_t)(b * SS + q0 + r0) * SS + k0 + c0);
            iv1[nt] = *(const uchar2*)(rel8 + (size_t)(b * SS + q0 + r0 + 8) * SS + k0 + c0);
        }

        float s[8][4];
        #pragma unroll
        for (int nt = 0; nt < 8; nt++)
            #pragma unroll
            for (int j = 0; j < 4; j++) s[nt][j] = 0.f;

        #pragma unroll
        for (int ks = 0; ks < 4; ks++) {
            uint32_t kf[8][2];
            #pragma unroll
            for (int np = 0; np < 4; np++) {
                uint32_t off = stg + SWZ128(np * 16 + lr, ks * 2 + lh);
                ldsm4(off, kf[2*np][0], kf[2*np+1][0], kf[2*np][1], kf[2*np+1][1]);
            }
            #pragma unroll
            for (int nt = 0; nt < 8; nt++) mma_f16(s[nt], qf[ks], kf[nt]);
            #pragma unroll
            for (int np = 0; np < 4; np++) {
                uint32_t off = stg + 8192 + SWZ128(np * 16 + lr, ks * 2 + lh);
                ldsm4(off, kf[2*np][0], kf[2*np+1][0], kf[2*np][1], kf[2*np+1][1]);
            }
            #pragma unroll
            for (int nt = 0; nt < 8; nt++) mma_f16(s[nt], qf[ks], kf[nt]);
        }

        float mx0 = -1e30f, mx1 = -1e30f;
        #pragma unroll
        for (int nt = 0; nt < 8; nt++) {
            const int c0 = nt * 8 + (lane & 3) * 2;
            float mb0 = mbc[c0], mb1 = mbc[c0 + 1];
            s[nt][0] = fmaf(s[nt][0], C1F, pick3(rs00, rs01, rs02, iv0[nt].x) + mb0);
            s[nt][1] = fmaf(s[nt][1], C1F, pick3(rs00, rs01, rs02, iv0[nt].y) + mb1);
            s[nt][2] = fmaf(s[nt][2], C1F, pick3(rs10, rs11, rs12, iv1[nt].x) + mb0);
            s[nt][3] = fmaf(s[nt][3], C1F, pick3(rs10, rs11, rs12, iv1[nt].y) + mb1);
            mx0 = fmaxf(mx0, fmaxf(s[nt][0], s[nt][1]));
            mx1 = fmaxf(mx1, fmaxf(s[nt][2], s[nt][3]));
        }
        #pragma unroll
        for (int off = 1; off <= 2; off <<= 1) {
            mx0 = fmaxf(mx0, __shfl_xor_sync(0xffffffffu, mx0, off));
            mx1 = fmaxf(mx1, __shfl_xor_sync(0xffffffffu, mx1, off));
        }
        const float mn0 = fmaxf(m0, mx0), mn1 = fmaxf(m1, mx1);
        const float fac0 = exp2f(m0 - mn0), fac1 = exp2f(m1 - mn1);
        m0 = mn0; m1 = mn1;

        lacc[0] *= fac0; lacc[1] *= fac0;
        lacc[2] *= fac1; lacc[3] *= fac1;
        #pragma unroll
        for (int nt = 0; nt < 8; nt++) {
            o[nt][0] *= fac0; o[nt][1] *= fac0;
            o[nt][2] *= fac1; o[nt][3] *= fac1;
        }

        uint32_t ph[8], pl[8];
        #pragma unroll
        for (int nt = 0; nt < 8; nt++) {
            ph[nt] = exp2_h2(s[nt][0] - mn0, s[nt][1] - mn0);
            pl[nt] = exp2_h2(s[nt][2] - mn1, s[nt][3] - mn1);
        }

        #pragma unroll
        for (int ks2 = 0; ks2 < 4; ks2++) {
            uint32_t pa[4];
            pa[0] = ph[2*ks2];   pa[1] = pl[2*ks2];
            pa[2] = ph[2*ks2+1]; pa[3] = pl[2*ks2+1];
            mma_f16(lacc, pa, ones_b);
            uint32_t vf[8][2];
            #pragma unroll
            for (int np = 0; np < 4; np++) {
                uint32_t off = stg + 16384 + SWZ128(ks2 * 16 + lr, np * 2 + lh);
                ldsm4t(off, vf[2*np][0], vf[2*np][1], vf[2*np+1][0], vf[2*np+1][1]);
            }
            #pragma unroll
            for (int nt = 0; nt < 8; nt++) mma_f16(o[nt], pa, vf[nt]);
        }
    }

    const float l0 = __shfl_sync(0xffffffffu, lacc[0], 0, 4);
    const float l1 = __shfl_sync(0xffffffffu, lacc[2], 0, 4);
    const float inv0 = 1.0f / l0, inv1 = 1.0f / l1;
    #pragma unroll
    for (int nt = 0; nt < 8; nt++) {
        const int c0 = nt * 8 + (lane & 3) * 2;
        size_t base0 = (size_t)(b * SS + q0 + r0) * DD + h * HDIM + c0;
        size_t base1 = (size_t)(b * SS + q0 + r0 + 8) * DD + h * HDIM + c0;
        *(uint32_t*)(outp + base0) = pack_h2(o[nt][0] * inv0, o[nt][1] * inv0);
        *(uint32_t*)(outp + base1) = pack_h2(o[nt][2] * inv1, o[nt][3] * inv1);
    }
}

// ================= launch =================
extern "C" void kernel_launch(void* const* d_in, const int* in_sizes, int n_in,
                              void* d_out, int out_size)
{
    const float*         inp   = (const float*)d_in[0];
    const unsigned char* amask = (const unsigned char*)d_in[1];
    const int*           relm  = (const int*)d_in[2];
    const float*         qkv_w = (const float*)d_in[3];
    const float*         relA  = (const float*)d_in[4];
    const float*         o_w   = (const float*)d_in[5];
    const float*         w1    = (const float*)d_in[6];
    const float*         b1    = (const float*)d_in[7];
    const float*         w2    = (const float*)d_in[8];
    const float*         b2    = (const float*)d_in[9];
    const float*         ln1g  = (const float*)d_in[10];
    const float*         ln1b  = (const float*)d_in[11];
    const float*         ln2g  = (const float*)d_in[12];
    const float*         ln2b  = (const float*)d_in[13];
    float* out = (float*)d_out;

    float *x1;
    unsigned char* rel8;
    __half *xln, *hbuf, *attn, *ff, *qsp, *khp, *klp, *vsp;
    __half *wq, *wo, *w1p, *w2p;
    cudaGetSymbolAddress((void**)&x1,   g_x1);
    cudaGetSymbolAddress((void**)&rel8, g_rel8);
    cudaGetSymbolAddress((void**)&xln,  g_xln);
    cudaGetSymbolAddress((void**)&hbuf, g_h);
    cudaGetSymbolAddress((void**)&attn, g_attn);
    cudaGetSymbolAddress((void**)&ff,   g_ff);
    cudaGetSymbolAddress((void**)&qsp,  g_qs);
    cudaGetSymbolAddress((void**)&khp,  g_kh);   cudaGetSymbolAddress((void**)&klp, g_kl);
    cudaGetSymbolAddress((void**)&vsp,  g_vs);
    cudaGetSymbolAddress((void**)&wq,   g_wqkv);
    cudaGetSymbolAddress((void**)&wo,   g_wo);
    cudaGetSymbolAddress((void**)&w1p,  g_w1);
    cudaGetSymbolAddress((void**)&w2p,  g_w2);

    const int SMEM128 = 2 * (128 * 128 + 16384);   // 65536
    const int SMEM64  = 2 * (64 * 128 + 16384);    // 49152
    const int ASMEM = 16384 + 2 * 24576 + 512;     // 66048
    cudaFuncSetAttribute(hgemm<false,false,false,3,128>, cudaFuncAttributeMaxDynamicSharedMemorySize, SMEM128);
    cudaFuncSetAttribute(hgemm<true ,true ,false,1,128>, cudaFuncAttributeMaxDynamicSharedMemorySize, SMEM128);
    cudaFuncSetAttribute(hgemm<false,false,true ,0,64 >, cudaFuncAttributeMaxDynamicSharedMemorySize, SMEM64);
    cudaFuncSetAttribute(hgemm<false,true ,true ,0,64 >, cudaFuncAttributeMaxDynamicSharedMemorySize, SMEM64);
    cudaFuncSetAttribute(attn_mma_kernel, cudaFuncAttributeMaxDynamicSharedMemorySize, ASMEM);

    // 0) preprocessing
    convw_all_kernel<<<6912, 256>>>(qkv_w, o_w, w1, w2, wq, wo, w1p, w2p);
    rel8_kernel<<<NROW*SS/4/256, 256>>>(relm, rel8);

    // 1) LN1 -> xln fp16
    ln_kernel<<<NROW, 256>>>(inp, ln1g, ln1b, xln);

    // 2) QKV: Q fp16 single, K fp16 hi/lo, V fp16 single
    hgemm<false,false,false,3,128><<<dim3(D3/128, NROW/128), 256, SMEM128>>>(
        xln, wq, nullptr, nullptr, nullptr, qsp, khp, klp, vsp, NROW, D3, DD);

    // 3) attention -> fp16
    attn_mma_kernel<<<dim3(SS/128, HH, BB), 256, ASMEM>>>(
        qsp, khp, klp, vsp, rel8, amask, relA, attn);

    // 4) x1 = inp + attn @ o_w^T (fp32)
    hgemm<false,false,true,0,64><<<dim3(DD/128, NROW/64), 256, SMEM64>>>(
        attn, wo, nullptr, inp, x1, nullptr, nullptr, nullptr, nullptr, NROW, DD, DD);

    // 5) LN2 -> h fp16
    ln_kernel<<<NROW, 256>>>(x1, ln2g, ln2b, hbuf);

    // 6) ff = relu(h @ w1^T + b1) -> fp16
    hgemm<true,true,false,1,128><<<dim3(DFF/128, NROW/128), 256, SMEM128>>>(
        hbuf, w1p, b1, nullptr, nullptr, ff, nullptr, nullptr, nullptr, NROW, DFF, DD);

    // 7) out = x1 + ff @ w2^T + b2 (fp32)
    hgemm<false,true,true,0,64><<<dim3(DD/128, NROW/64), 256, SMEM64>>>(
        ff, w2p, b2, x1, out, nullptr, nullptr, nullptr, nullptr, NROW, DD, DFF);
}

// round 15
// speedup vs baseline: 8.5825x; 1.0293x over previous
#include <cuda_runtime.h>
#include <cuda_fp16.h>
#include <cstdint>

// ---------------- problem constants ----------------
#define BB   2
#define SS   1024
#define DD   768
#define HH   12
#define HDIM 64
#define DFF  3072
#define NROW (BB*SS)        // 2048
#define D3   (3*DD)         // 2304

// 0.125 * log2(e)
#define C1F 0.18033688011112042f

// ---------------- scratch (device globals, no allocs) ----------------
__device__ __align__(16) float g_x1  [NROW*DD];
__device__ __align__(16) unsigned char g_rel8[NROW*SS];

__device__ __align__(16) __half g_xln [NROW*DD];
__device__ __align__(16) __half g_h   [NROW*DD];
__device__ __align__(16) __half g_attn[NROW*DD];
__device__ __align__(16) __half g_ff  [NROW*DFF];
__device__ __align__(16) __half g_qkvs[NROW*D3];     // Q|K|V contiguous fp16
__device__ __align__(16) __half g_wqkv[D3*DD];
__device__ __align__(16) __half g_wo  [DD*DD];
__device__ __align__(16) __half g_w1  [DFF*DD];
__device__ __align__(16) __half g_w2  [DD*DFF];

// ================= helpers =================
__device__ __forceinline__ uint32_t smem_u32(const void* p) {
    uint32_t a;
    asm("{ .reg .u64 t; cvta.to.shared.u64 t, %1; cvt.u32.u64 %0, t; }" : "=r"(a) : "l"(p));
    return a;
}
__device__ __forceinline__ void cp_async16(uint32_t dst, const void* src) {
    asm volatile("cp.async.cg.shared.global [%0], [%1], 16;\n" :: "r"(dst), "l"(src));
}
__device__ __forceinline__ void cp_commit() { asm volatile("cp.async.commit_group;\n" ::: "memory"); }

__device__ __forceinline__ void ldsm4(uint32_t addr, uint32_t& r0, uint32_t& r1, uint32_t& r2, uint32_t& r3) {
    asm volatile("ldmatrix.sync.aligned.m8n8.x4.shared.b16 {%0,%1,%2,%3}, [%4];"
                 : "=r"(r0), "=r"(r1), "=r"(r2), "=r"(r3) : "r"(addr));
}
__device__ __forceinline__ void ldsm4t(uint32_t addr, uint32_t& r0, uint32_t& r1, uint32_t& r2, uint32_t& r3) {
    asm volatile("ldmatrix.sync.aligned.m8n8.x4.trans.shared.b16 {%0,%1,%2,%3}, [%4];"
                 : "=r"(r0), "=r"(r1), "=r"(r2), "=r"(r3) : "r"(addr));
}
__device__ __forceinline__ void mma_f16(float* c, const uint32_t* a, const uint32_t* b) {
    asm volatile("mma.sync.aligned.m16n8k16.row.col.f32.f16.f16.f32 "
                 "{%0,%1,%2,%3}, {%4,%5,%6,%7}, {%8,%9}, {%0,%1,%2,%3};"
                 : "+f"(c[0]), "+f"(c[1]), "+f"(c[2]), "+f"(c[3])
                 : "r"(a[0]), "r"(a[1]), "r"(a[2]), "r"(a[3]), "r"(b[0]), "r"(b[1]));
}
__device__ __forceinline__ uint32_t pack_h2(float a, float b) {
    __half2 h; h.x = __float2half(a); h.y = __float2half(b);
    return *(uint32_t*)&h;
}
// half2{lo, hi} = 2^{lo_arg}, 2^{hi_arg}
__device__ __forceinline__ uint32_t exp2_h2(float lo, float hi) {
    uint32_t r;
    asm("{ .reg .b32 t; cvt.rn.f16x2.f32 t, %2, %1; ex2.approx.f16x2 %0, t; }"
        : "=r"(r) : "f"(lo), "f"(hi));
    return r;
}
__device__ __forceinline__ float pick3(float a, float b, float c, int i) {
    return i == 0 ? a : (i == 1 ? b : c);
}

// ======== fused weight convert (fp32 -> fp16 single), all 4 weights ====
__global__ void __launch_bounds__(256) convw_all_kernel(
    const float* __restrict__ qkv_w, const float* __restrict__ o_w,
    const float* __restrict__ w1,    const float* __restrict__ w2,
    __half* __restrict__ qkvo, __half* __restrict__ oo,
    __half* __restrict__ w1o,  __half* __restrict__ w2o)
{
    int bid = blockIdx.x;
    const float* src; __half* dst; int base;
    if (bid < 1728)      { src = qkv_w; dst = qkvo; base = bid; }
    else if (bid < 2304) { src = o_w;   dst = oo;   base = bid - 1728; }
    else if (bid < 4608) { src = w1;    dst = w1o;  base = bid - 2304; }
    else                 { src = w2;    dst = w2o;  base = bid - 4608; }
    int i = base * 1024 + threadIdx.x * 4;
    float4 v = *(const float4*)(src + i);
    *(uint32_t*)(dst + i)     = pack_h2(v.x, v.y);
    *(uint32_t*)(dst + i + 2) = pack_h2(v.z, v.w);
}

// ================= relm int32 -> uint8 (idx+1) =================
__global__ void __launch_bounds__(256) rel8_kernel(
    const int* __restrict__ relm, unsigned char* __restrict__ out)
{
    int i = blockIdx.x * 256 + threadIdx.x;
    int4 v = ((const int4*)relm)[i];
    uchar4 o;
    o.x = (unsigned char)(v.x + 1); o.y = (unsigned char)(v.y + 1);
    o.z = (unsigned char)(v.z + 1); o.w = (unsigned char)(v.w + 1);
    ((uchar4*)out)[i] = o;
}

// ================= LayerNorm -> fp16 =================
__global__ void __launch_bounds__(256) ln_kernel(
    const float* __restrict__ x, const float* __restrict__ g,
    const float* __restrict__ bt, __half* __restrict__ y)
{
    __shared__ float red[8];
    __shared__ float red2[8];
    const int row = blockIdx.x;
    const int tid = threadIdx.x;
    const float* xr = x + (size_t)row * DD;

    float v0 = xr[tid], v1 = xr[tid + 256], v2 = xr[tid + 512];
    float s = v0 + v1 + v2;
    #pragma unroll
    for (int off = 16; off >= 1; off >>= 1)
        s += __shfl_xor_sync(0xffffffffu, s, off);
    if ((tid & 31) == 0) red[tid >> 5] = s;
    __syncthreads();
    float tot = 0.f;
    #pragma unroll
    for (int i = 0; i < 8; i++) tot += red[i];
    const float mean = tot * (1.0f / DD);

    float d0 = v0 - mean, d1 = v1 - mean, d2 = v2 - mean;
    float ss = d0*d0 + d1*d1 + d2*d2;
    #pragma unroll
    for (int off = 16; off >= 1; off >>= 1)
        ss += __shfl_xor_sync(0xffffffffu, ss, off);
    if ((tid & 31) == 0) red2[tid >> 5] = ss;
    __syncthreads();
    float vtot = 0.f;
    #pragma unroll
    for (int i = 0; i < 8; i++) vtot += red2[i];
    const float rstd = rsqrtf(vtot * (1.0f / DD) + 1e-5f);

    #pragma unroll
    for (int j = 0; j < 3; j++) {
        int c = tid + j * 256;
        float dv = (j == 0 ? d0 : (j == 1 ? d1 : d2));
        y[(size_t)row * DD + c] = __float2half(dv * rstd * g[c] + bt[c]);
    }
}

// 128-byte-row swizzle (8 x 16B chunks per row)
#define SWZ128(row, ch) ((uint32_t)((row) * 128 + (((ch) ^ ((row) & 7)) * 16)))

// ========== fp16 single-W HMMA GEMM, BK=64, 2-stage, occ 2 ==========
// OUT: 0 fp32(+resid), 1 fp16
template<bool RELU, bool BIAS, bool RESID, int OUT, int BM>
__global__ void __launch_bounds__(256, 2) hgemm(
    const __half* __restrict__ A, const __half* __restrict__ W,
    const float* __restrict__ bias, const float* __restrict__ resid,
    float* __restrict__ C, __half* __restrict__ Ch,
    int M, int N, int K)
{
    constexpr int WMW = BM / 32;
    constexpr int WNW = 8 / WMW;
    constexpr int WN  = 128 / WNW;
    constexpr int NT  = WN / 8;
    constexpr int NP  = NT / 2;
    constexpr int A_BYTES = BM * 128;           // BM rows x 64 fp16
    constexpr int STAGE = A_BYTES + 16384;      // + W 16KB
    constexpr int CHUNKS = BM * 8 + 1024;
    constexpr int ITERS = CHUNKS / 256;
    static_assert(CHUNKS % 256 == 0, "chunk count must divide");

    extern __shared__ __align__(128) char smem[];
    const uint32_t sb = smem_u32(smem);

    const int tid = threadIdx.x;
    const int wid = tid >> 5, lane = tid & 31;
    const int warp_m = wid & (WMW - 1), warp_n = wid / WMW;
    const int m0 = blockIdx.y * BM, n0 = blockIdx.x * 128;

    float acc[2][NT][4];
    #pragma unroll
    for (int mt = 0; mt < 2; mt++)
        #pragma unroll
        for (int nt = 0; nt < NT; nt++)
            #pragma unroll
            for (int j = 0; j < 4; j++) acc[mt][nt][j] = 0.f;

    const int niter = K >> 6;

    auto load_stage = [&](int buf, int k0) {
        uint32_t base = sb + buf * STAGE;
        #pragma unroll
        for (int t = 0; t < ITERS; t++) {
            int c = tid + t * 256;
            if (c < BM * 8) {
                int row = c >> 3, ch = c & 7;
                cp_async16(base + SWZ128(row, ch),
                           A + (size_t)(m0 + row) * K + k0 + ch * 8);
            } else {
                int w = c - BM * 8;
                int row = w >> 3, ch = w & 7;
                cp_async16(base + A_BYTES + SWZ128(row, ch),
                           W + (size_t)(n0 + row) * K + k0 + ch * 8);
            }
        }
        cp_commit();
    };

    load_stage(0, 0);

    const int lr = lane & 15, lh = lane >> 4;

    for (int it = 0; it < niter; it++) {
        asm volatile("cp.async.wait_group 0;\n" ::: "memory");
        __syncthreads();
        if (it + 1 < niter) load_stage((it + 1) & 1, (it + 1) * 64);

        const uint32_t base = sb + (it & 1) * STAGE;
        #pragma unroll
        for (int ks = 0; ks < 4; ks++) {
            const int ch = ks * 2 + lh;
            uint32_t af[2][4];
            #pragma unroll
            for (int mt = 0; mt < 2; mt++) {
                int row = warp_m * 32 + mt * 16 + lr;
                ldsm4(base + SWZ128(row, ch), af[mt][0], af[mt][1], af[mt][2], af[mt][3]);
            }
            uint32_t bh[NT][2];
            #pragma unroll
            for (int np = 0; np < NP; np++) {
                int row = warp_n * WN + np * 16 + lr;
                uint32_t off = base + A_BYTES + SWZ128(row, ch);
                ldsm4(off, bh[2*np][0], bh[2*np+1][0], bh[2*np][1], bh[2*np+1][1]);
            }
            #pragma unroll
            for (int mt = 0; mt < 2; mt++)
                #pragma unroll
                for (int nt = 0; nt < NT; nt++)
                    mma_f16(acc[mt][nt], af[mt], bh[nt]);
        }
    }

    #pragma unroll
    for (int mt = 0; mt < 2; mt++) {
        #pragma unroll
        for (int half = 0; half < 2; half++) {
            const int m = m0 + warp_m * 32 + mt * 16 + (lane >> 2) + half * 8;
            #pragma unroll
            for (int nt = 0; nt < NT; nt++) {
                const int n = n0 + warp_n * WN + nt * 8 + (lane & 3) * 2;
                float v0 = acc[mt][nt][half * 2 + 0];
                float v1 = acc[mt][nt][half * 2 + 1];
                if (BIAS) { v0 += bias[n]; v1 += bias[n + 1]; }
                if (RELU) { v0 = fmaxf(v0, 0.f); v1 = fmaxf(v1, 0.f); }
                if (RESID) {
                    float2 rv = *(const float2*)(resid + (size_t)m * N + n);
                    v0 += rv.x; v1 += rv.y;
                }
                if (OUT == 0) {
                    float2 o2; o2.x = v0; o2.y = v1;
                    *(float2*)(C + (size_t)m * N + n) = o2;
                } else {
                    *(uint32_t*)(Ch + (size_t)m * N + n) = pack_h2(v0, v1);
                }
            }
        }
    }
}

// ====== HMMA flash attention: single-fp16 QKV, exp2-f16x2 softmax ==========
// Smem: Q [128][64] 16KB + 2 stages of {K,V}[64][64] 16KB each + mb
__global__ void __launch_bounds__(256, 2) attn_mma_kernel(
    const __half* __restrict__ qkv,
    const unsigned char* __restrict__ rel8, const unsigned char* __restrict__ amask,
    const float* __restrict__ relA, __half* __restrict__ outp)
{
    extern __shared__ __align__(128) char smem[];
    const uint32_t sQ = smem_u32(smem);
    const uint32_t sStage = sQ + 16384;           // +stage*16384: K,V
    float* mb = (float*)(smem + 16384 + 32768);   // [2][64]

    const int tid = threadIdx.x, wid = tid >> 5, lane = tid & 31;
    const int lr = lane & 15, lh = lane >> 4;
    const int b = blockIdx.z, h = blockIdx.y;
    const int q0 = blockIdx.x * 128;

    // ---- Q tile ----
    #pragma unroll
    for (int t = 0; t < 4; t++) {
        int lin = tid + t * 256;
        int row = lin >> 3, ch = lin & 7;
        cp_async16(sQ + SWZ128(row, ch),
                   qkv + (size_t)(b * SS + q0 + row) * D3 + h * HDIM + ch * 8);
    }
    cp_commit();

    auto load_kv = [&](int stage, int kt) {
        const int k0 = kt * 64;
        uint32_t base = sStage + stage * 16384;
        #pragma unroll
        for (int t = 0; t < 4; t++) {
            int lin = tid + t * 256;          // 0..1023
            int tensor = lin >> 9;            // 0:K 1:V
            int w = lin & 511;
            int row = w >> 3, ch = w & 7;
            uint32_t off = base + tensor * 8192 + SWZ128(row, ch);
            size_t g = (size_t)(b * SS + k0 + row) * D3 + (tensor + 1) * DD + h * HDIM + ch * 8;
            cp_async16(off, qkv + g);
        }
        if (tid < 64) mb[stage * 64 + tid] = amask[b * SS + k0 + tid] ? -1e30f : 0.f;
        cp_commit();
    };

    load_kv(0, 0);

    asm volatile("cp.async.wait_group 1;\n" ::: "memory");  // Q ready
    __syncthreads();

    uint32_t qf[4][4];
    #pragma unroll
    for (int ks = 0; ks < 4; ks++) {
        uint32_t off = SWZ128(wid * 16 + lr, ks * 2 + lh);
        ldsm4(sQ + off, qf[ks][0], qf[ks][1], qf[ks][2], qf[ks][3]);
    }

    // per-row relative logits, pre-scaled into exp2 domain
    const int r0 = wid * 16 + (lane >> 2);
    float rs00 = 0.f, rs01 = 0.f, rs02 = 0.f;
    float rs10 = 0.f, rs11 = 0.f, rs12 = 0.f;
    {
        const int dbase = (lane & 3) * 16;
        #pragma unroll
        for (int dd = 0; dd < 16; dd++) {
            int d = dbase + dd;
            float q0v = __half2float(*(const __half*)(smem + SWZ128(r0, d >> 3) + (d & 7) * 2));
            float q1v = __half2float(*(const __half*)(smem + SWZ128(r0 + 8, d >> 3) + (d & 7) * 2));
            float a0 = relA[d], a1 = relA[64 + d], a2 = relA[128 + d];
            rs00 += q0v * a0; rs01 += q0v * a1; rs02 += q0v * a2;
            rs10 += q1v * a0; rs11 += q1v * a1; rs12 += q1v * a2;
        }
        #pragma unroll
        for (int off = 1; off <= 2; off <<= 1) {
            rs00 += __shfl_xor_sync(0xffffffffu, rs00, off);
            rs01 += __shfl_xor_sync(0xffffffffu, rs01, off);
            rs02 += __shfl_xor_sync(0xffffffffu, rs02, off);
            rs10 += __shfl_xor_sync(0xffffffffu, rs10, off);
            rs11 += __shfl_xor_sync(0xffffffffu, rs11, off);
            rs12 += __shfl_xor_sync(0xffffffffu, rs12, off);
        }
        rs00 *= C1F; rs01 *= C1F; rs02 *= C1F;
        rs10 *= C1F; rs11 *= C1F; rs12 *= C1F;
    }

    uint32_t ones_b[2];
    ones_b[0] = ones_b[1] = (lane < 4) ? 0x3C003C00u : 0u;

    float o[8][4];
    #pragma unroll
    for (int nt = 0; nt < 8; nt++)
        #pragma unroll
        for (int j = 0; j < 4; j++) o[nt][j] = 0.f;
    float lacc[4] = {0.f, 0.f, 0.f, 0.f};
    float m0 = -1e30f, m1 = -1e30f;

    for (int kt = 0; kt < SS / 64; kt++) {
        const int cur = kt & 1;
        asm volatile("cp.async.wait_group 0;\n" ::: "memory");
        __syncthreads();
        if (kt + 1 < SS / 64) load_kv((kt + 1) & 1, kt + 1);

        const uint32_t stg = sStage + cur * 16384;
        const float* mbc = mb + cur * 64;
        const int k0 = kt * 64;

        uchar2 iv0[8], iv1[8];
        #pragma unroll
        for (int nt = 0; nt < 8; nt++) {
            const int c0 = nt * 8 + (lane & 3) * 2;
            iv0[nt] = *(const uchar2*)(rel8 + (size_t)(b * SS + q0 + r0) * SS + k0 + c0);
            iv1[nt] = *(const uchar2*)(rel8 + (size_t)(b * SS + q0 + r0 + 8) * SS + k0 + c0);
        }

        // ---- S = Q K^T (single term) ----
        float s[8][4];
        #pragma unroll
        for (int nt = 0; nt < 8; nt++)
            #pragma unroll
            for (int j = 0; j < 4; j++) s[nt][j] = 0.f;

        #pragma unroll
        for (int ks = 0; ks < 4; ks++) {
            uint32_t kf[8][2];
            #pragma unroll
            for (int np = 0; np < 4; np++) {
                uint32_t off = stg + SWZ128(np * 16 + lr, ks * 2 + lh);
                ldsm4(off, kf[2*np][0], kf[2*np+1][0], kf[2*np][1], kf[2*np+1][1]);
            }
            #pragma unroll
            for (int nt = 0; nt < 8; nt++) mma_f16(s[nt], qf[ks], kf[nt]);
        }

        float mx0 = -1e30f, mx1 = -1e30f;
        #pragma unroll
        for (int nt = 0; nt < 8; nt++) {
            const int c0 = nt * 8 + (lane & 3) * 2;
            float mb0 = mbc[c0], mb1 = mbc[c0 + 1];
            s[nt][0] = fmaf(s[nt][0], C1F, pick3(rs00, rs01, rs02, iv0[nt].x) + mb0);
            s[nt][1] = fmaf(s[nt][1], C1F, pick3(rs00, rs01, rs02, iv0[nt].y) + mb1);
            s[nt][2] = fmaf(s[nt][2], C1F, pick3(rs10, rs11, rs12, iv1[nt].x) + mb0);
            s[nt][3] = fmaf(s[nt][3], C1F, pick3(rs10, rs11, rs12, iv1[nt].y) + mb1);
            mx0 = fmaxf(mx0, fmaxf(s[nt][0], s[nt][1]));
            mx1 = fmaxf(mx1, fmaxf(s[nt][2], s[nt][3]));
        }
        #pragma unroll
        for (int off = 1; off <= 2; off <<= 1) {
            mx0 = fmaxf(mx0, __shfl_xor_sync(0xffffffffu, mx0, off));
            mx1 = fmaxf(mx1, __shfl_xor_sync(0xffffffffu, mx1, off));
        }
        const float mn0 = fmaxf(m0, mx0), mn1 = fmaxf(m1, mx1);
        const float fac0 = exp2f(m0 - mn0), fac1 = exp2f(m1 - mn1);
        m0 = mn0; m1 = mn1;

        lacc[0] *= fac0; lacc[1] *= fac0;
        lacc[2] *= fac1; lacc[3] *= fac1;
        #pragma unroll
        for (int nt = 0; nt < 8; nt++) {
            o[nt][0] *= fac0; o[nt][1] *= fac0;
            o[nt][2] *= fac1; o[nt][3] *= fac1;
        }

        uint32_t ph[8], pl[8];
        #pragma unroll
        for (int nt = 0; nt < 8; nt++) {
            ph[nt] = exp2_h2(s[nt][0] - mn0, s[nt][1] - mn0);
            pl[nt] = exp2_h2(s[nt][2] - mn1, s[nt][3] - mn1);
        }

        #pragma unroll
        for (int ks2 = 0; ks2 < 4; ks2++) {
            uint32_t pa[4];
            pa[0] = ph[2*ks2];   pa[1] = pl[2*ks2];
            pa[2] = ph[2*ks2+1]; pa[3] = pl[2*ks2+1];
            mma_f16(lacc, pa, ones_b);
            uint32_t vf[8][2];
            #pragma unroll
            for (int np = 0; np < 4; np++) {
                uint32_t off = stg + 8192 + SWZ128(ks2 * 16 + lr, np * 2 + lh);
                ldsm4t(off, vf[2*np][0], vf[2*np][1], vf[2*np+1][0], vf[2*np+1][1]);
            }
            #pragma unroll
            for (int nt = 0; nt < 8; nt++) mma_f16(o[nt], pa, vf[nt]);
        }
    }

    const float l0 = __shfl_sync(0xffffffffu, lacc[0], 0, 4);
    const float l1 = __shfl_sync(0xffffffffu, lacc[2], 0, 4);
    const float inv0 = 1.0f / l0, inv1 = 1.0f / l1;
    #pragma unroll
    for (int nt = 0; nt < 8; nt++) {
        const int c0 = nt * 8 + (lane & 3) * 2;
        size_t base0 = (size_t)(b * SS + q0 + r0) * DD + h * HDIM + c0;
        size_t base1 = (size_t)(b * SS + q0 + r0 + 8) * DD + h * HDIM + c0;
        *(uint32_t*)(outp + base0) = pack_h2(o[nt][0] * inv0, o[nt][1] * inv0);
        *(uint32_t*)(outp + base1) = pack_h2(o[nt][2] * inv1, o[nt][3] * inv1);
    }
}

// ================= launch =================
extern "C" void kernel_launch(void* const* d_in, const int* in_sizes, int n_in,
                              void* d_out, int out_size)
{
    const float*         inp   = (const float*)d_in[0];
    const unsigned char* amask = (const unsigned char*)d_in[1];
    const int*           relm  = (const int*)d_in[2];
    const float*         qkv_w = (const float*)d_in[3];
    const float*         relA  = (const float*)d_in[4];
    const float*         o_w   = (const float*)d_in[5];
    const float*         w1    = (const float*)d_in[6];
    const float*         b1    = (const float*)d_in[7];
    const float*         w2    = (const float*)d_in[8];
    const float*         b2    = (const float*)d_in[9];
    const float*         ln1g  = (const float*)d_in[10];
    const float*         ln1b  = (const float*)d_in[11];
    const float*         ln2g  = (const float*)d_in[12];
    const float*         ln2b  = (const float*)d_in[13];
    float* out = (float*)d_out;

    float *x1;
    unsigned char* rel8;
    __half *xln, *hbuf, *attn, *ff, *qkvs;
    __half *wq, *wo, *w1p, *w2p;
    cudaGetSymbolAddress((void**)&x1,   g_x1);
    cudaGetSymbolAddress((void**)&rel8, g_rel8);
    cudaGetSymbolAddress((void**)&xln,  g_xln);
    cudaGetSymbolAddress((void**)&hbuf, g_h);
    cudaGetSymbolAddress((void**)&attn, g_attn);
    cudaGetSymbolAddress((void**)&ff,   g_ff);
    cudaGetSymbolAddress((void**)&qkvs, g_qkvs);
    cudaGetSymbolAddress((void**)&wq,   g_wqkv);
    cudaGetSymbolAddress((void**)&wo,   g_wo);
    cudaGetSymbolAddress((void**)&w1p,  g_w1);
    cudaGetSymbolAddress((void**)&w2p,  g_w2);

    const int SMEM128 = 2 * (128 * 128 + 16384);   // 65536
    const int SMEM64  = 2 * (64 * 128 + 16384);    // 49152
    const int ASMEM = 16384 + 2 * 16384 + 512;     // 49664
    cudaFuncSetAttribute(hgemm<false,false,false,1,128>, cudaFuncAttributeMaxDynamicSharedMemorySize, SMEM128);
    cudaFuncSetAttribute(hgemm<true ,true ,false,1,128>, cudaFuncAttributeMaxDynamicSharedMemorySize, SMEM128);
    cudaFuncSetAttribute(hgemm<false,false,true ,0,64 >, cudaFuncAttributeMaxDynamicSharedMemorySize, SMEM64);
    cudaFuncSetAttribute(hgemm<false,true ,true ,0,64 >, cudaFuncAttributeMaxDynamicSharedMemorySize, SMEM64);
    cudaFuncSetAttribute(attn_mma_kernel, cudaFuncAttributeMaxDynamicSharedMemorySize, ASMEM);

    // 0) preprocessing
    convw_all_kernel<<<6912, 256>>>(qkv_w, o_w, w1, w2, wq, wo, w1p, w2p);
    rel8_kernel<<<NROW*SS/4/256, 256>>>(relm, rel8);

    // 1) LN1 -> xln fp16
    ln_kernel<<<NROW, 256>>>(inp, ln1g, ln1b, xln);

    // 2) QKV -> contiguous fp16 [row][2304]
    hgemm<false,false,false,1,128><<<dim3(D3/128, NROW/128), 256, SMEM128>>>(
        xln, wq, nullptr, nullptr, nullptr, qkvs, NROW, D3, DD);

    // 3) attention -> fp16
    attn_mma_kernel<<<dim3(SS/128, HH, BB), 256, ASMEM>>>(
        qkvs, rel8, amask, relA, attn);

    // 4) x1 = inp + attn @ o_w^T (fp32)
    hgemm<false,false,true,0,64><<<dim3(DD/128, NROW/64), 256, SMEM64>>>(
        attn, wo, nullptr, inp, x1, nullptr, NROW, DD, DD);

    // 5) LN2 -> h fp16
    ln_kernel<<<NROW, 256>>>(x1, ln2g, ln2b, hbuf);

    // 6) ff = relu(h @ w1^T + b1) -> fp16
    hgemm<true,true,false,1,128><<<dim3(DFF/128, NROW/128), 256, SMEM128>>>(
        hbuf, w1p, b1, nullptr, nullptr, ff, NROW, DFF, DD);

    // 7) out = x1 + ff @ w2^T + b2 (fp32)
    hgemm<false,true,true,0,64><<<dim3(DD/128, NROW/64), 256, SMEM64>>>(
        ff, w2p, b2, x1, out, nullptr, NROW, DD, DFF);
}